// round 2
// baseline (speedup 1.0000x reference)
#include <cuda_runtime.h>
#include <math.h>
#include <stdint.h>

// ---------------- problem constants ----------------
#define BROWS   8192
#define HID     256
#define HID2    512
#define VOCAB   32000
#define INPAD   128      // 121 real features zero-padded to 128
#define NSTEPS  48

// ---------------- device scratch (static, no allocation) ----------------
__device__ float g_feats[BROWS * INPAD];   // 4 MB
__device__ float g_w1p[INPAD * HID];       // 128 KB padded W_in1
__device__ float g_hA[BROWS * HID];        // 8 MB
__device__ float g_hB[BROWS * HID];        // 8 MB
__device__ float g_u [BROWS * HID2];       // 16 MB

// ---------------- feature assembly ----------------
// layout per row (padded to 128):
// [0] xc | [1..32] sin | [33..64] cos | [65..88] hash(12 lvl x 2) | [89..120] z | [121..127] 0
__global__ void feats_kernel(const float* __restrict__ x,
                             const float* __restrict__ z,
                             const float* __restrict__ emb) {
    int b = blockIdx.x * blockDim.x + threadIdx.x;
    if (b >= BROWS) return;
    float xc = fminf(fmaxf(x[b], 0.0f), 1.0f);
    float* f = g_feats + (size_t)b * INPAD;
    f[0] = xc;

    const float TWO_PI = 6.283185307179586f;   // f32(2*pi), matches f32(2.0*jnp.pi)
    float a = TWO_PI * xc;
    double fd = 1.0;                            // 3.5^j via exact-ish double iteration
    #pragma unroll 1
    for (int j = 0; j < 32; j++) {
        float fr  = (float)fd;                  // correctly-rounded f32(3.5^j)
        float arg = a * fr;
        f[1 + j]  = sinf(arg);
        f[33 + j] = cosf(arg);
        fd *= 3.5;
    }

    // hash grid: resolutions 16 * 2^l, table 16384 x (12*2)
    float res = 16.0f;
    #pragma unroll 1
    for (int l = 0; l < 12; l++) {
        float pos = xc * res;
        float i0f = floorf(pos);
        int   i0  = (int)i0f;
        float w   = pos - i0f;
        int h0 = i0 & 16383;
        int h1 = (i0 + 1) & 16383;
        const float* t0 = emb + (size_t)h0 * 24 + l * 2;
        const float* t1 = emb + (size_t)h1 * 24 + l * 2;
        f[65 + l * 2 + 0] = (1.0f - w) * t0[0] + w * t1[0];
        f[65 + l * 2 + 1] = (1.0f - w) * t0[1] + w * t1[1];
        res *= 2.0f;
    }

    const float* zp = z + (size_t)b * 32;
    #pragma unroll
    for (int j = 0; j < 32; j++) f[89 + j] = zp[j];
    #pragma unroll
    for (int j = 121; j < 128; j++) f[j] = 0.0f;
}

// zero-pad W_in1 [121,256] -> [128,256]
__global__ void padw1_kernel(const float* __restrict__ w) {
    int i = blockIdx.x * blockDim.x + threadIdx.x;   // 0 .. 128*256-1
    if (i >= INPAD * HID) return;
    int k = i / HID;
    g_w1p[i] = (k < 121) ? w[i] : 0.0f;   // same row-major layout, rows >=121 zero
}

// ---------------- generic fp32 GEMM:  C[M,N] = epi(A[M,K] @ W[K,N] + bias) ----------------
// BM=128 BN=64 BK=16, 256 threads, 8x4 per thread. M%128==0, N%64==0, K%16==0 assumed.
// EPI: 0 = GELU(erf), 1 = 0.5*Hp + 0.5*tanh(v), 2 = bias only
template <int EPI>
__global__ void __launch_bounds__(256) gemm_kernel(
    const float* __restrict__ A, const float* __restrict__ W,
    const float* __restrict__ bias, const float* __restrict__ Hp,
    float* __restrict__ C, int M, int N, int K)
{
    __shared__ float As[16][132];   // [k][m], padded stride
    __shared__ float Bs[16][64];    // [k][n]

    const int tid = threadIdx.x;
    const int tx  = tid & 15;        // n group (x4)
    const int ty  = tid >> 4;        // m group (x8)
    const int bm  = blockIdx.y * 128;
    const int bn  = blockIdx.x * 64;

    const int arow = tid >> 2;          // 0..63
    const int ak   = (tid & 3) << 2;    // 0,4,8,12
    const int brow = tid >> 4;          // 0..15
    const int bcol = (tid & 15) << 2;   // 0..60

    float acc[8][4];
    #pragma unroll
    for (int i = 0; i < 8; i++)
        #pragma unroll
        for (int j = 0; j < 4; j++) acc[i][j] = 0.0f;

    const float* Ap0 = A + (size_t)(bm + arow)      * K + ak;
    const float* Ap1 = A + (size_t)(bm + arow + 64) * K + ak;
    const float* Bp  = W + (size_t)brow * N + bn + bcol;

    for (int k0 = 0; k0 < K; k0 += 16) {
        float4 a0 = *(const float4*)(Ap0 + k0);
        float4 a1 = *(const float4*)(Ap1 + k0);
        float4 bv = *(const float4*)(Bp + (size_t)k0 * N);

        As[ak + 0][arow] = a0.x;  As[ak + 1][arow] = a0.y;
        As[ak + 2][arow] = a0.z;  As[ak + 3][arow] = a0.w;
        As[ak + 0][arow + 64] = a1.x;  As[ak + 1][arow + 64] = a1.y;
        As[ak + 2][arow + 64] = a1.z;  As[ak + 3][arow + 64] = a1.w;
        *(float4*)&Bs[brow][bcol] = bv;
        __syncthreads();

        #pragma unroll
        for (int kk = 0; kk < 16; kk++) {
            float4 alo = *(const float4*)&As[kk][ty * 8];
            float4 ahi = *(const float4*)&As[kk][ty * 8 + 4];
            float4 b4  = *(const float4*)&Bs[kk][tx * 4];
            float am[8] = {alo.x, alo.y, alo.z, alo.w, ahi.x, ahi.y, ahi.z, ahi.w};
            float bb[4] = {b4.x, b4.y, b4.z, b4.w};
            #pragma unroll
            for (int i = 0; i < 8; i++)
                #pragma unroll
                for (int j = 0; j < 4; j++)
                    acc[i][j] = fmaf(am[i], bb[j], acc[i][j]);
        }
        __syncthreads();
    }

    float4 bia = *(const float4*)&bias[bn + tx * 4];
    const float RS2 = 0.70710678118654752f;   // 1/sqrt(2)

    #pragma unroll
    for (int i = 0; i < 8; i++) {
        size_t row = (size_t)(bm + ty * 8 + i);
        float v[4] = { acc[i][0] + bia.x, acc[i][1] + bia.y,
                       acc[i][2] + bia.z, acc[i][3] + bia.w };
        float4 r;
        if (EPI == 0) {
            r.x = 0.5f * v[0] * (1.0f + erff(v[0] * RS2));
            r.y = 0.5f * v[1] * (1.0f + erff(v[1] * RS2));
            r.z = 0.5f * v[2] * (1.0f + erff(v[2] * RS2));
            r.w = 0.5f * v[3] * (1.0f + erff(v[3] * RS2));
        } else if (EPI == 1) {
            float4 hp = *(const float4*)&Hp[row * N + bn + tx * 4];
            r.x = 0.5f * hp.x + 0.5f * tanhf(v[0]);
            r.y = 0.5f * hp.y + 0.5f * tanhf(v[1]);
            r.z = 0.5f * hp.z + 0.5f * tanhf(v[2]);
            r.w = 0.5f * hp.w + 0.5f * tanhf(v[3]);
        } else {
            r.x = v[0]; r.y = v[1]; r.z = v[2]; r.w = v[3];
        }
        *(float4*)&C[row * N + bn + tx * 4] = r;
    }
}

// ---------------- launch ----------------
extern "C" void kernel_launch(void* const* d_in, const int* in_sizes, int n_in,
                              void* d_out, int out_size) {
    const float* x     = (const float*)d_in[0];
    const float* z     = (const float*)d_in[1];
    const float* emb   = (const float*)d_in[2];
    const float* W_in1 = (const float*)d_in[3];
    const float* b_in1 = (const float*)d_in[4];
    const float* W_in2 = (const float*)d_in[5];
    const float* b_in2 = (const float*)d_in[6];
    const float* W_f1  = (const float*)d_in[7];
    const float* b_f1  = (const float*)d_in[8];
    const float* W_f2  = (const float*)d_in[9];
    const float* b_f2  = (const float*)d_in[10];
    const float* W_out = (const float*)d_in[11];
    const float* b_out = (const float*)d_in[12];
    float* out = (float*)d_out;

    void *p_feats, *p_w1p, *p_hA, *p_hB, *p_u;
    cudaGetSymbolAddress(&p_feats, g_feats);
    cudaGetSymbolAddress(&p_w1p,   g_w1p);
    cudaGetSymbolAddress(&p_hA,    g_hA);
    cudaGetSymbolAddress(&p_hB,    g_hB);
    cudaGetSymbolAddress(&p_u,     g_u);
    float* feats = (float*)p_feats;
    float* w1p   = (float*)p_w1p;
    float* hA    = (float*)p_hA;
    float* hB    = (float*)p_hB;
    float* u     = (float*)p_u;

    feats_kernel<<<BROWS / 256, 256>>>(x, z, emb);
    padw1_kernel<<<(INPAD * HID) / 256, 256>>>(W_in1);

    dim3 blk(256);
    // mlp_in layer 1: feats[8192,128] @ w1p[128,256] -> gelu -> hA
    gemm_kernel<0><<<dim3(HID / 64, BROWS / 128), blk>>>(feats, w1p, b_in1, nullptr, hA, BROWS, HID, INPAD);
    // mlp_in layer 2: hA @ W_in2[256,256] -> gelu -> hB
    gemm_kernel<0><<<dim3(HID / 64, BROWS / 128), blk>>>(hA, W_in2, b_in2, nullptr, hB, BROWS, HID, HID);

    // fractal refinement, 48 weight-tied steps
    for (int s = 0; s < NSTEPS; s++) {
        // u = gelu(hB @ W_f1[256,512] + b_f1)
        gemm_kernel<0><<<dim3(HID2 / 64, BROWS / 128), blk>>>(hB, W_f1, b_f1, nullptr, u, BROWS, HID2, HID);
        // hB = 0.5*hB + 0.5*tanh(u @ W_f2[512,256] + b_f2)   (in-place safe: elementwise epilogue)
        gemm_kernel<1><<<dim3(HID / 64, BROWS / 128), blk>>>(u, W_f2, b_f2, hB, hB, BROWS, HID, HID2);
    }

    // output head: hB @ W_out[256,32000] + b_out
    gemm_kernel<2><<<dim3(VOCAB / 64, BROWS / 128), blk>>>(hB, W_out, b_out, nullptr, out, BROWS, VOCAB, HID);
}

// round 6
// speedup vs baseline: 1.8385x; 1.8385x over previous
#include <cuda_runtime.h>
#include <cuda_bf16.h>
#include <math.h>
#include <stdint.h>

#define BROWS 8192
#define HID   256
#define HID2  512
#define VOCAB 32000
#define INPAD 128
#define NSTEPS 48

// ---------------- device scratch (static, no allocation) ----------------
__device__ __align__(16) __nv_bfloat16 g_ftH[BROWS * INPAD];
__device__ __align__(16) __nv_bfloat16 g_ftL[BROWS * INPAD];
__device__ __align__(16) __nv_bfloat16 g_w1H[HID * INPAD],  g_w1L[HID * INPAD];
__device__ __align__(16) __nv_bfloat16 g_w2H[HID * HID],    g_w2L[HID * HID];
__device__ __align__(16) __nv_bfloat16 g_f1H[HID2 * HID],   g_f1L[HID2 * HID];
__device__ __align__(16) __nv_bfloat16 g_f2H[HID * HID2],   g_f2L[HID * HID2];
__device__ __align__(16) __nv_bfloat16 g_woH[(size_t)VOCAB * HID], g_woL[(size_t)VOCAB * HID];
__device__ __align__(16) __nv_bfloat16 g_hAH[BROWS * HID],  g_hAL[BROWS * HID];
__device__ __align__(16) __nv_bfloat16 g_hBH[BROWS * HID],  g_hBL[BROWS * HID];
__device__ __align__(16) __nv_bfloat16 g_uH [BROWS * HID2], g_uL [BROWS * HID2];

// ---------------- helpers ----------------
__device__ __forceinline__ uint32_t smem_u32(const void* p) {
    uint32_t a;
    asm("{ .reg .u64 t; cvta.to.shared.u64 t, %1; cvt.u32.u64 %0, t; }" : "=r"(a) : "l"(p));
    return a;
}
__device__ __forceinline__ void split2(float v, __nv_bfloat16& h, __nv_bfloat16& l) {
    h = __float2bfloat16(v);
    l = __float2bfloat16(v - __bfloat162float(h));
}
__device__ __forceinline__ uint32_t packsplit(float v0, float v1, uint32_t& lo) {
    __nv_bfloat16 h0, l0, h1, l1;
    split2(v0, h0, l0); split2(v1, h1, l1);
    uint16_t uh0 = *(uint16_t*)&h0, uh1 = *(uint16_t*)&h1;
    uint16_t ul0 = *(uint16_t*)&l0, ul1 = *(uint16_t*)&l1;
    lo = (uint32_t)ul0 | ((uint32_t)ul1 << 16);
    return (uint32_t)uh0 | ((uint32_t)uh1 << 16);
}
__device__ __forceinline__ void cp16(uint32_t dst, const void* src) {
    asm volatile("cp.async.cg.shared.global [%0], [%1], 16;" :: "r"(dst), "l"(src));
}
__device__ __forceinline__ void ldsm4(uint32_t* r, uint32_t a) {
    asm volatile("ldmatrix.sync.aligned.m8n8.x4.shared.b16 {%0,%1,%2,%3}, [%4];"
                 : "=r"(r[0]), "=r"(r[1]), "=r"(r[2]), "=r"(r[3]) : "r"(a));
}
__device__ __forceinline__ void mma16816(float* d, const uint32_t* a, uint32_t b0, uint32_t b1) {
    asm volatile("mma.sync.aligned.m16n8k16.row.col.f32.bf16.bf16.f32 "
                 "{%0,%1,%2,%3}, {%4,%5,%6,%7}, {%8,%9}, {%0,%1,%2,%3};"
                 : "+f"(d[0]), "+f"(d[1]), "+f"(d[2]), "+f"(d[3])
                 : "r"(a[0]), "r"(a[1]), "r"(a[2]), "r"(a[3]), "r"(b0), "r"(b1));
}

// ---------------- feature assembly (bf16 hi/lo, padded to 128) ----------------
__global__ void feats_kernel(const float* __restrict__ x, const float* __restrict__ z,
                             const float* __restrict__ emb) {
    int b = blockIdx.x * blockDim.x + threadIdx.x;
    if (b >= BROWS) return;
    float xc = fminf(fmaxf(x[b], 0.0f), 1.0f);
    __nv_bfloat16* fH = g_ftH + (size_t)b * INPAD;
    __nv_bfloat16* fL = g_ftL + (size_t)b * INPAD;
    __nv_bfloat16 h, l;
    split2(xc, h, l); fH[0] = h; fL[0] = l;

    const float TWO_PI = 6.283185307179586f;
    float a = TWO_PI * xc;
    double fd = 1.0;
    #pragma unroll 1
    for (int j = 0; j < 32; j++) {
        float fr = (float)fd;
        float arg = a * fr;
        split2(sinf(arg), h, l); fH[1 + j] = h;  fL[1 + j] = l;
        split2(cosf(arg), h, l); fH[33 + j] = h; fL[33 + j] = l;
        fd *= 3.5;
    }
    float res = 16.0f;
    #pragma unroll 1
    for (int lv = 0; lv < 12; lv++) {
        float pos = xc * res;
        float i0f = floorf(pos);
        int   i0  = (int)i0f;
        float w   = pos - i0f;
        int h0 = i0 & 16383, h1 = (i0 + 1) & 16383;
        const float* t0 = emb + (size_t)h0 * 24 + lv * 2;
        const float* t1 = emb + (size_t)h1 * 24 + lv * 2;
        split2((1.0f - w) * t0[0] + w * t1[0], h, l); fH[65 + lv*2]   = h; fL[65 + lv*2]   = l;
        split2((1.0f - w) * t0[1] + w * t1[1], h, l); fH[65 + lv*2+1] = h; fL[65 + lv*2+1] = l;
        res *= 2.0f;
    }
    const float* zp = z + (size_t)b * 32;
    #pragma unroll
    for (int j = 0; j < 32; j++) { split2(zp[j], h, l); fH[89 + j] = h; fL[89 + j] = l; }
    #pragma unroll
    for (int j = 121; j < 128; j++) { fH[j] = __float2bfloat16(0.0f); fL[j] = __float2bfloat16(0.0f); }
}

// ---------------- weight transpose + split: W[Kreal][N] -> T{h,l}[N][Kpad] ----------------
__global__ void wsplit_kernel(const float* __restrict__ W, __nv_bfloat16* __restrict__ Th,
                              __nv_bfloat16* __restrict__ Tl, int Kreal, int Kpad, int N) {
    __shared__ float t[32][33];
    int kt = blockIdx.x * 32, nt = blockIdx.y * 32;
    int tx = threadIdx.x, ty = threadIdx.y;
    #pragma unroll
    for (int i = 0; i < 32; i += 8) {
        int k = kt + ty + i;
        t[ty + i][tx] = (k < Kreal) ? W[(size_t)k * N + nt + tx] : 0.0f;
    }
    __syncthreads();
    #pragma unroll
    for (int i = 0; i < 32; i += 8) {
        int n = nt + ty + i, k = kt + tx;
        __nv_bfloat16 h, l;
        split2(t[tx][ty + i], h, l);
        Th[(size_t)n * Kpad + k] = h;
        Tl[(size_t)n * Kpad + k] = l;
    }
}

// ---------------- HMMA split-bf16 GEMM ----------------
// C[M,N] = epi(A[M,K] @ B^T + bias); A[M][K], B[N][K] as bf16 hi/lo pairs.
// BM=128 BN=128 BK=32, 256 threads (8 warps: 4M x 2N), cp.async double buffer.
// EPI 0: GELU -> Ch/Cl ; 1: 0.5*(HpH+HpL)+0.5*tanh(v) -> Ch/Cl ; 2: fp32 + bias -> Cf
#define TSTR   80                 // smem row pitch bytes (32 bf16 + 16B pad)
#define TBYTES (128 * TSTR)       // 10240 per matrix
#define BUFB   (4 * TBYTES)       // Ah,Al,Bh,Bl
#define SMEMTOT (2 * BUFB)        // 81920

template <int EPI>
__global__ void __launch_bounds__(256) hgemm(
    const __nv_bfloat16* __restrict__ Ah, const __nv_bfloat16* __restrict__ Al,
    const __nv_bfloat16* __restrict__ Bh, const __nv_bfloat16* __restrict__ Bl,
    const float* __restrict__ bias,
    const __nv_bfloat16* __restrict__ HpH, const __nv_bfloat16* __restrict__ HpL,
    __nv_bfloat16* __restrict__ Ch, __nv_bfloat16* __restrict__ Cl,
    float* __restrict__ Cf, int N, int K)
{
    extern __shared__ char smem[];
    const uint32_t sb = smem_u32(smem);
    const int tid  = threadIdx.x;
    const int lane = tid & 31, wid = tid >> 5;
    const int wm = wid & 3, wn = wid >> 2;
    const int bm = blockIdx.y * 128, bn = blockIdx.x * 128;
    const int nchunks = K >> 5;

    float acc[2][8][4];
    #pragma unroll
    for (int a = 0; a < 2; a++)
        #pragma unroll
        for (int b = 0; b < 8; b++)
            #pragma unroll
            for (int c = 0; c < 4; c++) acc[a][b][c] = 0.0f;

    const __nv_bfloat16* gsrc[4] = {Ah, Al, Bh, Bl};

    auto load_chunk = [&](int c, int buf) {
        const int k0 = c << 5;
        uint32_t base = sb + buf * BUFB;
        #pragma unroll
        for (int t4 = 0; t4 < 4; t4++) {
            const __nv_bfloat16* g = gsrc[t4];
            int rb = (t4 < 2) ? bm : bn;
            #pragma unroll
            for (int i = 0; i < 2; i++) {
                int idx = tid + i * 256;              // 0..511
                int row = idx >> 2, c16 = idx & 3;
                uint32_t dst = base + t4 * TBYTES + row * TSTR + c16 * 16;
                cp16(dst, g + (size_t)(rb + row) * K + k0 + c16 * 8);
            }
        }
    };

    // ldmatrix lane geometry
    const int mat = lane >> 3, rin = lane & 7;
    const int lrow = (mat & 1) * 8 + rin;       // row within 16-block
    const int kof  = (mat >> 1) * 8;            // 0 or 8 (bf16 elems)

    load_chunk(0, 0);
    asm volatile("cp.async.commit_group;" ::: "memory");

    for (int c = 0; c < nchunks; c++) {
        const int buf = c & 1;
        if (c + 1 < nchunks) load_chunk(c + 1, buf ^ 1);
        asm volatile("cp.async.commit_group;" ::: "memory");
        if (c + 1 < nchunks) asm volatile("cp.async.wait_group 1;" ::: "memory");
        else                 asm volatile("cp.async.wait_group 0;" ::: "memory");
        __syncthreads();

        const uint32_t sa = sb + buf * BUFB;
        #pragma unroll
        for (int k16 = 0; k16 < 32; k16 += 16) {
            uint32_t ahf[2][4], alf[2][4];
            #pragma unroll
            for (int mt = 0; mt < 2; mt++) {
                uint32_t ad = sa + (wm * 32 + mt * 16 + lrow) * TSTR + (k16 + kof) * 2;
                ldsm4(ahf[mt], ad);
                ldsm4(alf[mt], ad + TBYTES);
            }
            uint32_t bhf[4][4], blf[4][4];
            #pragma unroll
            for (int g = 0; g < 4; g++) {
                uint32_t bd = sa + 2 * TBYTES + (wn * 64 + g * 16 + lrow) * TSTR + (k16 + kof) * 2;
                ldsm4(bhf[g], bd);
                ldsm4(blf[g], bd + TBYTES);
            }
            // term hi*hi
            #pragma unroll
            for (int nj = 0; nj < 8; nj++) {
                uint32_t b0 = bhf[nj >> 1][nj & 1], b1 = bhf[nj >> 1][2 + (nj & 1)];
                mma16816(acc[0][nj], ahf[0], b0, b1);
                mma16816(acc[1][nj], ahf[1], b0, b1);
            }
            // term hi*lo
            #pragma unroll
            for (int nj = 0; nj < 8; nj++) {
                uint32_t b0 = blf[nj >> 1][nj & 1], b1 = blf[nj >> 1][2 + (nj & 1)];
                mma16816(acc[0][nj], ahf[0], b0, b1);
                mma16816(acc[1][nj], ahf[1], b0, b1);
            }
            // term lo*hi
            #pragma unroll
            for (int nj = 0; nj < 8; nj++) {
                uint32_t b0 = bhf[nj >> 1][nj & 1], b1 = bhf[nj >> 1][2 + (nj & 1)];
                mma16816(acc[0][nj], alf[0], b0, b1);
                mma16816(acc[1][nj], alf[1], b0, b1);
            }
        }
        __syncthreads();
    }

    // -------- epilogue --------
    const float RS2 = 0.70710678118654752f;
    #pragma unroll
    for (int mt = 0; mt < 2; mt++) {
        #pragma unroll
        for (int nj = 0; nj < 8; nj++) {
            float* d = acc[mt][nj];
            int rg = bm + wm * 32 + mt * 16 + (lane >> 2);
            int cg = bn + wn * 64 + nj * 8 + (lane & 3) * 2;
            float bb0 = bias[cg], bb1 = bias[cg + 1];
            size_t off0 = (size_t)rg * N + cg;
            size_t off1 = (size_t)(rg + 8) * N + cg;
            if (EPI == 2) {
                float2 v0 = make_float2(d[0] + bb0, d[1] + bb1);
                float2 v1 = make_float2(d[2] + bb0, d[3] + bb1);
                *(float2*)(Cf + off0) = v0;
                *(float2*)(Cf + off1) = v1;
            } else {
                float v[4] = {d[0] + bb0, d[1] + bb1, d[2] + bb0, d[3] + bb1};
                float o[4];
                if (EPI == 0) {
                    #pragma unroll
                    for (int j = 0; j < 4; j++)
                        o[j] = 0.5f * v[j] * (1.0f + erff(v[j] * RS2));
                } else {
                    __nv_bfloat162 hh0 = *(const __nv_bfloat162*)(HpH + off0);
                    __nv_bfloat162 hl0 = *(const __nv_bfloat162*)(HpL + off0);
                    __nv_bfloat162 hh1 = *(const __nv_bfloat162*)(HpH + off1);
                    __nv_bfloat162 hl1 = *(const __nv_bfloat162*)(HpL + off1);
                    o[0] = 0.5f * (__bfloat162float(hh0.x) + __bfloat162float(hl0.x)) + 0.5f * tanhf(v[0]);
                    o[1] = 0.5f * (__bfloat162float(hh0.y) + __bfloat162float(hl0.y)) + 0.5f * tanhf(v[1]);
                    o[2] = 0.5f * (__bfloat162float(hh1.x) + __bfloat162float(hl1.x)) + 0.5f * tanhf(v[2]);
                    o[3] = 0.5f * (__bfloat162float(hh1.y) + __bfloat162float(hl1.y)) + 0.5f * tanhf(v[3]);
                }
                uint32_t lo0, lo1;
                uint32_t hi0 = packsplit(o[0], o[1], lo0);
                uint32_t hi1 = packsplit(o[2], o[3], lo1);
                *(uint32_t*)(Ch + off0) = hi0;  *(uint32_t*)(Cl + off0) = lo0;
                *(uint32_t*)(Ch + off1) = hi1;  *(uint32_t*)(Cl + off1) = lo1;
            }
        }
    }
}

// ---------------- launch ----------------
extern "C" void kernel_launch(void* const* d_in, const int* in_sizes, int n_in,
                              void* d_out, int out_size) {
    const float* x     = (const float*)d_in[0];
    const float* z     = (const float*)d_in[1];
    const float* emb   = (const float*)d_in[2];
    const float* W_in1 = (const float*)d_in[3];
    const float* b_in1 = (const float*)d_in[4];
    const float* W_in2 = (const float*)d_in[5];
    const float* b_in2 = (const float*)d_in[6];
    const float* W_f1  = (const float*)d_in[7];
    const float* b_f1  = (const float*)d_in[8];
    const float* W_f2  = (const float*)d_in[9];
    const float* b_f2  = (const float*)d_in[10];
    const float* W_out = (const float*)d_in[11];
    const float* b_out = (const float*)d_in[12];
    float* out = (float*)d_out;

    cudaFuncSetAttribute(hgemm<0>, cudaFuncAttributeMaxDynamicSharedMemorySize, SMEMTOT);
    cudaFuncSetAttribute(hgemm<1>, cudaFuncAttributeMaxDynamicSharedMemorySize, SMEMTOT);
    cudaFuncSetAttribute(hgemm<2>, cudaFuncAttributeMaxDynamicSharedMemorySize, SMEMTOT);

    #define SYM(p, s) void* p; cudaGetSymbolAddress(&p, s)
    SYM(ftH, g_ftH); SYM(ftL, g_ftL);
    SYM(w1H, g_w1H); SYM(w1L, g_w1L);
    SYM(w2H, g_w2H); SYM(w2L, g_w2L);
    SYM(f1H, g_f1H); SYM(f1L, g_f1L);
    SYM(f2H, g_f2H); SYM(f2L, g_f2L);
    SYM(woH, g_woH); SYM(woL, g_woL);
    SYM(hAH, g_hAH); SYM(hAL, g_hAL);
    SYM(hBH, g_hBH); SYM(hBL, g_hBL);
    SYM(uH,  g_uH);  SYM(uL,  g_uL);
    #undef SYM
    typedef __nv_bfloat16 bf;

    feats_kernel<<<BROWS / 256, 256>>>(x, z, emb);
    dim3 wb(32, 8);
    wsplit_kernel<<<dim3(INPAD / 32, HID / 32),  wb>>>(W_in1, (bf*)w1H, (bf*)w1L, 121, INPAD, HID);
    wsplit_kernel<<<dim3(HID / 32,  HID / 32),   wb>>>(W_in2, (bf*)w2H, (bf*)w2L, HID, HID, HID);
    wsplit_kernel<<<dim3(HID / 32,  HID2 / 32),  wb>>>(W_f1,  (bf*)f1H, (bf*)f1L, HID, HID, HID2);
    wsplit_kernel<<<dim3(HID2 / 32, HID / 32),   wb>>>(W_f2,  (bf*)f2H, (bf*)f2L, HID2, HID2, HID);
    wsplit_kernel<<<dim3(HID / 32,  VOCAB / 32), wb>>>(W_out, (bf*)woH, (bf*)woL, HID, HID, VOCAB);

    // mlp_in
    hgemm<0><<<dim3(HID / 128, BROWS / 128), 256, SMEMTOT>>>(
        (bf*)ftH, (bf*)ftL, (bf*)w1H, (bf*)w1L, b_in1, nullptr, nullptr,
        (bf*)hAH, (bf*)hAL, nullptr, HID, INPAD);
    hgemm<0><<<dim3(HID / 128, BROWS / 128), 256, SMEMTOT>>>(
        (bf*)hAH, (bf*)hAL, (bf*)w2H, (bf*)w2L, b_in2, nullptr, nullptr,
        (bf*)hBH, (bf*)hBL, nullptr, HID, HID);

    // fractal refinement: 48 weight-tied steps
    for (int s = 0; s < NSTEPS; s++) {
        hgemm<0><<<dim3(HID2 / 128, BROWS / 128), 256, SMEMTOT>>>(
            (bf*)hBH, (bf*)hBL, (bf*)f1H, (bf*)f1L, b_f1, nullptr, nullptr,
            (bf*)uH, (bf*)uL, nullptr, HID2, HID);
        hgemm<1><<<dim3(HID / 128, BROWS / 128), 256, SMEMTOT>>>(
            (bf*)uH, (bf*)uL, (bf*)f2H, (bf*)f2L, b_f2, (bf*)hBH, (bf*)hBL,
            (bf*)hBH, (bf*)hBL, nullptr, HID, HID2);
    }

    // output head
    hgemm<2><<<dim3(VOCAB / 128, BROWS / 128), 256, SMEMTOT>>>(
        (bf*)hBH, (bf*)hBL, (bf*)woH, (bf*)woL, b_out, nullptr, nullptr,
        nullptr, nullptr, out, VOCAB, HID);
}

// round 7
// speedup vs baseline: 2.2186x; 1.2068x over previous
#include <cuda_runtime.h>
#include <cuda_bf16.h>
#include <math.h>
#include <stdint.h>

#define BROWS 8192
#define HID   256
#define HID2  512
#define VOCAB 32000
#define INPAD 128
#define NSTEPS 48

// ---------------- device scratch (static, no allocation) ----------------
__device__ __align__(16) __nv_bfloat16 g_ftH[BROWS * INPAD];
__device__ __align__(16) __nv_bfloat16 g_ftL[BROWS * INPAD];
__device__ __align__(16) __nv_bfloat16 g_w1H[HID * INPAD],  g_w1L[HID * INPAD];
__device__ __align__(16) __nv_bfloat16 g_w2H[HID * HID],    g_w2L[HID * HID];
__device__ __align__(16) __nv_bfloat16 g_woH[(size_t)VOCAB * HID], g_woL[(size_t)VOCAB * HID];
__device__ __align__(16) __nv_bfloat16 g_hAH[BROWS * HID],  g_hAL[BROWS * HID];
__device__ __align__(16) __nv_bfloat16 g_hBH[BROWS * HID],  g_hBL[BROWS * HID];
// packed weight panels for the fractal loop (ldmatrix-ready, 80B pitch rows)
// W_f1: 32 panels (nt 0..3 x kc 0..7): [128n][32k] hi(10240) + lo(10240) = 20480 B
__device__ __align__(16) unsigned char g_p1[32 * 20480];
// W_f2: 16 panels (nt 0..3 x kc2 0..3): [256n][32k] hi(20480) + lo(20480) = 40960 B
__device__ __align__(16) unsigned char g_p2[16 * 40960];

// ---------------- helpers ----------------
__device__ __forceinline__ uint32_t smem_u32(const void* p) {
    uint32_t a;
    asm("{ .reg .u64 t; cvta.to.shared.u64 t, %1; cvt.u32.u64 %0, t; }" : "=r"(a) : "l"(p));
    return a;
}
__device__ __forceinline__ void split2(float v, __nv_bfloat16& h, __nv_bfloat16& l) {
    h = __float2bfloat16(v);
    l = __float2bfloat16(v - __bfloat162float(h));
}
__device__ __forceinline__ uint32_t packsplit(float v0, float v1, uint32_t& lo) {
    __nv_bfloat16 h0, l0, h1, l1;
    split2(v0, h0, l0); split2(v1, h1, l1);
    uint16_t uh0 = *(uint16_t*)&h0, uh1 = *(uint16_t*)&h1;
    uint16_t ul0 = *(uint16_t*)&l0, ul1 = *(uint16_t*)&l1;
    lo = (uint32_t)ul0 | ((uint32_t)ul1 << 16);
    return (uint32_t)uh0 | ((uint32_t)uh1 << 16);
}
__device__ __forceinline__ void cp16(uint32_t dst, const void* src) {
    asm volatile("cp.async.cg.shared.global [%0], [%1], 16;" :: "r"(dst), "l"(src));
}
__device__ __forceinline__ void ldsm4(uint32_t* r, uint32_t a) {
    asm volatile("ldmatrix.sync.aligned.m8n8.x4.shared.b16 {%0,%1,%2,%3}, [%4];"
                 : "=r"(r[0]), "=r"(r[1]), "=r"(r[2]), "=r"(r[3]) : "r"(a));
}
__device__ __forceinline__ void mma16816(float* d, const uint32_t* a, uint32_t b0, uint32_t b1) {
    asm volatile("mma.sync.aligned.m16n8k16.row.col.f32.bf16.bf16.f32 "
                 "{%0,%1,%2,%3}, {%4,%5,%6,%7}, {%8,%9}, {%0,%1,%2,%3};"
                 : "+f"(d[0]), "+f"(d[1]), "+f"(d[2]), "+f"(d[3])
                 : "r"(a[0]), "r"(a[1]), "r"(a[2]), "r"(a[3]), "r"(b0), "r"(b1));
}
__device__ __forceinline__ void bulkcp(uint32_t dst, const void* src, uint32_t bytes, uint32_t mbar) {
    asm volatile("cp.async.bulk.shared::cluster.global.mbarrier::complete_tx::bytes [%0], [%1], %2, [%3];"
                 :: "r"(dst), "l"(src), "r"(bytes), "r"(mbar) : "memory");
}
#define MBAR_INIT(a, c) \
    asm volatile("mbarrier.init.shared.b64 [%0], %1;" :: "r"(a), "r"((uint32_t)(c)) : "memory")
#define MBAR_EXPECT_TX(a, bytes) \
    asm volatile("mbarrier.arrive.expect_tx.shared.b64 _, [%0], %1;" :: "r"(a), "r"((uint32_t)(bytes)) : "memory")
#define MBAR_WAIT(a, p) do {                                                      \
    uint32_t _m = (a), _p = (uint32_t)(p), _d;                                    \
    asm volatile("{ .reg .pred q; mbarrier.try_wait.parity.acquire.cta.shared::cta.b64 q, [%1], %2; " \
                 "selp.b32 %0, 1, 0, q; }" : "=r"(_d) : "r"(_m), "r"(_p) : "memory"); \
    if (!_d) {                                                                    \
        asm volatile("{ .reg .pred Q; WL_%=: mbarrier.try_wait.parity.acquire.cta.shared::cta.b64 Q, [%0], %1, 0x989680; " \
                     "@Q bra.uni WD_%=; bra.uni WL_%=; WD_%=: }" :: "r"(_m), "r"(_p) : "memory"); \
    } } while (0)

// ---------------- feature assembly (bf16 hi/lo, padded to 128) ----------------
__global__ void feats_kernel(const float* __restrict__ x, const float* __restrict__ z,
                             const float* __restrict__ emb) {
    int b = blockIdx.x * blockDim.x + threadIdx.x;
    if (b >= BROWS) return;
    float xc = fminf(fmaxf(x[b], 0.0f), 1.0f);
    __nv_bfloat16* fH = g_ftH + (size_t)b * INPAD;
    __nv_bfloat16* fL = g_ftL + (size_t)b * INPAD;
    __nv_bfloat16 h, l;
    split2(xc, h, l); fH[0] = h; fL[0] = l;

    const float TWO_PI = 6.283185307179586f;
    float a = TWO_PI * xc;
    double fd = 1.0;
    #pragma unroll 1
    for (int j = 0; j < 32; j++) {
        float fr = (float)fd;
        float arg = a * fr;
        split2(sinf(arg), h, l); fH[1 + j] = h;  fL[1 + j] = l;
        split2(cosf(arg), h, l); fH[33 + j] = h; fL[33 + j] = l;
        fd *= 3.5;
    }
    float res = 16.0f;
    #pragma unroll 1
    for (int lv = 0; lv < 12; lv++) {
        float pos = xc * res;
        float i0f = floorf(pos);
        int   i0  = (int)i0f;
        float w   = pos - i0f;
        int h0 = i0 & 16383, h1 = (i0 + 1) & 16383;
        const float* t0 = emb + (size_t)h0 * 24 + lv * 2;
        const float* t1 = emb + (size_t)h1 * 24 + lv * 2;
        split2((1.0f - w) * t0[0] + w * t1[0], h, l); fH[65 + lv*2]   = h; fL[65 + lv*2]   = l;
        split2((1.0f - w) * t0[1] + w * t1[1], h, l); fH[65 + lv*2+1] = h; fL[65 + lv*2+1] = l;
        res *= 2.0f;
    }
    const float* zp = z + (size_t)b * 32;
    #pragma unroll
    for (int j = 0; j < 32; j++) { split2(zp[j], h, l); fH[89 + j] = h; fL[89 + j] = l; }
    #pragma unroll
    for (int j = 121; j < 128; j++) { fH[j] = __float2bfloat16(0.0f); fL[j] = __float2bfloat16(0.0f); }
}

// ---------------- weight transpose + split: W[Kreal][N] -> T{h,l}[N][Kpad] ----------------
__global__ void wsplit_kernel(const float* __restrict__ W, __nv_bfloat16* __restrict__ Th,
                              __nv_bfloat16* __restrict__ Tl, int Kreal, int Kpad, int N) {
    __shared__ float t[32][33];
    int kt = blockIdx.x * 32, nt = blockIdx.y * 32;
    int tx = threadIdx.x, ty = threadIdx.y;
    #pragma unroll
    for (int i = 0; i < 32; i += 8) {
        int k = kt + ty + i;
        t[ty + i][tx] = (k < Kreal) ? W[(size_t)k * N + nt + tx] : 0.0f;
    }
    __syncthreads();
    #pragma unroll
    for (int i = 0; i < 32; i += 8) {
        int n = nt + ty + i, k = kt + tx;
        __nv_bfloat16 h, l;
        split2(t[tx][ty + i], h, l);
        Th[(size_t)n * Kpad + k] = h;
        Tl[(size_t)n * Kpad + k] = l;
    }
}

// ---------------- pack W_f1 [256k][512n] into 32 bulk panels ----------------
__global__ void pack_f1(const float* __restrict__ W) {
    int i = blockIdx.x * 256 + threadIdx.x;
    if (i >= HID * HID2) return;
    int k = i / HID2, n = i % HID2;
    __nv_bfloat16 h, l; split2(W[i], h, l);
    int nt = n >> 7, nl = n & 127, kc = k >> 5, kl = k & 31;
    size_t base = (size_t)(nt * 8 + kc) * 20480;
    *(__nv_bfloat16*)(g_p1 + base + nl * 80 + kl * 2) = h;
    *(__nv_bfloat16*)(g_p1 + base + 10240 + nl * 80 + kl * 2) = l;
}
// ---------------- pack W_f2 [512k][256n] into 16 bulk panels ----------------
__global__ void pack_f2(const float* __restrict__ W) {
    int i = blockIdx.x * 256 + threadIdx.x;
    if (i >= HID2 * HID) return;
    int k = i / HID, n = i % HID;
    __nv_bfloat16 h, l; split2(W[i], h, l);
    int nt = k >> 7, kc = (k >> 5) & 3, kl = k & 31;
    size_t base = (size_t)(nt * 4 + kc) * 40960;
    *(__nv_bfloat16*)(g_p2 + base + n * 80 + kl * 2) = h;
    *(__nv_bfloat16*)(g_p2 + base + 20480 + n * 80 + kl * 2) = l;
}

// ---------------- HMMA split-bf16 GEMM (mlp_in + head) ----------------
#define TSTR   80
#define TBYTES (128 * TSTR)
#define BUFB   (4 * TBYTES)
#define SMEMTOT (2 * BUFB)

template <int EPI>   // 0: GELU -> Ch/Cl ; 2: fp32 + bias -> Cf
__global__ void __launch_bounds__(256) hgemm(
    const __nv_bfloat16* __restrict__ Ah, const __nv_bfloat16* __restrict__ Al,
    const __nv_bfloat16* __restrict__ Bh, const __nv_bfloat16* __restrict__ Bl,
    const float* __restrict__ bias,
    __nv_bfloat16* __restrict__ Ch, __nv_bfloat16* __restrict__ Cl,
    float* __restrict__ Cf, int N, int K)
{
    extern __shared__ char smem[];
    const uint32_t sb = smem_u32(smem);
    const int tid  = threadIdx.x;
    const int lane = tid & 31, wid = tid >> 5;
    const int wm = wid & 3, wn = wid >> 2;
    const int bm = blockIdx.y * 128, bn = blockIdx.x * 128;
    const int nchunks = K >> 5;

    float acc[2][8][4];
    #pragma unroll
    for (int a = 0; a < 2; a++)
        #pragma unroll
        for (int b = 0; b < 8; b++)
            #pragma unroll
            for (int c = 0; c < 4; c++) acc[a][b][c] = 0.0f;

    const __nv_bfloat16* gsrc[4] = {Ah, Al, Bh, Bl};

    auto load_chunk = [&](int c, int buf) {
        const int k0 = c << 5;
        uint32_t base = sb + buf * BUFB;
        #pragma unroll
        for (int t4 = 0; t4 < 4; t4++) {
            const __nv_bfloat16* g = gsrc[t4];
            int rb = (t4 < 2) ? bm : bn;
            #pragma unroll
            for (int i = 0; i < 2; i++) {
                int idx = tid + i * 256;
                int row = idx >> 2, c16 = idx & 3;
                uint32_t dst = base + t4 * TBYTES + row * TSTR + c16 * 16;
                cp16(dst, g + (size_t)(rb + row) * K + k0 + c16 * 8);
            }
        }
    };

    const int mat = lane >> 3, rin = lane & 7;
    const int lrow = (mat & 1) * 8 + rin;
    const int kof  = (mat >> 1) * 8;

    load_chunk(0, 0);
    asm volatile("cp.async.commit_group;" ::: "memory");

    for (int c = 0; c < nchunks; c++) {
        const int buf = c & 1;
        if (c + 1 < nchunks) load_chunk(c + 1, buf ^ 1);
        asm volatile("cp.async.commit_group;" ::: "memory");
        if (c + 1 < nchunks) asm volatile("cp.async.wait_group 1;" ::: "memory");
        else                 asm volatile("cp.async.wait_group 0;" ::: "memory");
        __syncthreads();

        const uint32_t sa = sb + buf * BUFB;
        #pragma unroll
        for (int k16 = 0; k16 < 32; k16 += 16) {
            uint32_t ahf[2][4], alf[2][4];
            #pragma unroll
            for (int mt = 0; mt < 2; mt++) {
                uint32_t ad = sa + (wm * 32 + mt * 16 + lrow) * TSTR + (k16 + kof) * 2;
                ldsm4(ahf[mt], ad);
                ldsm4(alf[mt], ad + TBYTES);
            }
            uint32_t bhf[4][4], blf[4][4];
            #pragma unroll
            for (int g = 0; g < 4; g++) {
                uint32_t bd = sa + 2 * TBYTES + (wn * 64 + g * 16 + lrow) * TSTR + (k16 + kof) * 2;
                ldsm4(bhf[g], bd);
                ldsm4(blf[g], bd + TBYTES);
            }
            #pragma unroll
            for (int nj = 0; nj < 8; nj++) {
                uint32_t b0 = bhf[nj >> 1][nj & 1], b1 = bhf[nj >> 1][2 + (nj & 1)];
                mma16816(acc[0][nj], ahf[0], b0, b1);
                mma16816(acc[1][nj], ahf[1], b0, b1);
            }
            #pragma unroll
            for (int nj = 0; nj < 8; nj++) {
                uint32_t b0 = blf[nj >> 1][nj & 1], b1 = blf[nj >> 1][2 + (nj & 1)];
                mma16816(acc[0][nj], ahf[0], b0, b1);
                mma16816(acc[1][nj], ahf[1], b0, b1);
            }
            #pragma unroll
            for (int nj = 0; nj < 8; nj++) {
                uint32_t b0 = bhf[nj >> 1][nj & 1], b1 = bhf[nj >> 1][2 + (nj & 1)];
                mma16816(acc[0][nj], alf[0], b0, b1);
                mma16816(acc[1][nj], alf[1], b0, b1);
            }
        }
        __syncthreads();
    }

    const float RS2 = 0.70710678118654752f;
    #pragma unroll
    for (int mt = 0; mt < 2; mt++) {
        #pragma unroll
        for (int nj = 0; nj < 8; nj++) {
            float* d = acc[mt][nj];
            int rg = bm + wm * 32 + mt * 16 + (lane >> 2);
            int cg = bn + wn * 64 + nj * 8 + (lane & 3) * 2;
            float bb0 = bias[cg], bb1 = bias[cg + 1];
            size_t off0 = (size_t)rg * N + cg;
            size_t off1 = (size_t)(rg + 8) * N + cg;
            if (EPI == 2) {
                *(float2*)(Cf + off0) = make_float2(d[0] + bb0, d[1] + bb1);
                *(float2*)(Cf + off1) = make_float2(d[2] + bb0, d[3] + bb1);
            } else {
                float v[4] = {d[0] + bb0, d[1] + bb1, d[2] + bb0, d[3] + bb1};
                float o[4];
                #pragma unroll
                for (int j = 0; j < 4; j++)
                    o[j] = 0.5f * v[j] * (1.0f + erff(v[j] * RS2));
                uint32_t lo0, lo1;
                uint32_t hi0 = packsplit(o[0], o[1], lo0);
                uint32_t hi1 = packsplit(o[2], o[3], lo1);
                *(uint32_t*)(Ch + off0) = hi0;  *(uint32_t*)(Cl + off0) = lo0;
                *(uint32_t*)(Ch + off1) = hi1;  *(uint32_t*)(Cl + off1) = lo1;
            }
        }
    }
}

// ---------------- persistent fractal loop kernel ----------------
// 128 CTAs x 64 rows. hB + u in smem for all 48 steps; weights stream via cp.async.bulk.
#define FM       64
#define SM_HBH   0
#define SM_HBL   33792          // 64*528
#define SM_UH    67584
#define SM_UL    84992          // +64*272
#define SM_WS0   102400
#define SM_WS1   143360         // +40960
#define SM_MB    184320
#define SMEM_FRAC 184336
#define NCHUNK_TOT (NSTEPS * 48)

__global__ void __launch_bounds__(256) fractal_kernel(
    __nv_bfloat16* __restrict__ hBH, __nv_bfloat16* __restrict__ hBL,
    const unsigned char* __restrict__ p1, const unsigned char* __restrict__ p2,
    const float* __restrict__ b_f1, const float* __restrict__ b_f2)
{
    extern __shared__ char smem[];
    const uint32_t sb = smem_u32(smem);
    const int tid = threadIdx.x, lane = tid & 31, wid = tid >> 5;
    const int wm = wid & 3, wn = wid >> 2;
    const int bm = blockIdx.x * FM;
    const int mat = lane >> 3, rin = lane & 7;
    const int lrow = (mat & 1) * 8 + rin;
    const int kof  = (mat >> 1) * 8;
    const float RS2 = 0.70710678118654752f;

    if (tid == 0) { MBAR_INIT(sb + SM_MB, 1); MBAR_INIT(sb + SM_MB + 8, 1); }
    // load hB block into smem (pitch 528)
    for (int i = tid; i < 2048; i += 256) {
        int row = i >> 5, c8 = i & 31;
        *(uint4*)(smem + SM_HBH + row * 528 + c8 * 16) = *(const uint4*)(hBH + (size_t)(bm + row) * 256 + c8 * 8);
        *(uint4*)(smem + SM_HBL + row * 528 + c8 * 16) = *(const uint4*)(hBL + (size_t)(bm + row) * 256 + c8 * 8);
    }
    __syncthreads();

    auto issue = [&](int j) {
        int jj = j % 48;
        int nt = jj / 12, pi = jj % 12;
        const unsigned char* src; uint32_t bytes;
        if (pi < 8) { src = p1 + (size_t)(nt * 8 + pi) * 20480;       bytes = 20480; }
        else        { src = p2 + (size_t)(nt * 4 + (pi - 8)) * 40960; bytes = 40960; }
        uint32_t mb = sb + SM_MB + (j & 1) * 8;
        MBAR_EXPECT_TX(mb, bytes);
        bulkcp(sb + ((j & 1) ? SM_WS1 : SM_WS0), src, bytes, mb);
    };
    if (tid == 0) { issue(0); issue(1); }
    int cidx = 2, cc = 0, ph0 = 0, ph1 = 0;

    #pragma unroll 1
    for (int step = 0; step < NSTEPS; step++) {
        float acc2[16][4];
        #pragma unroll
        for (int a = 0; a < 16; a++)
            #pragma unroll
            for (int b = 0; b < 4; b++) acc2[a][b] = 0.0f;

        #pragma unroll 1
        for (int nt = 0; nt < 4; nt++) {
            // ---- GEMM1: u_tile[64,128] = hB[64,256] @ W_f1_panel^T ----
            float acc1[8][4];
            #pragma unroll
            for (int a = 0; a < 8; a++)
                #pragma unroll
                for (int b = 0; b < 4; b++) acc1[a][b] = 0.0f;

            #pragma unroll 1
            for (int kc = 0; kc < 8; kc++) {
                if ((cc & 1) == 0) { MBAR_WAIT(sb + SM_MB,     ph0); ph0 ^= 1; }
                else               { MBAR_WAIT(sb + SM_MB + 8, ph1); ph1 ^= 1; }
                const uint32_t ws = sb + ((cc & 1) ? SM_WS1 : SM_WS0);
                #pragma unroll
                for (int k16 = 0; k16 < 32; k16 += 16) {
                    int kg = kc * 32 + k16;
                    uint32_t ahf[4], alf[4];
                    uint32_t ad = sb + SM_HBH + (wm * 16 + lrow) * 528 + (kg + kof) * 2;
                    ldsm4(ahf, ad); ldsm4(alf, ad + (SM_HBL - SM_HBH));
                    uint32_t bh[4][4], bl[4][4];
                    #pragma unroll
                    for (int g = 0; g < 4; g++) {
                        uint32_t bd = ws + (wn * 64 + g * 16 + lrow) * 80 + (k16 + kof) * 2;
                        ldsm4(bh[g], bd); ldsm4(bl[g], bd + 10240);
                    }
                    #pragma unroll
                    for (int nj = 0; nj < 8; nj++) {
                        uint32_t b0 = bh[nj >> 1][nj & 1], b1 = bh[nj >> 1][2 + (nj & 1)];
                        uint32_t c0 = bl[nj >> 1][nj & 1], c1 = bl[nj >> 1][2 + (nj & 1)];
                        mma16816(acc1[nj], ahf, b0, b1);
                        mma16816(acc1[nj], ahf, c0, c1);
                        mma16816(acc1[nj], alf, b0, b1);
                    }
                }
                __syncthreads();
                if (tid == 0 && cidx < NCHUNK_TOT) issue(cidx);
                cidx++; cc++;
            }
            // u epilogue: gelu + split -> u smem (pitch 272)
            {
                int r0 = wm * 16 + (lane >> 2);
                #pragma unroll
                for (int nj = 0; nj < 8; nj++) {
                    int c = wn * 64 + nj * 8 + (lane & 3) * 2;
                    float bb0 = b_f1[nt * 128 + c], bb1 = b_f1[nt * 128 + c + 1];
                    float v[4] = {acc1[nj][0] + bb0, acc1[nj][1] + bb1,
                                  acc1[nj][2] + bb0, acc1[nj][3] + bb1};
                    float o[4];
                    #pragma unroll
                    for (int j = 0; j < 4; j++) o[j] = 0.5f * v[j] * (1.0f + erff(v[j] * RS2));
                    uint32_t lo0, lo1;
                    uint32_t hi0 = packsplit(o[0], o[1], lo0);
                    uint32_t hi1 = packsplit(o[2], o[3], lo1);
                    *(uint32_t*)(smem + SM_UH + (size_t)r0 * 272 + c * 2)       = hi0;
                    *(uint32_t*)(smem + SM_UL + (size_t)r0 * 272 + c * 2)       = lo0;
                    *(uint32_t*)(smem + SM_UH + (size_t)(r0 + 8) * 272 + c * 2) = hi1;
                    *(uint32_t*)(smem + SM_UL + (size_t)(r0 + 8) * 272 + c * 2) = lo1;
                }
            }
            __syncthreads();
            // ---- GEMM2 partial: acc2 += u_tile[64,128] @ W_f2_panel^T ----
            #pragma unroll 1
            for (int kc2 = 0; kc2 < 4; kc2++) {
                if ((cc & 1) == 0) { MBAR_WAIT(sb + SM_MB,     ph0); ph0 ^= 1; }
                else               { MBAR_WAIT(sb + SM_MB + 8, ph1); ph1 ^= 1; }
                const uint32_t ws = sb + ((cc & 1) ? SM_WS1 : SM_WS0);
                #pragma unroll
                for (int k16 = 0; k16 < 32; k16 += 16) {
                    int kl = kc2 * 32 + k16;
                    uint32_t ahf[4], alf[4];
                    uint32_t ad = sb + SM_UH + (wm * 16 + lrow) * 272 + (kl + kof) * 2;
                    ldsm4(ahf, ad); ldsm4(alf, ad + (SM_UL - SM_UH));
                    #pragma unroll
                    for (int g = 0; g < 8; g++) {
                        uint32_t bd = ws + (wn * 128 + g * 16 + lrow) * 80 + (k16 + kof) * 2;
                        uint32_t bh[4], bl2[4];
                        ldsm4(bh, bd); ldsm4(bl2, bd + 20480);
                        #pragma unroll
                        for (int s = 0; s < 2; s++) {
                            int nj = g * 2 + s;
                            mma16816(acc2[nj], ahf, bh[s],  bh[2 + s]);
                            mma16816(acc2[nj], ahf, bl2[s], bl2[2 + s]);
                            mma16816(acc2[nj], alf, bh[s],  bh[2 + s]);
                        }
                    }
                }
                __syncthreads();
                if (tid == 0 && cidx < NCHUNK_TOT) issue(cidx);
                cidx++; cc++;
            }
        }
        // hB epilogue: hB = 0.5*hB + 0.5*tanh(acc2 + b_f2)
        {
            int r0 = wm * 16 + (lane >> 2);
            #pragma unroll
            for (int nj = 0; nj < 16; nj++) {
                int c = wn * 128 + nj * 8 + (lane & 3) * 2;
                float bb0 = b_f2[c], bb1 = b_f2[c + 1];
                #pragma unroll
                for (int p = 0; p < 2; p++) {
                    int r = r0 + p * 8;
                    float v0 = acc2[nj][p * 2]     + bb0;
                    float v1 = acc2[nj][p * 2 + 1] + bb1;
                    uint32_t ohr = *(uint32_t*)(smem + SM_HBH + (size_t)r * 528 + c * 2);
                    uint32_t olr = *(uint32_t*)(smem + SM_HBL + (size_t)r * 528 + c * 2);
                    __nv_bfloat162 oh2 = *(__nv_bfloat162*)&ohr;
                    __nv_bfloat162 ol2 = *(__nv_bfloat162*)&olr;
                    float o0 = __bfloat162float(oh2.x) + __bfloat162float(ol2.x);
                    float o1 = __bfloat162float(oh2.y) + __bfloat162float(ol2.y);
                    float n0 = 0.5f * o0 + 0.5f * tanhf(v0);
                    float n1 = 0.5f * o1 + 0.5f * tanhf(v1);
                    uint32_t lo; uint32_t hi = packsplit(n0, n1, lo);
                    *(uint32_t*)(smem + SM_HBH + (size_t)r * 528 + c * 2) = hi;
                    *(uint32_t*)(smem + SM_HBL + (size_t)r * 528 + c * 2) = lo;
                }
            }
        }
        __syncthreads();
    }
    // store hB block back
    for (int i = tid; i < 2048; i += 256) {
        int row = i >> 5, c8 = i & 31;
        *(uint4*)(hBH + (size_t)(bm + row) * 256 + c8 * 8) = *(const uint4*)(smem + SM_HBH + row * 528 + c8 * 16);
        *(uint4*)(hBL + (size_t)(bm + row) * 256 + c8 * 8) = *(const uint4*)(smem + SM_HBL + row * 528 + c8 * 16);
    }
}

// ---------------- launch ----------------
extern "C" void kernel_launch(void* const* d_in, const int* in_sizes, int n_in,
                              void* d_out, int out_size) {
    const float* x     = (const float*)d_in[0];
    const float* z     = (const float*)d_in[1];
    const float* emb   = (const float*)d_in[2];
    const float* W_in1 = (const float*)d_in[3];
    const float* b_in1 = (const float*)d_in[4];
    const float* W_in2 = (const float*)d_in[5];
    const float* b_in2 = (const float*)d_in[6];
    const float* W_f1  = (const float*)d_in[7];
    const float* b_f1  = (const float*)d_in[8];
    const float* W_f2  = (const float*)d_in[9];
    const float* b_f2  = (const float*)d_in[10];
    const float* W_out = (const float*)d_in[11];
    const float* b_out = (const float*)d_in[12];
    float* out = (float*)d_out;

    cudaFuncSetAttribute(hgemm<0>, cudaFuncAttributeMaxDynamicSharedMemorySize, SMEMTOT);
    cudaFuncSetAttribute(hgemm<2>, cudaFuncAttributeMaxDynamicSharedMemorySize, SMEMTOT);
    cudaFuncSetAttribute(fractal_kernel, cudaFuncAttributeMaxDynamicSharedMemorySize, SMEM_FRAC);

    #define SYM(p, s) void* p; cudaGetSymbolAddress(&p, s)
    SYM(ftH, g_ftH); SYM(ftL, g_ftL);
    SYM(w1H, g_w1H); SYM(w1L, g_w1L);
    SYM(w2H, g_w2H); SYM(w2L, g_w2L);
    SYM(woH, g_woH); SYM(woL, g_woL);
    SYM(hAH, g_hAH); SYM(hAL, g_hAL);
    SYM(hBH, g_hBH); SYM(hBL, g_hBL);
    SYM(p1,  g_p1);  SYM(p2,  g_p2);
    #undef SYM
    typedef __nv_bfloat16 bf;

    feats_kernel<<<BROWS / 256, 256>>>(x, z, emb);
    dim3 wb(32, 8);
    wsplit_kernel<<<dim3(INPAD / 32, HID / 32),  wb>>>(W_in1, (bf*)w1H, (bf*)w1L, 121, INPAD, HID);
    wsplit_kernel<<<dim3(HID / 32,  HID / 32),   wb>>>(W_in2, (bf*)w2H, (bf*)w2L, HID, HID, HID);
    wsplit_kernel<<<dim3(HID / 32,  VOCAB / 32), wb>>>(W_out, (bf*)woH, (bf*)woL, HID, HID, VOCAB);
    pack_f1<<<(HID * HID2 + 255) / 256, 256>>>(W_f1);
    pack_f2<<<(HID2 * HID + 255) / 256, 256>>>(W_f2);

    // mlp_in
    hgemm<0><<<dim3(HID / 128, BROWS / 128), 256, SMEMTOT>>>(
        (bf*)ftH, (bf*)ftL, (bf*)w1H, (bf*)w1L, b_in1,
        (bf*)hAH, (bf*)hAL, nullptr, HID, INPAD);
    hgemm<0><<<dim3(HID / 128, BROWS / 128), 256, SMEMTOT>>>(
        (bf*)hAH, (bf*)hAL, (bf*)w2H, (bf*)w2L, b_in2,
        (bf*)hBH, (bf*)hBL, nullptr, HID, HID);

    // fractal refinement: ONE persistent launch for all 48 steps
    fractal_kernel<<<BROWS / FM, 256, SMEM_FRAC>>>(
        (bf*)hBH, (bf*)hBL, (const unsigned char*)p1, (const unsigned char*)p2, b_f1, b_f2);

    // output head
    hgemm<2><<<dim3(VOCAB / 128, BROWS / 128), 256, SMEMTOT>>>(
        (bf*)hBH, (bf*)hBL, (bf*)woH, (bf*)woL, b_out,
        nullptr, nullptr, out, VOCAB, HID);
}

// round 8
// speedup vs baseline: 2.6050x; 1.1742x over previous
#include <cuda_runtime.h>
#include <cuda_fp16.h>
#include <math.h>
#include <stdint.h>

#define BROWS 8192
#define HID   256
#define HID2  512
#define VOCAB 32000
#define INPAD 128
#define NSTEPS 48

// ---------------- device scratch (static, no allocation) ----------------
__device__ __align__(16) __half g_ftH[BROWS * INPAD];
__device__ __align__(16) __half g_ftL[BROWS * INPAD];
__device__ __align__(16) __half g_w1H[HID * INPAD],  g_w1L[HID * INPAD];
__device__ __align__(16) __half g_w2H[HID * HID],    g_w2L[HID * HID];
__device__ __align__(16) __half g_woH[(size_t)VOCAB * HID], g_woL[(size_t)VOCAB * HID];
__device__ __align__(16) __half g_hAH[BROWS * HID],  g_hAL[BROWS * HID];
__device__ __align__(16) __half g_hBH[BROWS * HID],  g_hBL[BROWS * HID];
// packed weight panels for the fractal loop (ldmatrix-ready, 80B pitch rows)
__device__ __align__(16) unsigned char g_p1[32 * 20480];
__device__ __align__(16) unsigned char g_p2[16 * 40960];

// ---------------- helpers ----------------
__device__ __forceinline__ uint32_t smem_u32(const void* p) {
    uint32_t a;
    asm("{ .reg .u64 t; cvta.to.shared.u64 t, %1; cvt.u32.u64 %0, t; }" : "=r"(a) : "l"(p));
    return a;
}
__device__ __forceinline__ void split2(float v, __half& h, __half& l) {
    h = __float2half(v);
    l = __float2half(v - __half2float(h));
}
__device__ __forceinline__ uint32_t packsplit(float v0, float v1, uint32_t& lo) {
    __half h0, l0, h1, l1;
    split2(v0, h0, l0); split2(v1, h1, l1);
    uint16_t uh0 = __half_as_ushort(h0), uh1 = __half_as_ushort(h1);
    uint16_t ul0 = __half_as_ushort(l0), ul1 = __half_as_ushort(l1);
    lo = (uint32_t)ul0 | ((uint32_t)ul1 << 16);
    return (uint32_t)uh0 | ((uint32_t)uh1 << 16);
}
__device__ __forceinline__ void cp16(uint32_t dst, const void* src) {
    asm volatile("cp.async.cg.shared.global [%0], [%1], 16;" :: "r"(dst), "l"(src));
}
__device__ __forceinline__ void ldsm4(uint32_t* r, uint32_t a) {
    asm volatile("ldmatrix.sync.aligned.m8n8.x4.shared.b16 {%0,%1,%2,%3}, [%4];"
                 : "=r"(r[0]), "=r"(r[1]), "=r"(r[2]), "=r"(r[3]) : "r"(a));
}
__device__ __forceinline__ void mma16816(float* d, const uint32_t* a, uint32_t b0, uint32_t b1) {
    asm volatile("mma.sync.aligned.m16n8k16.row.col.f32.f16.f16.f32 "
                 "{%0,%1,%2,%3}, {%4,%5,%6,%7}, {%8,%9}, {%0,%1,%2,%3};"
                 : "+f"(d[0]), "+f"(d[1]), "+f"(d[2]), "+f"(d[3])
                 : "r"(a[0]), "r"(a[1]), "r"(a[2]), "r"(a[3]), "r"(b0), "r"(b1));
}
__device__ __forceinline__ void bulkcp(uint32_t dst, const void* src, uint32_t bytes, uint32_t mbar) {
    asm volatile("cp.async.bulk.shared::cluster.global.mbarrier::complete_tx::bytes [%0], [%1], %2, [%3];"
                 :: "r"(dst), "l"(src), "r"(bytes), "r"(mbar) : "memory");
}
#define MBAR_INIT(a, c) \
    asm volatile("mbarrier.init.shared.b64 [%0], %1;" :: "r"(a), "r"((uint32_t)(c)) : "memory")
#define MBAR_EXPECT_TX(a, bytes) \
    asm volatile("mbarrier.arrive.expect_tx.shared.b64 _, [%0], %1;" :: "r"(a), "r"((uint32_t)(bytes)) : "memory")
#define MBAR_WAIT(a, p) do {                                                      \
    uint32_t _m = (a), _p = (uint32_t)(p), _d;                                    \
    asm volatile("{ .reg .pred q; mbarrier.try_wait.parity.acquire.cta.shared::cta.b64 q, [%1], %2; " \
                 "selp.b32 %0, 1, 0, q; }" : "=r"(_d) : "r"(_m), "r"(_p) : "memory"); \
    if (!_d) {                                                                    \
        asm volatile("{ .reg .pred Q; WL_%=: mbarrier.try_wait.parity.acquire.cta.shared::cta.b64 Q, [%0], %1, 0x989680; " \
                     "@Q bra.uni WD_%=; bra.uni WL_%=; WD_%=: }" :: "r"(_m), "r"(_p) : "memory"); \
    } } while (0)

// ---------------- feature assembly (fp16 hi/lo, padded to 128) ----------------
__global__ void feats_kernel(const float* __restrict__ x, const float* __restrict__ z,
                             const float* __restrict__ emb) {
    int b = blockIdx.x * blockDim.x + threadIdx.x;
    if (b >= BROWS) return;
    float xc = fminf(fmaxf(x[b], 0.0f), 1.0f);
    __half* fH = g_ftH + (size_t)b * INPAD;
    __half* fL = g_ftL + (size_t)b * INPAD;
    __half h, l;
    split2(xc, h, l); fH[0] = h; fL[0] = l;

    const float TWO_PI = 6.283185307179586f;
    float a = TWO_PI * xc;
    double fd = 1.0;
    #pragma unroll 1
    for (int j = 0; j < 32; j++) {
        float fr = (float)fd;
        float arg = a * fr;
        split2(sinf(arg), h, l); fH[1 + j] = h;  fL[1 + j] = l;
        split2(cosf(arg), h, l); fH[33 + j] = h; fL[33 + j] = l;
        fd *= 3.5;
    }
    float res = 16.0f;
    #pragma unroll 1
    for (int lv = 0; lv < 12; lv++) {
        float pos = xc * res;
        float i0f = floorf(pos);
        int   i0  = (int)i0f;
        float w   = pos - i0f;
        int h0 = i0 & 16383, h1 = (i0 + 1) & 16383;
        const float* t0 = emb + (size_t)h0 * 24 + lv * 2;
        const float* t1 = emb + (size_t)h1 * 24 + lv * 2;
        split2((1.0f - w) * t0[0] + w * t1[0], h, l); fH[65 + lv*2]   = h; fL[65 + lv*2]   = l;
        split2((1.0f - w) * t0[1] + w * t1[1], h, l); fH[65 + lv*2+1] = h; fL[65 + lv*2+1] = l;
        res *= 2.0f;
    }
    const float* zp = z + (size_t)b * 32;
    #pragma unroll
    for (int j = 0; j < 32; j++) { split2(zp[j], h, l); fH[89 + j] = h; fL[89 + j] = l; }
    #pragma unroll
    for (int j = 121; j < 128; j++) { fH[j] = __float2half(0.0f); fL[j] = __float2half(0.0f); }
}

// ---------------- weight transpose + split: W[Kreal][N] -> T{h,l}[N][Kpad] ----------------
__global__ void wsplit_kernel(const float* __restrict__ W, __half* __restrict__ Th,
                              __half* __restrict__ Tl, int Kreal, int Kpad, int N) {
    __shared__ float t[32][33];
    int kt = blockIdx.x * 32, nt = blockIdx.y * 32;
    int tx = threadIdx.x, ty = threadIdx.y;
    #pragma unroll
    for (int i = 0; i < 32; i += 8) {
        int k = kt + ty + i;
        t[ty + i][tx] = (k < Kreal) ? W[(size_t)k * N + nt + tx] : 0.0f;
    }
    __syncthreads();
    #pragma unroll
    for (int i = 0; i < 32; i += 8) {
        int n = nt + ty + i, k = kt + tx;
        __half h, l;
        split2(t[tx][ty + i], h, l);
        Th[(size_t)n * Kpad + k] = h;
        Tl[(size_t)n * Kpad + k] = l;
    }
}

// ---------------- pack W_f1 [256k][512n] into 32 bulk panels ----------------
__global__ void pack_f1(const float* __restrict__ W) {
    int i = blockIdx.x * 256 + threadIdx.x;
    if (i >= HID * HID2) return;
    int k = i / HID2, n = i % HID2;
    __half h, l; split2(W[i], h, l);
    int nt = n >> 7, nl = n & 127, kc = k >> 5, kl = k & 31;
    size_t base = (size_t)(nt * 8 + kc) * 20480;
    *(__half*)(g_p1 + base + nl * 80 + kl * 2) = h;
    *(__half*)(g_p1 + base + 10240 + nl * 80 + kl * 2) = l;
}
// ---------------- pack W_f2 [512k][256n] into 16 bulk panels ----------------
__global__ void pack_f2(const float* __restrict__ W) {
    int i = blockIdx.x * 256 + threadIdx.x;
    if (i >= HID2 * HID) return;
    int k = i / HID, n = i % HID;
    __half h, l; split2(W[i], h, l);
    int nt = k >> 7, kc = (k >> 5) & 3, kl = k & 31;
    size_t base = (size_t)(nt * 4 + kc) * 40960;
    *(__half*)(g_p2 + base + n * 80 + kl * 2) = h;
    *(__half*)(g_p2 + base + 20480 + n * 80 + kl * 2) = l;
}

// ---------------- 3-term fp16 GEMM (mlp_in) ----------------
#define TSTR   80
#define TBYTES (128 * TSTR)
#define BUFB   (4 * TBYTES)
#define SMEMTOT (2 * BUFB)

__global__ void __launch_bounds__(256) hgemm_g(
    const __half* __restrict__ Ah, const __half* __restrict__ Al,
    const __half* __restrict__ Bh, const __half* __restrict__ Bl,
    const float* __restrict__ bias,
    __half* __restrict__ Ch, __half* __restrict__ Cl, int N, int K)
{
    extern __shared__ char smem[];
    const uint32_t sb = smem_u32(smem);
    const int tid  = threadIdx.x;
    const int lane = tid & 31, wid = tid >> 5;
    const int wm = wid & 3, wn = wid >> 2;
    const int bm = blockIdx.y * 128, bn = blockIdx.x * 128;
    const int nchunks = K >> 5;

    float acc[2][8][4];
    #pragma unroll
    for (int a = 0; a < 2; a++)
        #pragma unroll
        for (int b = 0; b < 8; b++)
            #pragma unroll
            for (int c = 0; c < 4; c++) acc[a][b][c] = 0.0f;

    const __half* gsrc[4] = {Ah, Al, Bh, Bl};

    auto load_chunk = [&](int c, int buf) {
        const int k0 = c << 5;
        uint32_t base = sb + buf * BUFB;
        #pragma unroll
        for (int t4 = 0; t4 < 4; t4++) {
            const __half* g = gsrc[t4];
            int rb = (t4 < 2) ? bm : bn;
            #pragma unroll
            for (int i = 0; i < 2; i++) {
                int idx = tid + i * 256;
                int row = idx >> 2, c16 = idx & 3;
                cp16(base + t4 * TBYTES + row * TSTR + c16 * 16,
                     g + (size_t)(rb + row) * K + k0 + c16 * 8);
            }
        }
    };

    const int mat = lane >> 3, rin = lane & 7;
    const int lrow = (mat & 1) * 8 + rin;
    const int kof  = (mat >> 1) * 8;

    load_chunk(0, 0);
    asm volatile("cp.async.commit_group;" ::: "memory");

    for (int c = 0; c < nchunks; c++) {
        const int buf = c & 1;
        if (c + 1 < nchunks) load_chunk(c + 1, buf ^ 1);
        asm volatile("cp.async.commit_group;" ::: "memory");
        if (c + 1 < nchunks) asm volatile("cp.async.wait_group 1;" ::: "memory");
        else                 asm volatile("cp.async.wait_group 0;" ::: "memory");
        __syncthreads();

        const uint32_t sa = sb + buf * BUFB;
        #pragma unroll
        for (int k16 = 0; k16 < 32; k16 += 16) {
            uint32_t ahf[2][4], alf[2][4];
            #pragma unroll
            for (int mt = 0; mt < 2; mt++) {
                uint32_t ad = sa + (wm * 32 + mt * 16 + lrow) * TSTR + (k16 + kof) * 2;
                ldsm4(ahf[mt], ad);
                ldsm4(alf[mt], ad + TBYTES);
            }
            uint32_t bhf[4][4], blf[4][4];
            #pragma unroll
            for (int g = 0; g < 4; g++) {
                uint32_t bd = sa + 2 * TBYTES + (wn * 64 + g * 16 + lrow) * TSTR + (k16 + kof) * 2;
                ldsm4(bhf[g], bd);
                ldsm4(blf[g], bd + TBYTES);
            }
            #pragma unroll
            for (int nj = 0; nj < 8; nj++) {
                uint32_t b0 = bhf[nj >> 1][nj & 1], b1 = bhf[nj >> 1][2 + (nj & 1)];
                uint32_t c0 = blf[nj >> 1][nj & 1], c1 = blf[nj >> 1][2 + (nj & 1)];
                mma16816(acc[0][nj], ahf[0], b0, b1);
                mma16816(acc[1][nj], ahf[1], b0, b1);
                mma16816(acc[0][nj], ahf[0], c0, c1);
                mma16816(acc[1][nj], ahf[1], c0, c1);
                mma16816(acc[0][nj], alf[0], b0, b1);
                mma16816(acc[1][nj], alf[1], b0, b1);
            }
        }
        __syncthreads();
    }

    const float RS2 = 0.70710678118654752f;
    #pragma unroll
    for (int mt = 0; mt < 2; mt++) {
        #pragma unroll
        for (int nj = 0; nj < 8; nj++) {
            float* d = acc[mt][nj];
            int rg = bm + wm * 32 + mt * 16 + (lane >> 2);
            int cg = bn + wn * 64 + nj * 8 + (lane & 3) * 2;
            float bb0 = bias[cg], bb1 = bias[cg + 1];
            size_t off0 = (size_t)rg * N + cg;
            size_t off1 = (size_t)(rg + 8) * N + cg;
            float v[4] = {d[0] + bb0, d[1] + bb1, d[2] + bb0, d[3] + bb1};
            float o[4];
            #pragma unroll
            for (int j = 0; j < 4; j++)
                o[j] = 0.5f * v[j] * (1.0f + erff(v[j] * RS2));
            uint32_t lo0, lo1;
            uint32_t hi0 = packsplit(o[0], o[1], lo0);
            uint32_t hi1 = packsplit(o[2], o[3], lo1);
            *(uint32_t*)(Ch + off0) = hi0;  *(uint32_t*)(Cl + off0) = lo0;
            *(uint32_t*)(Ch + off1) = hi1;  *(uint32_t*)(Cl + off1) = lo1;
        }
    }
}

// ---------------- 2-term fp16 head GEMM: C = A_hi @ (Bh+Bl)^T + bias ----------------
#define HBUFB    (3 * TBYTES)
#define SMEMHEAD (2 * HBUFB)

__global__ void __launch_bounds__(256) hgemm_head(
    const __half* __restrict__ Ah,
    const __half* __restrict__ Bh, const __half* __restrict__ Bl,
    const float* __restrict__ bias, float* __restrict__ Cf, int N, int K)
{
    extern __shared__ char smem[];
    const uint32_t sb = smem_u32(smem);
    const int tid  = threadIdx.x;
    const int lane = tid & 31, wid = tid >> 5;
    const int wm = wid & 3, wn = wid >> 2;
    const int bm = blockIdx.y * 128, bn = blockIdx.x * 128;
    const int nchunks = K >> 5;

    float acc[2][8][4];
    #pragma unroll
    for (int a = 0; a < 2; a++)
        #pragma unroll
        for (int b = 0; b < 8; b++)
            #pragma unroll
            for (int c = 0; c < 4; c++) acc[a][b][c] = 0.0f;

    const __half* gsrc[3] = {Ah, Bh, Bl};

    auto load_chunk = [&](int c, int buf) {
        const int k0 = c << 5;
        uint32_t base = sb + buf * HBUFB;
        #pragma unroll
        for (int t3 = 0; t3 < 3; t3++) {
            const __half* g = gsrc[t3];
            int rb = (t3 == 0) ? bm : bn;
            #pragma unroll
            for (int i = 0; i < 2; i++) {
                int idx = tid + i * 256;
                int row = idx >> 2, c16 = idx & 3;
                cp16(base + t3 * TBYTES + row * TSTR + c16 * 16,
                     g + (size_t)(rb + row) * K + k0 + c16 * 8);
            }
        }
    };

    const int mat = lane >> 3, rin = lane & 7;
    const int lrow = (mat & 1) * 8 + rin;
    const int kof  = (mat >> 1) * 8;

    load_chunk(0, 0);
    asm volatile("cp.async.commit_group;" ::: "memory");

    for (int c = 0; c < nchunks; c++) {
        const int buf = c & 1;
        if (c + 1 < nchunks) load_chunk(c + 1, buf ^ 1);
        asm volatile("cp.async.commit_group;" ::: "memory");
        if (c + 1 < nchunks) asm volatile("cp.async.wait_group 1;" ::: "memory");
        else                 asm volatile("cp.async.wait_group 0;" ::: "memory");
        __syncthreads();

        const uint32_t sa = sb + buf * HBUFB;
        #pragma unroll
        for (int k16 = 0; k16 < 32; k16 += 16) {
            uint32_t ahf[2][4];
            #pragma unroll
            for (int mt = 0; mt < 2; mt++) {
                uint32_t ad = sa + (wm * 32 + mt * 16 + lrow) * TSTR + (k16 + kof) * 2;
                ldsm4(ahf[mt], ad);
            }
            uint32_t bhf[4][4], blf[4][4];
            #pragma unroll
            for (int g = 0; g < 4; g++) {
                uint32_t bd = sa + TBYTES + (wn * 64 + g * 16 + lrow) * TSTR + (k16 + kof) * 2;
                ldsm4(bhf[g], bd);
                ldsm4(blf[g], bd + TBYTES);
            }
            #pragma unroll
            for (int nj = 0; nj < 8; nj++) {
                uint32_t b0 = bhf[nj >> 1][nj & 1], b1 = bhf[nj >> 1][2 + (nj & 1)];
                uint32_t c0 = blf[nj >> 1][nj & 1], c1 = blf[nj >> 1][2 + (nj & 1)];
                mma16816(acc[0][nj], ahf[0], b0, b1);
                mma16816(acc[1][nj], ahf[1], b0, b1);
                mma16816(acc[0][nj], ahf[0], c0, c1);
                mma16816(acc[1][nj], ahf[1], c0, c1);
            }
        }
        __syncthreads();
    }

    #pragma unroll
    for (int mt = 0; mt < 2; mt++) {
        #pragma unroll
        for (int nj = 0; nj < 8; nj++) {
            float* d = acc[mt][nj];
            int rg = bm + wm * 32 + mt * 16 + (lane >> 2);
            int cg = bn + wn * 64 + nj * 8 + (lane & 3) * 2;
            float bb0 = bias[cg], bb1 = bias[cg + 1];
            *(float2*)(Cf + (size_t)rg * N + cg)       = make_float2(d[0] + bb0, d[1] + bb1);
            *(float2*)(Cf + (size_t)(rg + 8) * N + cg) = make_float2(d[2] + bb0, d[3] + bb1);
        }
    }
}

// ---------------- persistent fractal loop kernel ----------------
#define FM       64
#define SM_HBH   0
#define SM_HBL   33792
#define SM_UH    67584
#define SM_UL    84992
#define SM_WS0   102400
#define SM_WS1   143360
#define SM_MB    184320
#define SMEM_FRAC 184336
#define NCHUNK_TOT (NSTEPS * 48)

__global__ void __launch_bounds__(256) fractal_kernel(
    __half* __restrict__ hBH, __half* __restrict__ hBL,
    const unsigned char* __restrict__ p1, const unsigned char* __restrict__ p2,
    const float* __restrict__ b_f1, const float* __restrict__ b_f2)
{
    extern __shared__ char smem[];
    const uint32_t sb = smem_u32(smem);
    const int tid = threadIdx.x, lane = tid & 31, wid = tid >> 5;
    const int wm = wid & 3, wn = wid >> 2;
    const int bm = blockIdx.x * FM;
    const int mat = lane >> 3, rin = lane & 7;
    const int lrow = (mat & 1) * 8 + rin;
    const int kof  = (mat >> 1) * 8;
    const float RS2 = 0.70710678118654752f;

    if (tid == 0) { MBAR_INIT(sb + SM_MB, 1); MBAR_INIT(sb + SM_MB + 8, 1); }
    for (int i = tid; i < 2048; i += 256) {
        int row = i >> 5, c8 = i & 31;
        *(uint4*)(smem + SM_HBH + row * 528 + c8 * 16) = *(const uint4*)(hBH + (size_t)(bm + row) * 256 + c8 * 8);
        *(uint4*)(smem + SM_HBL + row * 528 + c8 * 16) = *(const uint4*)(hBL + (size_t)(bm + row) * 256 + c8 * 8);
    }
    __syncthreads();

    auto issue = [&](int j) {
        int jj = j % 48;
        int nt = jj / 12, pi = jj % 12;
        const unsigned char* src; uint32_t bytes;
        if (pi < 8) { src = p1 + (size_t)(nt * 8 + pi) * 20480;       bytes = 20480; }
        else        { src = p2 + (size_t)(nt * 4 + (pi - 8)) * 40960; bytes = 40960; }
        uint32_t mb = sb + SM_MB + (j & 1) * 8;
        MBAR_EXPECT_TX(mb, bytes);
        bulkcp(sb + ((j & 1) ? SM_WS1 : SM_WS0), src, bytes, mb);
    };
    if (tid == 0) { issue(0); issue(1); }
    int cidx = 2, cc = 0, ph0 = 0, ph1 = 0;

    #pragma unroll 1
    for (int step = 0; step < NSTEPS; step++) {
        float acc2[16][4];
        #pragma unroll
        for (int a = 0; a < 16; a++)
            #pragma unroll
            for (int b = 0; b < 4; b++) acc2[a][b] = 0.0f;

        #pragma unroll 1
        for (int nt = 0; nt < 4; nt++) {
            float acc1[8][4];
            #pragma unroll
            for (int a = 0; a < 8; a++)
                #pragma unroll
                for (int b = 0; b < 4; b++) acc1[a][b] = 0.0f;

            #pragma unroll 1
            for (int kc = 0; kc < 8; kc++) {
                if ((cc & 1) == 0) { MBAR_WAIT(sb + SM_MB,     ph0); ph0 ^= 1; }
                else               { MBAR_WAIT(sb + SM_MB + 8, ph1); ph1 ^= 1; }
                const uint32_t ws = sb + ((cc & 1) ? SM_WS1 : SM_WS0);
                #pragma unroll
                for (int k16 = 0; k16 < 32; k16 += 16) {
                    int kg = kc * 32 + k16;
                    uint32_t ahf[4], alf[4];
                    uint32_t ad = sb + SM_HBH + (wm * 16 + lrow) * 528 + (kg + kof) * 2;
                    ldsm4(ahf, ad); ldsm4(alf, ad + (SM_HBL - SM_HBH));
                    uint32_t bh[4][4], bl[4][4];
                    #pragma unroll
                    for (int g = 0; g < 4; g++) {
                        uint32_t bd = ws + (wn * 64 + g * 16 + lrow) * 80 + (k16 + kof) * 2;
                        ldsm4(bh[g], bd); ldsm4(bl[g], bd + 10240);
                    }
                    #pragma unroll
                    for (int nj = 0; nj < 8; nj++) {
                        uint32_t b0 = bh[nj >> 1][nj & 1], b1 = bh[nj >> 1][2 + (nj & 1)];
                        uint32_t c0 = bl[nj >> 1][nj & 1], c1 = bl[nj >> 1][2 + (nj & 1)];
                        mma16816(acc1[nj], ahf, b0, b1);
                        mma16816(acc1[nj], ahf, c0, c1);
                        mma16816(acc1[nj], alf, b0, b1);
                    }
                }
                __syncthreads();
                if (tid == 0 && cidx < NCHUNK_TOT) issue(cidx);
                cidx++; cc++;
            }
            {
                int r0 = wm * 16 + (lane >> 2);
                #pragma unroll
                for (int nj = 0; nj < 8; nj++) {
                    int c = wn * 64 + nj * 8 + (lane & 3) * 2;
                    float bb0 = b_f1[nt * 128 + c], bb1 = b_f1[nt * 128 + c + 1];
                    float v[4] = {acc1[nj][0] + bb0, acc1[nj][1] + bb1,
                                  acc1[nj][2] + bb0, acc1[nj][3] + bb1};
                    float o[4];
                    #pragma unroll
                    for (int j = 0; j < 4; j++) o[j] = 0.5f * v[j] * (1.0f + erff(v[j] * RS2));
                    uint32_t lo0, lo1;
                    uint32_t hi0 = packsplit(o[0], o[1], lo0);
                    uint32_t hi1 = packsplit(o[2], o[3], lo1);
                    *(uint32_t*)(smem + SM_UH + (size_t)r0 * 272 + c * 2)       = hi0;
                    *(uint32_t*)(smem + SM_UL + (size_t)r0 * 272 + c * 2)       = lo0;
                    *(uint32_t*)(smem + SM_UH + (size_t)(r0 + 8) * 272 + c * 2) = hi1;
                    *(uint32_t*)(smem + SM_UL + (size_t)(r0 + 8) * 272 + c * 2) = lo1;
                }
            }
            __syncthreads();
            #pragma unroll 1
            for (int kc2 = 0; kc2 < 4; kc2++) {
                if ((cc & 1) == 0) { MBAR_WAIT(sb + SM_MB,     ph0); ph0 ^= 1; }
                else               { MBAR_WAIT(sb + SM_MB + 8, ph1); ph1 ^= 1; }
                const uint32_t ws = sb + ((cc & 1) ? SM_WS1 : SM_WS0);
                #pragma unroll
                for (int k16 = 0; k16 < 32; k16 += 16) {
                    int kl = kc2 * 32 + k16;
                    uint32_t ahf[4], alf[4];
                    uint32_t ad = sb + SM_UH + (wm * 16 + lrow) * 272 + (kl + kof) * 2;
                    ldsm4(ahf, ad); ldsm4(alf, ad + (SM_UL - SM_UH));
                    #pragma unroll
                    for (int g = 0; g < 8; g++) {
                        uint32_t bd = ws + (wn * 128 + g * 16 + lrow) * 80 + (k16 + kof) * 2;
                        uint32_t bh[4], bl2[4];
                        ldsm4(bh, bd); ldsm4(bl2, bd + 20480);
                        #pragma unroll
                        for (int s = 0; s < 2; s++) {
                            int nj = g * 2 + s;
                            mma16816(acc2[nj], ahf, bh[s],  bh[2 + s]);
                            mma16816(acc2[nj], ahf, bl2[s], bl2[2 + s]);
                            mma16816(acc2[nj], alf, bh[s],  bh[2 + s]);
                        }
                    }
                }
                __syncthreads();
                if (tid == 0 && cidx < NCHUNK_TOT) issue(cidx);
                cidx++; cc++;
            }
        }
        {
            int r0 = wm * 16 + (lane >> 2);
            #pragma unroll
            for (int nj = 0; nj < 16; nj++) {
                int c = wn * 128 + nj * 8 + (lane & 3) * 2;
                float bb0 = b_f2[c], bb1 = b_f2[c + 1];
                #pragma unroll
                for (int p = 0; p < 2; p++) {
                    int r = r0 + p * 8;
                    float v0 = acc2[nj][p * 2]     + bb0;
                    float v1 = acc2[nj][p * 2 + 1] + bb1;
                    uint32_t ohr = *(uint32_t*)(smem + SM_HBH + (size_t)r * 528 + c * 2);
                    uint32_t olr = *(uint32_t*)(smem + SM_HBL + (size_t)r * 528 + c * 2);
                    __half2 oh2 = *(__half2*)&ohr;
                    __half2 ol2 = *(__half2*)&olr;
                    float2 fh = __half22float2(oh2);
                    float2 fl = __half22float2(ol2);
                    float n0 = 0.5f * (fh.x + fl.x) + 0.5f * tanhf(v0);
                    float n1 = 0.5f * (fh.y + fl.y) + 0.5f * tanhf(v1);
                    uint32_t lo; uint32_t hi = packsplit(n0, n1, lo);
                    *(uint32_t*)(smem + SM_HBH + (size_t)r * 528 + c * 2) = hi;
                    *(uint32_t*)(smem + SM_HBL + (size_t)r * 528 + c * 2) = lo;
                }
            }
        }
        __syncthreads();
    }
    for (int i = tid; i < 2048; i += 256) {
        int row = i >> 5, c8 = i & 31;
        *(uint4*)(hBH + (size_t)(bm + row) * 256 + c8 * 8) = *(const uint4*)(smem + SM_HBH + row * 528 + c8 * 16);
        *(uint4*)(hBL + (size_t)(bm + row) * 256 + c8 * 8) = *(const uint4*)(smem + SM_HBL + row * 528 + c8 * 16);
    }
}

// ---------------- launch ----------------
extern "C" void kernel_launch(void* const* d_in, const int* in_sizes, int n_in,
                              void* d_out, int out_size) {
    const float* x     = (const float*)d_in[0];
    const float* z     = (const float*)d_in[1];
    const float* emb   = (const float*)d_in[2];
    const float* W_in1 = (const float*)d_in[3];
    const float* b_in1 = (const float*)d_in[4];
    const float* W_in2 = (const float*)d_in[5];
    const float* b_in2 = (const float*)d_in[6];
    const float* W_f1  = (const float*)d_in[7];
    const float* b_f1  = (const float*)d_in[8];
    const float* W_f2  = (const float*)d_in[9];
    const float* b_f2  = (const float*)d_in[10];
    const float* W_out = (const float*)d_in[11];
    const float* b_out = (const float*)d_in[12];
    float* out = (float*)d_out;

    cudaFuncSetAttribute(hgemm_g,    cudaFuncAttributeMaxDynamicSharedMemorySize, SMEMTOT);
    cudaFuncSetAttribute(hgemm_head, cudaFuncAttributeMaxDynamicSharedMemorySize, SMEMHEAD);
    cudaFuncSetAttribute(fractal_kernel, cudaFuncAttributeMaxDynamicSharedMemorySize, SMEM_FRAC);

    #define SYM(p, s) void* p; cudaGetSymbolAddress(&p, s)
    SYM(ftH, g_ftH); SYM(ftL, g_ftL);
    SYM(w1H, g_w1H); SYM(w1L, g_w1L);
    SYM(w2H, g_w2H); SYM(w2L, g_w2L);
    SYM(woH, g_woH); SYM(woL, g_woL);
    SYM(hAH, g_hAH); SYM(hAL, g_hAL);
    SYM(hBH, g_hBH); SYM(hBL, g_hBL);
    SYM(p1,  g_p1);  SYM(p2,  g_p2);
    #undef SYM
    typedef __half hf;

    feats_kernel<<<BROWS / 256, 256>>>(x, z, emb);
    dim3 wb(32, 8);
    wsplit_kernel<<<dim3(INPAD / 32, HID / 32),  wb>>>(W_in1, (hf*)w1H, (hf*)w1L, 121, INPAD, HID);
    wsplit_kernel<<<dim3(HID / 32,  HID / 32),   wb>>>(W_in2, (hf*)w2H, (hf*)w2L, HID, HID, HID);
    wsplit_kernel<<<dim3(HID / 32,  VOCAB / 32), wb>>>(W_out, (hf*)woH, (hf*)woL, HID, HID, VOCAB);
    pack_f1<<<(HID * HID2 + 255) / 256, 256>>>(W_f1);
    pack_f2<<<(HID2 * HID + 255) / 256, 256>>>(W_f2);

    // mlp_in (3-term)
    hgemm_g<<<dim3(HID / 128, BROWS / 128), 256, SMEMTOT>>>(
        (hf*)ftH, (hf*)ftL, (hf*)w1H, (hf*)w1L, b_in1,
        (hf*)hAH, (hf*)hAL, HID, INPAD);
    hgemm_g<<<dim3(HID / 128, BROWS / 128), 256, SMEMTOT>>>(
        (hf*)hAH, (hf*)hAL, (hf*)w2H, (hf*)w2L, b_in2,
        (hf*)hBH, (hf*)hBL, HID, HID);

    // fractal refinement: ONE persistent launch for all 48 steps (3-term)
    fractal_kernel<<<BROWS / FM, 256, SMEM_FRAC>>>(
        (hf*)hBH, (hf*)hBL, (const unsigned char*)p1, (const unsigned char*)p2, b_f1, b_f2);

    // output head (2-term: A_hi x (Wh + Wl))
    hgemm_head<<<dim3(VOCAB / 128, BROWS / 128), 256, SMEMHEAD>>>(
        (hf*)hBH, (hf*)woH, (hf*)woL, b_out, out, VOCAB, HID);
}

// round 9
// speedup vs baseline: 2.8707x; 1.1020x over previous
#include <cuda_runtime.h>
#include <cuda_fp16.h>
#include <math.h>
#include <stdint.h>

#define BROWS 8192
#define HID   256
#define HID2  512
#define VOCAB 32000
#define INPAD 128
#define NSTEPS 48

// ---------------- device scratch (static, no allocation) ----------------
__device__ __align__(16) __half g_ftH[BROWS * INPAD];
__device__ __align__(16) __half g_ftL[BROWS * INPAD];
__device__ __align__(16) __half g_w1H[HID * INPAD],  g_w1L[HID * INPAD];
__device__ __align__(16) __half g_w2H[HID * HID],    g_w2L[HID * HID];
__device__ __align__(16) __half g_woH[(size_t)VOCAB * HID];
__device__ __align__(16) __half g_hAH[BROWS * HID],  g_hAL[BROWS * HID];
__device__ __align__(16) __half g_hBH[BROWS * HID],  g_hBL[BROWS * HID];
// packed weight panels for the fractal loop (ldmatrix-ready, 80B pitch rows)
__device__ __align__(16) unsigned char g_p1[32 * 20480];
__device__ __align__(16) unsigned char g_p2[16 * 40960];

// ---------------- helpers ----------------
__device__ __forceinline__ uint32_t smem_u32(const void* p) {
    uint32_t a;
    asm("{ .reg .u64 t; cvta.to.shared.u64 t, %1; cvt.u32.u64 %0, t; }" : "=r"(a) : "l"(p));
    return a;
}
__device__ __forceinline__ void split2(float v, __half& h, __half& l) {
    h = __float2half(v);
    l = __float2half(v - __half2float(h));
}
__device__ __forceinline__ uint32_t packsplit(float v0, float v1, uint32_t& lo) {
    __half h0, l0, h1, l1;
    split2(v0, h0, l0); split2(v1, h1, l1);
    uint16_t uh0 = __half_as_ushort(h0), uh1 = __half_as_ushort(h1);
    uint16_t ul0 = __half_as_ushort(l0), ul1 = __half_as_ushort(l1);
    lo = (uint32_t)ul0 | ((uint32_t)ul1 << 16);
    return (uint32_t)uh0 | ((uint32_t)uh1 << 16);
}
__device__ __forceinline__ void cp16(uint32_t dst, const void* src) {
    asm volatile("cp.async.cg.shared.global [%0], [%1], 16;" :: "r"(dst), "l"(src));
}
__device__ __forceinline__ void ldsm4(uint32_t* r, uint32_t a) {
    asm volatile("ldmatrix.sync.aligned.m8n8.x4.shared.b16 {%0,%1,%2,%3}, [%4];"
                 : "=r"(r[0]), "=r"(r[1]), "=r"(r[2]), "=r"(r[3]) : "r"(a));
}
__device__ __forceinline__ void mma16816(float* d, const uint32_t* a, uint32_t b0, uint32_t b1) {
    asm volatile("mma.sync.aligned.m16n8k16.row.col.f32.f16.f16.f32 "
                 "{%0,%1,%2,%3}, {%4,%5,%6,%7}, {%8,%9}, {%0,%1,%2,%3};"
                 : "+f"(d[0]), "+f"(d[1]), "+f"(d[2]), "+f"(d[3])
                 : "r"(a[0]), "r"(a[1]), "r"(a[2]), "r"(a[3]), "r"(b0), "r"(b1));
}
__device__ __forceinline__ void bulkcp(uint32_t dst, const void* src, uint32_t bytes, uint32_t mbar) {
    asm volatile("cp.async.bulk.shared::cluster.global.mbarrier::complete_tx::bytes [%0], [%1], %2, [%3];"
                 :: "r"(dst), "l"(src), "r"(bytes), "r"(mbar) : "memory");
}
#define MBAR_INIT(a, c) \
    asm volatile("mbarrier.init.shared.b64 [%0], %1;" :: "r"(a), "r"((uint32_t)(c)) : "memory")
#define MBAR_EXPECT_TX(a, bytes) \
    asm volatile("mbarrier.arrive.expect_tx.shared.b64 _, [%0], %1;" :: "r"(a), "r"((uint32_t)(bytes)) : "memory")
#define MBAR_WAIT(a, p) do {                                                      \
    uint32_t _m = (a), _p = (uint32_t)(p), _d;                                    \
    asm volatile("{ .reg .pred q; mbarrier.try_wait.parity.acquire.cta.shared::cta.b64 q, [%1], %2; " \
                 "selp.b32 %0, 1, 0, q; }" : "=r"(_d) : "r"(_m), "r"(_p) : "memory"); \
    if (!_d) {                                                                    \
        asm volatile("{ .reg .pred Q; WL_%=: mbarrier.try_wait.parity.acquire.cta.shared::cta.b64 Q, [%0], %1, 0x989680; " \
                     "@Q bra.uni WD_%=; bra.uni WL_%=; WD_%=: }" :: "r"(_m), "r"(_p) : "memory"); \
    } } while (0)

// ---------------- feature assembly (fp16 hi/lo, padded to 128) ----------------
__global__ void feats_kernel(const float* __restrict__ x, const float* __restrict__ z,
                             const float* __restrict__ emb) {
    int b = blockIdx.x * blockDim.x + threadIdx.x;
    if (b >= BROWS) return;
    float xc = fminf(fmaxf(x[b], 0.0f), 1.0f);
    __half* fH = g_ftH + (size_t)b * INPAD;
    __half* fL = g_ftL + (size_t)b * INPAD;
    __half h, l;
    split2(xc, h, l); fH[0] = h; fL[0] = l;

    const float TWO_PI = 6.283185307179586f;
    float a = TWO_PI * xc;
    double fd = 1.0;
    #pragma unroll 1
    for (int j = 0; j < 32; j++) {
        float fr = (float)fd;
        float arg = a * fr;
        split2(sinf(arg), h, l); fH[1 + j] = h;  fL[1 + j] = l;
        split2(cosf(arg), h, l); fH[33 + j] = h; fL[33 + j] = l;
        fd *= 3.5;
    }
    float res = 16.0f;
    #pragma unroll 1
    for (int lv = 0; lv < 12; lv++) {
        float pos = xc * res;
        float i0f = floorf(pos);
        int   i0  = (int)i0f;
        float w   = pos - i0f;
        int h0 = i0 & 16383, h1 = (i0 + 1) & 16383;
        const float* t0 = emb + (size_t)h0 * 24 + lv * 2;
        const float* t1 = emb + (size_t)h1 * 24 + lv * 2;
        split2((1.0f - w) * t0[0] + w * t1[0], h, l); fH[65 + lv*2]   = h; fL[65 + lv*2]   = l;
        split2((1.0f - w) * t0[1] + w * t1[1], h, l); fH[65 + lv*2+1] = h; fL[65 + lv*2+1] = l;
        res *= 2.0f;
    }
    const float* zp = z + (size_t)b * 32;
    #pragma unroll
    for (int j = 0; j < 32; j++) { split2(zp[j], h, l); fH[89 + j] = h; fL[89 + j] = l; }
    #pragma unroll
    for (int j = 121; j < 128; j++) { fH[j] = __float2half(0.0f); fL[j] = __float2half(0.0f); }
}

// ---------------- weight transpose + split: W[Kreal][N] -> T{h,l}[N][Kpad] ----------------
__global__ void wsplit_kernel(const float* __restrict__ W, __half* __restrict__ Th,
                              __half* __restrict__ Tl, int Kreal, int Kpad, int N) {
    __shared__ float t[32][33];
    int kt = blockIdx.x * 32, nt = blockIdx.y * 32;
    int tx = threadIdx.x, ty = threadIdx.y;
    #pragma unroll
    for (int i = 0; i < 32; i += 8) {
        int k = kt + ty + i;
        t[ty + i][tx] = (k < Kreal) ? W[(size_t)k * N + nt + tx] : 0.0f;
    }
    __syncthreads();
    #pragma unroll
    for (int i = 0; i < 32; i += 8) {
        int n = nt + ty + i, k = kt + tx;
        __half h, l;
        split2(t[tx][ty + i], h, l);
        Th[(size_t)n * Kpad + k] = h;
        if (Tl) Tl[(size_t)n * Kpad + k] = l;
    }
}

// ---------------- pack W_f1 [256k][512n] into 32 bulk panels ----------------
__global__ void pack_f1(const float* __restrict__ W) {
    int i = blockIdx.x * 256 + threadIdx.x;
    if (i >= HID * HID2) return;
    int k = i / HID2, n = i % HID2;
    __half h, l; split2(W[i], h, l);
    int nt = n >> 7, nl = n & 127, kc = k >> 5, kl = k & 31;
    size_t base = (size_t)(nt * 8 + kc) * 20480;
    *(__half*)(g_p1 + base + nl * 80 + kl * 2) = h;
    *(__half*)(g_p1 + base + 10240 + nl * 80 + kl * 2) = l;
}
// ---------------- pack W_f2 [512k][256n] into 16 bulk panels ----------------
__global__ void pack_f2(const float* __restrict__ W) {
    int i = blockIdx.x * 256 + threadIdx.x;
    if (i >= HID2 * HID) return;
    int k = i / HID, n = i % HID;
    __half h, l; split2(W[i], h, l);
    int nt = k >> 7, kc = (k >> 5) & 3, kl = k & 31;
    size_t base = (size_t)(nt * 4 + kc) * 40960;
    *(__half*)(g_p2 + base + n * 80 + kl * 2) = h;
    *(__half*)(g_p2 + base + 20480 + n * 80 + kl * 2) = l;
}

// ---------------- 3-term fp16 GEMM (mlp_in) ----------------
#define TSTR   80
#define TBYTES (128 * TSTR)
#define BUFB   (4 * TBYTES)
#define SMEMTOT (2 * BUFB)

__global__ void __launch_bounds__(256) hgemm_g(
    const __half* __restrict__ Ah, const __half* __restrict__ Al,
    const __half* __restrict__ Bh, const __half* __restrict__ Bl,
    const float* __restrict__ bias,
    __half* __restrict__ Ch, __half* __restrict__ Cl, int N, int K)
{
    extern __shared__ char smem[];
    const uint32_t sb = smem_u32(smem);
    const int tid  = threadIdx.x;
    const int lane = tid & 31, wid = tid >> 5;
    const int wm = wid & 3, wn = wid >> 2;
    const int bm = blockIdx.y * 128, bn = blockIdx.x * 128;
    const int nchunks = K >> 5;

    float acc[2][8][4];
    #pragma unroll
    for (int a = 0; a < 2; a++)
        #pragma unroll
        for (int b = 0; b < 8; b++)
            #pragma unroll
            for (int c = 0; c < 4; c++) acc[a][b][c] = 0.0f;

    const __half* gsrc[4] = {Ah, Al, Bh, Bl};

    auto load_chunk = [&](int c, int buf) {
        const int k0 = c << 5;
        uint32_t base = sb + buf * BUFB;
        #pragma unroll
        for (int t4 = 0; t4 < 4; t4++) {
            const __half* g = gsrc[t4];
            int rb = (t4 < 2) ? bm : bn;
            #pragma unroll
            for (int i = 0; i < 2; i++) {
                int idx = tid + i * 256;
                int row = idx >> 2, c16 = idx & 3;
                cp16(base + t4 * TBYTES + row * TSTR + c16 * 16,
                     g + (size_t)(rb + row) * K + k0 + c16 * 8);
            }
        }
    };

    const int mat = lane >> 3, rin = lane & 7;
    const int lrow = (mat & 1) * 8 + rin;
    const int kof  = (mat >> 1) * 8;

    load_chunk(0, 0);
    asm volatile("cp.async.commit_group;" ::: "memory");

    for (int c = 0; c < nchunks; c++) {
        const int buf = c & 1;
        if (c + 1 < nchunks) load_chunk(c + 1, buf ^ 1);
        asm volatile("cp.async.commit_group;" ::: "memory");
        if (c + 1 < nchunks) asm volatile("cp.async.wait_group 1;" ::: "memory");
        else                 asm volatile("cp.async.wait_group 0;" ::: "memory");
        __syncthreads();

        const uint32_t sa = sb + buf * BUFB;
        #pragma unroll
        for (int k16 = 0; k16 < 32; k16 += 16) {
            uint32_t ahf[2][4], alf[2][4];
            #pragma unroll
            for (int mt = 0; mt < 2; mt++) {
                uint32_t ad = sa + (wm * 32 + mt * 16 + lrow) * TSTR + (k16 + kof) * 2;
                ldsm4(ahf[mt], ad);
                ldsm4(alf[mt], ad + TBYTES);
            }
            uint32_t bhf[4][4], blf[4][4];
            #pragma unroll
            for (int g = 0; g < 4; g++) {
                uint32_t bd = sa + 2 * TBYTES + (wn * 64 + g * 16 + lrow) * TSTR + (k16 + kof) * 2;
                ldsm4(bhf[g], bd);
                ldsm4(blf[g], bd + TBYTES);
            }
            #pragma unroll
            for (int nj = 0; nj < 8; nj++) {
                uint32_t b0 = bhf[nj >> 1][nj & 1], b1 = bhf[nj >> 1][2 + (nj & 1)];
                uint32_t c0 = blf[nj >> 1][nj & 1], c1 = blf[nj >> 1][2 + (nj & 1)];
                mma16816(acc[0][nj], ahf[0], b0, b1);
                mma16816(acc[1][nj], ahf[1], b0, b1);
                mma16816(acc[0][nj], ahf[0], c0, c1);
                mma16816(acc[1][nj], ahf[1], c0, c1);
                mma16816(acc[0][nj], alf[0], b0, b1);
                mma16816(acc[1][nj], alf[1], b0, b1);
            }
        }
        __syncthreads();
    }

    const float RS2 = 0.70710678118654752f;
    #pragma unroll
    for (int mt = 0; mt < 2; mt++) {
        #pragma unroll
        for (int nj = 0; nj < 8; nj++) {
            float* d = acc[mt][nj];
            int rg = bm + wm * 32 + mt * 16 + (lane >> 2);
            int cg = bn + wn * 64 + nj * 8 + (lane & 3) * 2;
            float bb0 = bias[cg], bb1 = bias[cg + 1];
            size_t off0 = (size_t)rg * N + cg;
            size_t off1 = (size_t)(rg + 8) * N + cg;
            float v[4] = {d[0] + bb0, d[1] + bb1, d[2] + bb0, d[3] + bb1};
            float o[4];
            #pragma unroll
            for (int j = 0; j < 4; j++)
                o[j] = 0.5f * v[j] * (1.0f + erff(v[j] * RS2));
            uint32_t lo0, lo1;
            uint32_t hi0 = packsplit(o[0], o[1], lo0);
            uint32_t hi1 = packsplit(o[2], o[3], lo1);
            *(uint32_t*)(Ch + off0) = hi0;  *(uint32_t*)(Cl + off0) = lo0;
            *(uint32_t*)(Ch + off1) = hi1;  *(uint32_t*)(Cl + off1) = lo1;
        }
    }
}

// ---------------- 1-term fp16 head GEMM: C = A_hi @ B_hi^T + bias ----------------
#define HBUFB    (2 * TBYTES)
#define SMEMHEAD (2 * HBUFB)

__global__ void __launch_bounds__(256) hgemm_head(
    const __half* __restrict__ Ah, const __half* __restrict__ Bh,
    const float* __restrict__ bias, float* __restrict__ Cf, int N, int K)
{
    extern __shared__ char smem[];
    const uint32_t sb = smem_u32(smem);
    const int tid  = threadIdx.x;
    const int lane = tid & 31, wid = tid >> 5;
    const int wm = wid & 3, wn = wid >> 2;
    const int bm = blockIdx.y * 128, bn = blockIdx.x * 128;
    const int nchunks = K >> 5;

    float acc[2][8][4];
    #pragma unroll
    for (int a = 0; a < 2; a++)
        #pragma unroll
        for (int b = 0; b < 8; b++)
            #pragma unroll
            for (int c = 0; c < 4; c++) acc[a][b][c] = 0.0f;

    const __half* gsrc[2] = {Ah, Bh};

    auto load_chunk = [&](int c, int buf) {
        const int k0 = c << 5;
        uint32_t base = sb + buf * HBUFB;
        #pragma unroll
        for (int t2 = 0; t2 < 2; t2++) {
            const __half* g = gsrc[t2];
            int rb = (t2 == 0) ? bm : bn;
            #pragma unroll
            for (int i = 0; i < 2; i++) {
                int idx = tid + i * 256;
                int row = idx >> 2, c16 = idx & 3;
                cp16(base + t2 * TBYTES + row * TSTR + c16 * 16,
                     g + (size_t)(rb + row) * K + k0 + c16 * 8);
            }
        }
    };

    const int mat = lane >> 3, rin = lane & 7;
    const int lrow = (mat & 1) * 8 + rin;
    const int kof  = (mat >> 1) * 8;

    load_chunk(0, 0);
    asm volatile("cp.async.commit_group;" ::: "memory");

    for (int c = 0; c < nchunks; c++) {
        const int buf = c & 1;
        if (c + 1 < nchunks) load_chunk(c + 1, buf ^ 1);
        asm volatile("cp.async.commit_group;" ::: "memory");
        if (c + 1 < nchunks) asm volatile("cp.async.wait_group 1;" ::: "memory");
        else                 asm volatile("cp.async.wait_group 0;" ::: "memory");
        __syncthreads();

        const uint32_t sa = sb + buf * HBUFB;
        #pragma unroll
        for (int k16 = 0; k16 < 32; k16 += 16) {
            uint32_t ahf[2][4];
            #pragma unroll
            for (int mt = 0; mt < 2; mt++) {
                uint32_t ad = sa + (wm * 32 + mt * 16 + lrow) * TSTR + (k16 + kof) * 2;
                ldsm4(ahf[mt], ad);
            }
            uint32_t bhf[4][4];
            #pragma unroll
            for (int g = 0; g < 4; g++) {
                uint32_t bd = sa + TBYTES + (wn * 64 + g * 16 + lrow) * TSTR + (k16 + kof) * 2;
                ldsm4(bhf[g], bd);
            }
            #pragma unroll
            for (int nj = 0; nj < 8; nj++) {
                uint32_t b0 = bhf[nj >> 1][nj & 1], b1 = bhf[nj >> 1][2 + (nj & 1)];
                mma16816(acc[0][nj], ahf[0], b0, b1);
                mma16816(acc[1][nj], ahf[1], b0, b1);
            }
        }
        __syncthreads();
    }

    #pragma unroll
    for (int mt = 0; mt < 2; mt++) {
        #pragma unroll
        for (int nj = 0; nj < 8; nj++) {
            float* d = acc[mt][nj];
            int rg = bm + wm * 32 + mt * 16 + (lane >> 2);
            int cg = bn + wn * 64 + nj * 8 + (lane & 3) * 2;
            float bb0 = bias[cg], bb1 = bias[cg + 1];
            *(float2*)(Cf + (size_t)rg * N + cg)       = make_float2(d[0] + bb0, d[1] + bb1);
            *(float2*)(Cf + (size_t)(rg + 8) * N + cg) = make_float2(d[2] + bb0, d[3] + bb1);
        }
    }
}

// ---------------- persistent fractal loop kernel ----------------
#define FM       64
#define SM_HBH   0
#define SM_HBL   33792
#define SM_UH    67584
#define SM_UL    84992
#define SM_WS0   102400
#define SM_WS1   143360
#define SM_MB    184320
#define SMEM_FRAC 184336
#define NCHUNK_TOT (NSTEPS * 48)

__global__ void __launch_bounds__(256) fractal_kernel(
    __half* __restrict__ hBH, __half* __restrict__ hBL,
    const unsigned char* __restrict__ p1, const unsigned char* __restrict__ p2,
    const float* __restrict__ b_f1, const float* __restrict__ b_f2)
{
    extern __shared__ char smem[];
    const uint32_t sb = smem_u32(smem);
    const int tid = threadIdx.x, lane = tid & 31, wid = tid >> 5;
    const int wm = wid & 3, wn = wid >> 2;
    const int bm = blockIdx.x * FM;
    const int mat = lane >> 3, rin = lane & 7;
    const int lrow = (mat & 1) * 8 + rin;
    const int kof  = (mat >> 1) * 8;
    const float RS2 = 0.70710678118654752f;

    if (tid == 0) { MBAR_INIT(sb + SM_MB, 1); MBAR_INIT(sb + SM_MB + 8, 1); }
    for (int i = tid; i < 2048; i += 256) {
        int row = i >> 5, c8 = i & 31;
        *(uint4*)(smem + SM_HBH + row * 528 + c8 * 16) = *(const uint4*)(hBH + (size_t)(bm + row) * 256 + c8 * 8);
        *(uint4*)(smem + SM_HBL + row * 528 + c8 * 16) = *(const uint4*)(hBL + (size_t)(bm + row) * 256 + c8 * 8);
    }
    __syncthreads();

    auto issue = [&](int j) {
        int jj = j % 48;
        int nt = jj / 12, pi = jj % 12;
        const unsigned char* src; uint32_t bytes;
        if (pi < 8) { src = p1 + (size_t)(nt * 8 + pi) * 20480;       bytes = 20480; }
        else        { src = p2 + (size_t)(nt * 4 + (pi - 8)) * 40960; bytes = 40960; }
        uint32_t mb = sb + SM_MB + (j & 1) * 8;
        MBAR_EXPECT_TX(mb, bytes);
        bulkcp(sb + ((j & 1) ? SM_WS1 : SM_WS0), src, bytes, mb);
    };
    if (tid == 0) { issue(0); issue(1); }
    int cidx = 2, cc = 0, ph0 = 0, ph1 = 0;

    #pragma unroll 1
    for (int step = 0; step < NSTEPS; step++) {
        float acc2[16][4];
        #pragma unroll
        for (int a = 0; a < 16; a++)
            #pragma unroll
            for (int b = 0; b < 4; b++) acc2[a][b] = 0.0f;

        #pragma unroll 1
        for (int nt = 0; nt < 4; nt++) {
            float acc1[8][4];
            #pragma unroll
            for (int a = 0; a < 8; a++)
                #pragma unroll
                for (int b = 0; b < 4; b++) acc1[a][b] = 0.0f;

            #pragma unroll 1
            for (int kc = 0; kc < 8; kc++) {
                if ((cc & 1) == 0) { MBAR_WAIT(sb + SM_MB,     ph0); ph0 ^= 1; }
                else               { MBAR_WAIT(sb + SM_MB + 8, ph1); ph1 ^= 1; }
                const uint32_t ws = sb + ((cc & 1) ? SM_WS1 : SM_WS0);
                #pragma unroll
                for (int k16 = 0; k16 < 32; k16 += 16) {
                    int kg = kc * 32 + k16;
                    uint32_t ahf[4], alf[4];
                    uint32_t ad = sb + SM_HBH + (wm * 16 + lrow) * 528 + (kg + kof) * 2;
                    ldsm4(ahf, ad); ldsm4(alf, ad + (SM_HBL - SM_HBH));
                    uint32_t bh[4][4], bl[4][4];
                    #pragma unroll
                    for (int g = 0; g < 4; g++) {
                        uint32_t bd = ws + (wn * 64 + g * 16 + lrow) * 80 + (k16 + kof) * 2;
                        ldsm4(bh[g], bd); ldsm4(bl[g], bd + 10240);
                    }
                    #pragma unroll
                    for (int nj = 0; nj < 8; nj++) {
                        uint32_t b0 = bh[nj >> 1][nj & 1], b1 = bh[nj >> 1][2 + (nj & 1)];
                        uint32_t c0 = bl[nj >> 1][nj & 1], c1 = bl[nj >> 1][2 + (nj & 1)];
                        mma16816(acc1[nj], ahf, b0, b1);
                        mma16816(acc1[nj], ahf, c0, c1);
                        mma16816(acc1[nj], alf, b0, b1);
                    }
                }
                __syncthreads();
                if (tid == 0 && cidx < NCHUNK_TOT) issue(cidx);
                cidx++; cc++;
            }
            {
                int r0 = wm * 16 + (lane >> 2);
                #pragma unroll
                for (int nj = 0; nj < 8; nj++) {
                    int c = wn * 64 + nj * 8 + (lane & 3) * 2;
                    float bb0 = b_f1[nt * 128 + c], bb1 = b_f1[nt * 128 + c + 1];
                    float v[4] = {acc1[nj][0] + bb0, acc1[nj][1] + bb1,
                                  acc1[nj][2] + bb0, acc1[nj][3] + bb1};
                    float o[4];
                    #pragma unroll
                    for (int j = 0; j < 4; j++) o[j] = 0.5f * v[j] * (1.0f + erff(v[j] * RS2));
                    uint32_t lo0, lo1;
                    uint32_t hi0 = packsplit(o[0], o[1], lo0);
                    uint32_t hi1 = packsplit(o[2], o[3], lo1);
                    *(uint32_t*)(smem + SM_UH + (size_t)r0 * 272 + c * 2)       = hi0;
                    *(uint32_t*)(smem + SM_UL + (size_t)r0 * 272 + c * 2)       = lo0;
                    *(uint32_t*)(smem + SM_UH + (size_t)(r0 + 8) * 272 + c * 2) = hi1;
                    *(uint32_t*)(smem + SM_UL + (size_t)(r0 + 8) * 272 + c * 2) = lo1;
                }
            }
            __syncthreads();
            #pragma unroll 1
            for (int kc2 = 0; kc2 < 4; kc2++) {
                if ((cc & 1) == 0) { MBAR_WAIT(sb + SM_MB,     ph0); ph0 ^= 1; }
                else               { MBAR_WAIT(sb + SM_MB + 8, ph1); ph1 ^= 1; }
                const uint32_t ws = sb + ((cc & 1) ? SM_WS1 : SM_WS0);
                #pragma unroll
                for (int k16 = 0; k16 < 32; k16 += 16) {
                    int kl = kc2 * 32 + k16;
                    uint32_t ahf[4], alf[4];
                    uint32_t ad = sb + SM_UH + (wm * 16 + lrow) * 272 + (kl + kof) * 2;
                    ldsm4(ahf, ad); ldsm4(alf, ad + (SM_UL - SM_UH));
                    #pragma unroll
                    for (int g = 0; g < 8; g++) {
                        uint32_t bd = ws + (wn * 128 + g * 16 + lrow) * 80 + (k16 + kof) * 2;
                        uint32_t bh[4], bl2[4];
                        ldsm4(bh, bd); ldsm4(bl2, bd + 20480);
                        #pragma unroll
                        for (int s = 0; s < 2; s++) {
                            int nj = g * 2 + s;
                            mma16816(acc2[nj], ahf, bh[s],  bh[2 + s]);
                            mma16816(acc2[nj], ahf, bl2[s], bl2[2 + s]);
                            mma16816(acc2[nj], alf, bh[s],  bh[2 + s]);
                        }
                    }
                }
                __syncthreads();
                if (tid == 0 && cidx < NCHUNK_TOT) issue(cidx);
                cidx++; cc++;
            }
        }
        {
            int r0 = wm * 16 + (lane >> 2);
            #pragma unroll
            for (int nj = 0; nj < 16; nj++) {
                int c = wn * 128 + nj * 8 + (lane & 3) * 2;
                float bb0 = b_f2[c], bb1 = b_f2[c + 1];
                #pragma unroll
                for (int p = 0; p < 2; p++) {
                    int r = r0 + p * 8;
                    float v0 = acc2[nj][p * 2]     + bb0;
                    float v1 = acc2[nj][p * 2 + 1] + bb1;
                    uint32_t ohr = *(uint32_t*)(smem + SM_HBH + (size_t)r * 528 + c * 2);
                    uint32_t olr = *(uint32_t*)(smem + SM_HBL + (size_t)r * 528 + c * 2);
                    __half2 oh2 = *(__half2*)&ohr;
                    __half2 ol2 = *(__half2*)&olr;
                    float2 fh = __half22float2(oh2);
                    float2 fl = __half22float2(ol2);
                    float n0 = 0.5f * (fh.x + fl.x) + 0.5f * tanhf(v0);
                    float n1 = 0.5f * (fh.y + fl.y) + 0.5f * tanhf(v1);
                    uint32_t lo; uint32_t hi = packsplit(n0, n1, lo);
                    *(uint32_t*)(smem + SM_HBH + (size_t)r * 528 + c * 2) = hi;
                    *(uint32_t*)(smem + SM_HBL + (size_t)r * 528 + c * 2) = lo;
                }
            }
        }
        __syncthreads();
    }
    for (int i = tid; i < 2048; i += 256) {
        int row = i >> 5, c8 = i & 31;
        *(uint4*)(hBH + (size_t)(bm + row) * 256 + c8 * 8) = *(const uint4*)(smem + SM_HBH + row * 528 + c8 * 16);
        *(uint4*)(hBL + (size_t)(bm + row) * 256 + c8 * 8) = *(const uint4*)(smem + SM_HBL + row * 528 + c8 * 16);
    }
}

// ---------------- launch ----------------
extern "C" void kernel_launch(void* const* d_in, const int* in_sizes, int n_in,
                              void* d_out, int out_size) {
    const float* x     = (const float*)d_in[0];
    const float* z     = (const float*)d_in[1];
    const float* emb   = (const float*)d_in[2];
    const float* W_in1 = (const float*)d_in[3];
    const float* b_in1 = (const float*)d_in[4];
    const float* W_in2 = (const float*)d_in[5];
    const float* b_in2 = (const float*)d_in[6];
    const float* W_f1  = (const float*)d_in[7];
    const float* b_f1  = (const float*)d_in[8];
    const float* W_f2  = (const float*)d_in[9];
    const float* b_f2  = (const float*)d_in[10];
    const float* W_out = (const float*)d_in[11];
    const float* b_out = (const float*)d_in[12];
    float* out = (float*)d_out;

    cudaFuncSetAttribute(hgemm_g,    cudaFuncAttributeMaxDynamicSharedMemorySize, SMEMTOT);
    cudaFuncSetAttribute(hgemm_head, cudaFuncAttributeMaxDynamicSharedMemorySize, SMEMHEAD);
    cudaFuncSetAttribute(fractal_kernel, cudaFuncAttributeMaxDynamicSharedMemorySize, SMEM_FRAC);

    #define SYM(p, s) void* p; cudaGetSymbolAddress(&p, s)
    SYM(ftH, g_ftH); SYM(ftL, g_ftL);
    SYM(w1H, g_w1H); SYM(w1L, g_w1L);
    SYM(w2H, g_w2H); SYM(w2L, g_w2L);
    SYM(woH, g_woH);
    SYM(hAH, g_hAH); SYM(hAL, g_hAL);
    SYM(hBH, g_hBH); SYM(hBL, g_hBL);
    SYM(p1,  g_p1);  SYM(p2,  g_p2);
    #undef SYM
    typedef __half hf;

    feats_kernel<<<BROWS / 256, 256>>>(x, z, emb);
    dim3 wb(32, 8);
    wsplit_kernel<<<dim3(INPAD / 32, HID / 32),  wb>>>(W_in1, (hf*)w1H, (hf*)w1L, 121, INPAD, HID);
    wsplit_kernel<<<dim3(HID / 32,  HID / 32),   wb>>>(W_in2, (hf*)w2H, (hf*)w2L, HID, HID, HID);
    wsplit_kernel<<<dim3(HID / 32,  VOCAB / 32), wb>>>(W_out, (hf*)woH, nullptr, HID, HID, VOCAB);
    pack_f1<<<(HID * HID2 + 255) / 256, 256>>>(W_f1);
    pack_f2<<<(HID2 * HID + 255) / 256, 256>>>(W_f2);

    // mlp_in (3-term)
    hgemm_g<<<dim3(HID / 128, BROWS / 128), 256, SMEMTOT>>>(
        (hf*)ftH, (hf*)ftL, (hf*)w1H, (hf*)w1L, b_in1,
        (hf*)hAH, (hf*)hAL, HID, INPAD);
    hgemm_g<<<dim3(HID / 128, BROWS / 128), 256, SMEMTOT>>>(
        (hf*)hAH, (hf*)hAL, (hf*)w2H, (hf*)w2L, b_in2,
        (hf*)hBH, (hf*)hBL, HID, HID);

    // fractal refinement: ONE persistent launch for all 48 steps (3-term)
    fractal_kernel<<<BROWS / FM, 256, SMEM_FRAC>>>(
        (hf*)hBH, (hf*)hBL, (const unsigned char*)p1, (const unsigned char*)p2, b_f1, b_f2);

    // output head (1-term: A_hi x W_hi)
    hgemm_head<<<dim3(VOCAB / 128, BROWS / 128), 256, SMEMHEAD>>>(
        (hf*)hBH, (hf*)woH, b_out, out, VOCAB, HID);
}

// round 13
// speedup vs baseline: 3.4153x; 1.1897x over previous
#include <cuda_runtime.h>
#include <cuda_fp16.h>
#include <math.h>
#include <stdint.h>

#define BROWS 8192
#define HID   256
#define HID2  512
#define VOCAB 32000
#define INPAD 128
#define NSTEPS 48

// ---------------- device scratch (static, no allocation) ----------------
__device__ __align__(16) __half g_ftH[BROWS * INPAD];
__device__ __align__(16) __half g_ftL[BROWS * INPAD];
__device__ __align__(16) __half g_w1H[HID * INPAD],  g_w1L[HID * INPAD];
__device__ __align__(16) __half g_w2H[HID * HID],    g_w2L[HID * HID];
__device__ __align__(16) __half g_woH[(size_t)VOCAB * HID];
__device__ __align__(16) __half g_hAH[BROWS * HID],  g_hAL[BROWS * HID];
__device__ __align__(16) __half g_hBH[BROWS * HID],  g_hBL[BROWS * HID];
// packed weight panels for the fractal loop (ldmatrix-ready, 80B pitch rows)
__device__ __align__(16) unsigned char g_p1[32 * 20480];
__device__ __align__(16) unsigned char g_p2[16 * 40960];

// ---------------- helpers ----------------
__device__ __forceinline__ uint32_t smem_u32(const void* p) {
    uint32_t a;
    asm("{ .reg .u64 t; cvta.to.shared.u64 t, %1; cvt.u32.u64 %0, t; }" : "=r"(a) : "l"(p));
    return a;
}
__device__ __forceinline__ void split2(float v, __half& h, __half& l) {
    h = __float2half(v);
    l = __float2half(v - __half2float(h));
}
__device__ __forceinline__ uint32_t packsplit(float v0, float v1, uint32_t& lo) {
    __half h0, l0, h1, l1;
    split2(v0, h0, l0); split2(v1, h1, l1);
    uint16_t uh0 = __half_as_ushort(h0), uh1 = __half_as_ushort(h1);
    uint16_t ul0 = __half_as_ushort(l0), ul1 = __half_as_ushort(l1);
    lo = (uint32_t)ul0 | ((uint32_t)ul1 << 16);
    return (uint32_t)uh0 | ((uint32_t)uh1 << 16);
}
__device__ __forceinline__ uint32_t packh2(float v0, float v1) {
    __half h0 = __float2half(v0), h1 = __float2half(v1);
    return (uint32_t)__half_as_ushort(h0) | ((uint32_t)__half_as_ushort(h1) << 16);
}
__device__ __forceinline__ void cp16(uint32_t dst, const void* src) {
    asm volatile("cp.async.cg.shared.global [%0], [%1], 16;" :: "r"(dst), "l"(src));
}
__device__ __forceinline__ void ldsm4(uint32_t* r, uint32_t a) {
    asm volatile("ldmatrix.sync.aligned.m8n8.x4.shared.b16 {%0,%1,%2,%3}, [%4];"
                 : "=r"(r[0]), "=r"(r[1]), "=r"(r[2]), "=r"(r[3]) : "r"(a));
}
__device__ __forceinline__ void mma16816(float* d, const uint32_t* a, uint32_t b0, uint32_t b1) {
    asm volatile("mma.sync.aligned.m16n8k16.row.col.f32.f16.f16.f32 "
                 "{%0,%1,%2,%3}, {%4,%5,%6,%7}, {%8,%9}, {%0,%1,%2,%3};"
                 : "+f"(d[0]), "+f"(d[1]), "+f"(d[2]), "+f"(d[3])
                 : "r"(a[0]), "r"(a[1]), "r"(a[2]), "r"(a[3]), "r"(b0), "r"(b1));
}
__device__ __forceinline__ void bulkcp(uint32_t dst, const void* src, uint32_t bytes, uint32_t mbar) {
    asm volatile("cp.async.bulk.shared::cluster.global.mbarrier::complete_tx::bytes [%0], [%1], %2, [%3];"
                 :: "r"(dst), "l"(src), "r"(bytes), "r"(mbar) : "memory");
}
#define MBAR_INIT(a, c) \
    asm volatile("mbarrier.init.shared.b64 [%0], %1;" :: "r"(a), "r"((uint32_t)(c)) : "memory")
#define MBAR_EXPECT_TX(a, bytes) \
    asm volatile("mbarrier.arrive.expect_tx.shared.b64 _, [%0], %1;" :: "r"(a), "r"((uint32_t)(bytes)) : "memory")
#define MBAR_WAIT(a, p) do {                                                      \
    uint32_t _m = (a), _p = (uint32_t)(p), _d;                                    \
    asm volatile("{ .reg .pred q; mbarrier.try_wait.parity.acquire.cta.shared::cta.b64 q, [%1], %2; " \
                 "selp.b32 %0, 1, 0, q; }" : "=r"(_d) : "r"(_m), "r"(_p) : "memory"); \
    if (!_d) {                                                                    \
        asm volatile("{ .reg .pred Q; WL_%=: mbarrier.try_wait.parity.acquire.cta.shared::cta.b64 Q, [%0], %1, 0x989680; " \
                     "@Q bra.uni WD_%=; bra.uni WL_%=; WD_%=: }" :: "r"(_m), "r"(_p) : "memory"); \
    } } while (0)

// ---------------- feature assembly (fp16 hi/lo, padded to 128) ----------------
__global__ void feats_kernel(const float* __restrict__ x, const float* __restrict__ z,
                             const float* __restrict__ emb) {
    int b = blockIdx.x * blockDim.x + threadIdx.x;
    if (b >= BROWS) return;
    float xc = fminf(fmaxf(x[b], 0.0f), 1.0f);
    __half* fH = g_ftH + (size_t)b * INPAD;
    __half* fL = g_ftL + (size_t)b * INPAD;
    __half h, l;
    split2(xc, h, l); fH[0] = h; fL[0] = l;

    const float TWO_PI = 6.283185307179586f;
    float a = TWO_PI * xc;
    double fd = 1.0;
    #pragma unroll 1
    for (int j = 0; j < 32; j++) {
        float fr = (float)fd;
        float arg = a * fr;
        split2(sinf(arg), h, l); fH[1 + j] = h;  fL[1 + j] = l;
        split2(cosf(arg), h, l); fH[33 + j] = h; fL[33 + j] = l;
        fd *= 3.5;
    }
    float res = 16.0f;
    #pragma unroll 1
    for (int lv = 0; lv < 12; lv++) {
        float pos = xc * res;
        float i0f = floorf(pos);
        int   i0  = (int)i0f;
        float w   = pos - i0f;
        int h0 = i0 & 16383, h1 = (i0 + 1) & 16383;
        const float* t0 = emb + (size_t)h0 * 24 + lv * 2;
        const float* t1 = emb + (size_t)h1 * 24 + lv * 2;
        split2((1.0f - w) * t0[0] + w * t1[0], h, l); fH[65 + lv*2]   = h; fL[65 + lv*2]   = l;
        split2((1.0f - w) * t0[1] + w * t1[1], h, l); fH[65 + lv*2+1] = h; fL[65 + lv*2+1] = l;
        res *= 2.0f;
    }
    const float* zp = z + (size_t)b * 32;
    #pragma unroll
    for (int j = 0; j < 32; j++) { split2(zp[j], h, l); fH[89 + j] = h; fL[89 + j] = l; }
    #pragma unroll
    for (int j = 121; j < 128; j++) { fH[j] = __float2half(0.0f); fL[j] = __float2half(0.0f); }
}

// ---------------- weight transpose + split: W[Kreal][N] -> T{h,l}[N][Kpad] ----------------
__global__ void wsplit_kernel(const float* __restrict__ W, __half* __restrict__ Th,
                              __half* __restrict__ Tl, int Kreal, int Kpad, int N) {
    __shared__ float t[32][33];
    int kt = blockIdx.x * 32, nt = blockIdx.y * 32;
    int tx = threadIdx.x, ty = threadIdx.y;
    #pragma unroll
    for (int i = 0; i < 32; i += 8) {
        int k = kt + ty + i;
        t[ty + i][tx] = (k < Kreal) ? W[(size_t)k * N + nt + tx] : 0.0f;
    }
    __syncthreads();
    #pragma unroll
    for (int i = 0; i < 32; i += 8) {
        int n = nt + ty + i, k = kt + tx;
        __half h, l;
        split2(t[tx][ty + i], h, l);
        Th[(size_t)n * Kpad + k] = h;
        if (Tl) Tl[(size_t)n * Kpad + k] = l;
    }
}

// ---------------- pack W_f1 [256k][512n] into 32 bulk panels ----------------
__global__ void pack_f1(const float* __restrict__ W) {
    int i = blockIdx.x * 256 + threadIdx.x;
    if (i >= HID * HID2) return;
    int k = i / HID2, n = i % HID2;
    __half h, l; split2(W[i], h, l);
    int nt = n >> 7, nl = n & 127, kc = k >> 5, kl = k & 31;
    size_t base = (size_t)(nt * 8 + kc) * 20480;
    *(__half*)(g_p1 + base + nl * 80 + kl * 2) = h;
    *(__half*)(g_p1 + base + 10240 + nl * 80 + kl * 2) = l;
}
// ---------------- pack W_f2 [512k][256n] into 16 bulk panels ----------------
__global__ void pack_f2(const float* __restrict__ W) {
    int i = blockIdx.x * 256 + threadIdx.x;
    if (i >= HID2 * HID) return;
    int k = i / HID, n = i % HID;
    __half h, l; split2(W[i], h, l);
    int nt = k >> 7, kc = (k >> 5) & 3, kl = k & 31;
    size_t base = (size_t)(nt * 4 + kc) * 40960;
    *(__half*)(g_p2 + base + n * 80 + kl * 2) = h;
    *(__half*)(g_p2 + base + 20480 + n * 80 + kl * 2) = l;
}

// ---------------- 3-term fp16 GEMM (mlp_in) ----------------
#define TSTR   80
#define TBYTES (128 * TSTR)
#define BUFB   (4 * TBYTES)
#define SMEMTOT (2 * BUFB)

__global__ void __launch_bounds__(256) hgemm_g(
    const __half* __restrict__ Ah, const __half* __restrict__ Al,
    const __half* __restrict__ Bh, const __half* __restrict__ Bl,
    const float* __restrict__ bias,
    __half* __restrict__ Ch, __half* __restrict__ Cl, int N, int K)
{
    extern __shared__ char smem[];
    const uint32_t sb = smem_u32(smem);
    const int tid  = threadIdx.x;
    const int lane = tid & 31, wid = tid >> 5;
    const int wm = wid & 3, wn = wid >> 2;
    const int bm = blockIdx.y * 128, bn = blockIdx.x * 128;
    const int nchunks = K >> 5;

    float acc[2][8][4];
    #pragma unroll
    for (int a = 0; a < 2; a++)
        #pragma unroll
        for (int b = 0; b < 8; b++)
            #pragma unroll
            for (int c = 0; c < 4; c++) acc[a][b][c] = 0.0f;

    const __half* gsrc[4] = {Ah, Al, Bh, Bl};

    auto load_chunk = [&](int c, int buf) {
        const int k0 = c << 5;
        uint32_t base = sb + buf * BUFB;
        #pragma unroll
        for (int t4 = 0; t4 < 4; t4++) {
            const __half* g = gsrc[t4];
            int rb = (t4 < 2) ? bm : bn;
            #pragma unroll
            for (int i = 0; i < 2; i++) {
                int idx = tid + i * 256;
                int row = idx >> 2, c16 = idx & 3;
                cp16(base + t4 * TBYTES + row * TSTR + c16 * 16,
                     g + (size_t)(rb + row) * K + k0 + c16 * 8);
            }
        }
    };

    const int mat = lane >> 3, rin = lane & 7;
    const int lrow = (mat & 1) * 8 + rin;
    const int kof  = (mat >> 1) * 8;

    load_chunk(0, 0);
    asm volatile("cp.async.commit_group;" ::: "memory");

    for (int c = 0; c < nchunks; c++) {
        const int buf = c & 1;
        if (c + 1 < nchunks) load_chunk(c + 1, buf ^ 1);
        asm volatile("cp.async.commit_group;" ::: "memory");
        if (c + 1 < nchunks) asm volatile("cp.async.wait_group 1;" ::: "memory");
        else                 asm volatile("cp.async.wait_group 0;" ::: "memory");
        __syncthreads();

        const uint32_t sa = sb + buf * BUFB;
        #pragma unroll
        for (int k16 = 0; k16 < 32; k16 += 16) {
            uint32_t ahf[2][4], alf[2][4];
            #pragma unroll
            for (int mt = 0; mt < 2; mt++) {
                uint32_t ad = sa + (wm * 32 + mt * 16 + lrow) * TSTR + (k16 + kof) * 2;
                ldsm4(ahf[mt], ad);
                ldsm4(alf[mt], ad + TBYTES);
            }
            uint32_t bhf[4][4], blf[4][4];
            #pragma unroll
            for (int g = 0; g < 4; g++) {
                uint32_t bd = sa + 2 * TBYTES + (wn * 64 + g * 16 + lrow) * TSTR + (k16 + kof) * 2;
                ldsm4(bhf[g], bd);
                ldsm4(blf[g], bd + TBYTES);
            }
            #pragma unroll
            for (int nj = 0; nj < 8; nj++) {
                uint32_t b0 = bhf[nj >> 1][nj & 1], b1 = bhf[nj >> 1][2 + (nj & 1)];
                uint32_t c0 = blf[nj >> 1][nj & 1], c1 = blf[nj >> 1][2 + (nj & 1)];
                mma16816(acc[0][nj], ahf[0], b0, b1);
                mma16816(acc[1][nj], ahf[1], b0, b1);
                mma16816(acc[0][nj], ahf[0], c0, c1);
                mma16816(acc[1][nj], ahf[1], c0, c1);
                mma16816(acc[0][nj], alf[0], b0, b1);
                mma16816(acc[1][nj], alf[1], b0, b1);
            }
        }
        __syncthreads();
    }

    const float RS2 = 0.70710678118654752f;
    #pragma unroll
    for (int mt = 0; mt < 2; mt++) {
        #pragma unroll
        for (int nj = 0; nj < 8; nj++) {
            float* d = acc[mt][nj];
            int rg = bm + wm * 32 + mt * 16 + (lane >> 2);
            int cg = bn + wn * 64 + nj * 8 + (lane & 3) * 2;
            float bb0 = bias[cg], bb1 = bias[cg + 1];
            size_t off0 = (size_t)rg * N + cg;
            size_t off1 = (size_t)(rg + 8) * N + cg;
            float v[4] = {d[0] + bb0, d[1] + bb1, d[2] + bb0, d[3] + bb1};
            float o[4];
            #pragma unroll
            for (int j = 0; j < 4; j++)
                o[j] = 0.5f * v[j] * (1.0f + erff(v[j] * RS2));
            uint32_t lo0, lo1;
            uint32_t hi0 = packsplit(o[0], o[1], lo0);
            uint32_t hi1 = packsplit(o[2], o[3], lo1);
            *(uint32_t*)(Ch + off0) = hi0;  *(uint32_t*)(Cl + off0) = lo0;
            *(uint32_t*)(Ch + off1) = hi1;  *(uint32_t*)(Cl + off1) = lo1;
        }
    }
}

// ---------------- 1-term fp16 head GEMM: C = A_hi @ B_hi^T + bias ----------------
#define HBUFB    (2 * TBYTES)
#define SMEMHEAD (2 * HBUFB)

__global__ void __launch_bounds__(256) hgemm_head(
    const __half* __restrict__ Ah, const __half* __restrict__ Bh,
    const float* __restrict__ bias, float* __restrict__ Cf, int N, int K)
{
    extern __shared__ char smem[];
    const uint32_t sb = smem_u32(smem);
    const int tid  = threadIdx.x;
    const int lane = tid & 31, wid = tid >> 5;
    const int wm = wid & 3, wn = wid >> 2;
    const int bm = blockIdx.y * 128, bn = blockIdx.x * 128;
    const int nchunks = K >> 5;

    float acc[2][8][4];
    #pragma unroll
    for (int a = 0; a < 2; a++)
        #pragma unroll
        for (int b = 0; b < 8; b++)
            #pragma unroll
            for (int c = 0; c < 4; c++) acc[a][b][c] = 0.0f;

    const __half* gsrc[2] = {Ah, Bh};

    auto load_chunk = [&](int c, int buf) {
        const int k0 = c << 5;
        uint32_t base = sb + buf * HBUFB;
        #pragma unroll
        for (int t2 = 0; t2 < 2; t2++) {
            const __half* g = gsrc[t2];
            int rb = (t2 == 0) ? bm : bn;
            #pragma unroll
            for (int i = 0; i < 2; i++) {
                int idx = tid + i * 256;
                int row = idx >> 2, c16 = idx & 3;
                cp16(base + t2 * TBYTES + row * TSTR + c16 * 16,
                     g + (size_t)(rb + row) * K + k0 + c16 * 8);
            }
        }
    };

    const int mat = lane >> 3, rin = lane & 7;
    const int lrow = (mat & 1) * 8 + rin;
    const int kof  = (mat >> 1) * 8;

    load_chunk(0, 0);
    asm volatile("cp.async.commit_group;" ::: "memory");

    for (int c = 0; c < nchunks; c++) {
        const int buf = c & 1;
        if (c + 1 < nchunks) load_chunk(c + 1, buf ^ 1);
        asm volatile("cp.async.commit_group;" ::: "memory");
        if (c + 1 < nchunks) asm volatile("cp.async.wait_group 1;" ::: "memory");
        else                 asm volatile("cp.async.wait_group 0;" ::: "memory");
        __syncthreads();

        const uint32_t sa = sb + buf * HBUFB;
        #pragma unroll
        for (int k16 = 0; k16 < 32; k16 += 16) {
            uint32_t ahf[2][4];
            #pragma unroll
            for (int mt = 0; mt < 2; mt++) {
                uint32_t ad = sa + (wm * 32 + mt * 16 + lrow) * TSTR + (k16 + kof) * 2;
                ldsm4(ahf[mt], ad);
            }
            uint32_t bhf[4][4];
            #pragma unroll
            for (int g = 0; g < 4; g++) {
                uint32_t bd = sa + TBYTES + (wn * 64 + g * 16 + lrow) * TSTR + (k16 + kof) * 2;
                ldsm4(bhf[g], bd);
            }
            #pragma unroll
            for (int nj = 0; nj < 8; nj++) {
                uint32_t b0 = bhf[nj >> 1][nj & 1], b1 = bhf[nj >> 1][2 + (nj & 1)];
                mma16816(acc[0][nj], ahf[0], b0, b1);
                mma16816(acc[1][nj], ahf[1], b0, b1);
            }
        }
        __syncthreads();
    }

    #pragma unroll
    for (int mt = 0; mt < 2; mt++) {
        #pragma unroll
        for (int nj = 0; nj < 8; nj++) {
            float* d = acc[mt][nj];
            int rg = bm + wm * 32 + mt * 16 + (lane >> 2);
            int cg = bn + wn * 64 + nj * 8 + (lane & 3) * 2;
            float bb0 = bias[cg], bb1 = bias[cg + 1];
            *(float2*)(Cf + (size_t)rg * N + cg)       = make_float2(d[0] + bb0, d[1] + bb1);
            *(float2*)(Cf + (size_t)(rg + 8) * N + cg) = make_float2(d[2] + bb0, d[3] + bb1);
        }
    }
}

// ---------------- persistent fractal loop kernel (2-term: activation-lo dropped) ----------------
// hB kept hi/lo in smem ONLY for the exact 0.5*h carry; GEMMs consume hi parts only.
#define FM       64
#define SM_HBH   0
#define SM_HBL   33792
#define SM_UH    67584
#define SM_WS0   102400
#define SM_WS1   143360
#define SM_MB    184320
#define SMEM_FRAC 184336
#define NCHUNK_TOT (NSTEPS * 48)

__global__ void __launch_bounds__(256) fractal_kernel(
    __half* __restrict__ hBH, __half* __restrict__ hBL,
    const unsigned char* __restrict__ p1, const unsigned char* __restrict__ p2,
    const float* __restrict__ b_f1, const float* __restrict__ b_f2)
{
    extern __shared__ char smem[];
    const uint32_t sb = smem_u32(smem);
    const int tid = threadIdx.x, lane = tid & 31, wid = tid >> 5;
    const int wm = wid & 3, wn = wid >> 2;
    const int bm = blockIdx.x * FM;
    const int mat = lane >> 3, rin = lane & 7;
    const int lrow = (mat & 1) * 8 + rin;
    const int kof  = (mat >> 1) * 8;
    const float RS2 = 0.70710678118654752f;

    if (tid == 0) { MBAR_INIT(sb + SM_MB, 1); MBAR_INIT(sb + SM_MB + 8, 1); }
    for (int i = tid; i < 2048; i += 256) {
        int row = i >> 5, c8 = i & 31;
        *(uint4*)(smem + SM_HBH + row * 528 + c8 * 16) = *(const uint4*)(hBH + (size_t)(bm + row) * 256 + c8 * 8);
        *(uint4*)(smem + SM_HBL + row * 528 + c8 * 16) = *(const uint4*)(hBL + (size_t)(bm + row) * 256 + c8 * 8);
    }
    __syncthreads();

    auto issue = [&](int j) {
        int jj = j % 48;
        int nt = jj / 12, pi = jj % 12;
        const unsigned char* src; uint32_t bytes;
        if (pi < 8) { src = p1 + (size_t)(nt * 8 + pi) * 20480;       bytes = 20480; }
        else        { src = p2 + (size_t)(nt * 4 + (pi - 8)) * 40960; bytes = 40960; }
        uint32_t mb = sb + SM_MB + (j & 1) * 8;
        MBAR_EXPECT_TX(mb, bytes);
        bulkcp(sb + ((j & 1) ? SM_WS1 : SM_WS0), src, bytes, mb);
    };
    if (tid == 0) { issue(0); issue(1); }
    int cidx = 2, cc = 0, ph0 = 0, ph1 = 0;

    #pragma unroll 1
    for (int step = 0; step < NSTEPS; step++) {
        float acc2[16][4];
        #pragma unroll
        for (int a = 0; a < 16; a++)
            #pragma unroll
            for (int b = 0; b < 4; b++) acc2[a][b] = 0.0f;

        #pragma unroll 1
        for (int nt = 0; nt < 4; nt++) {
            // ---- GEMM1 (2-term): u = gelu(hB_hi @ (W1h + W1l)^T + b) ----
            float acc1[8][4];
            #pragma unroll
            for (int a = 0; a < 8; a++)
                #pragma unroll
                for (int b = 0; b < 4; b++) acc1[a][b] = 0.0f;

            #pragma unroll 1
            for (int kc = 0; kc < 8; kc++) {
                if ((cc & 1) == 0) { MBAR_WAIT(sb + SM_MB,     ph0); ph0 ^= 1; }
                else               { MBAR_WAIT(sb + SM_MB + 8, ph1); ph1 ^= 1; }
                const uint32_t ws = sb + ((cc & 1) ? SM_WS1 : SM_WS0);
                #pragma unroll
                for (int k16 = 0; k16 < 32; k16 += 16) {
                    int kg = kc * 32 + k16;
                    uint32_t ahf[4];
                    uint32_t ad = sb + SM_HBH + (wm * 16 + lrow) * 528 + (kg + kof) * 2;
                    ldsm4(ahf, ad);
                    uint32_t bh[4][4], bl[4][4];
                    #pragma unroll
                    for (int g = 0; g < 4; g++) {
                        uint32_t bd = ws + (wn * 64 + g * 16 + lrow) * 80 + (k16 + kof) * 2;
                        ldsm4(bh[g], bd); ldsm4(bl[g], bd + 10240);
                    }
                    #pragma unroll
                    for (int nj = 0; nj < 8; nj++) {
                        uint32_t b0 = bh[nj >> 1][nj & 1], b1 = bh[nj >> 1][2 + (nj & 1)];
                        uint32_t c0 = bl[nj >> 1][nj & 1], c1 = bl[nj >> 1][2 + (nj & 1)];
                        mma16816(acc1[nj], ahf, b0, b1);
                        mma16816(acc1[nj], ahf, c0, c1);
                    }
                }
                __syncthreads();
                if (tid == 0 && cidx < NCHUNK_TOT) issue(cidx);
                cidx++; cc++;
            }
            {   // u epilogue: gelu -> u smem (hi only, pitch 272)
                int r0 = wm * 16 + (lane >> 2);
                #pragma unroll
                for (int nj = 0; nj < 8; nj++) {
                    int c = wn * 64 + nj * 8 + (lane & 3) * 2;
                    float bb0 = b_f1[nt * 128 + c], bb1 = b_f1[nt * 128 + c + 1];
                    float v[4] = {acc1[nj][0] + bb0, acc1[nj][1] + bb1,
                                  acc1[nj][2] + bb0, acc1[nj][3] + bb1};
                    float o[4];
                    #pragma unroll
                    for (int j = 0; j < 4; j++) o[j] = 0.5f * v[j] * (1.0f + erff(v[j] * RS2));
                    *(uint32_t*)(smem + SM_UH + (size_t)r0 * 272 + c * 2)       = packh2(o[0], o[1]);
                    *(uint32_t*)(smem + SM_UH + (size_t)(r0 + 8) * 272 + c * 2) = packh2(o[2], o[3]);
                }
            }
            __syncthreads();
            // ---- GEMM2 partial (2-term): acc2 += u_hi @ (W2h + W2l)^T ----
            #pragma unroll 1
            for (int kc2 = 0; kc2 < 4; kc2++) {
                if ((cc & 1) == 0) { MBAR_WAIT(sb + SM_MB,     ph0); ph0 ^= 1; }
                else               { MBAR_WAIT(sb + SM_MB + 8, ph1); ph1 ^= 1; }
                const uint32_t ws = sb + ((cc & 1) ? SM_WS1 : SM_WS0);
                #pragma unroll
                for (int k16 = 0; k16 < 32; k16 += 16) {
                    int kl = kc2 * 32 + k16;
                    uint32_t ahf[4];
                    uint32_t ad = sb + SM_UH + (wm * 16 + lrow) * 272 + (kl + kof) * 2;
                    ldsm4(ahf, ad);
                    #pragma unroll
                    for (int g = 0; g < 8; g++) {
                        uint32_t bd = ws + (wn * 128 + g * 16 + lrow) * 80 + (k16 + kof) * 2;
                        uint32_t bh[4], bl2[4];
                        ldsm4(bh, bd); ldsm4(bl2, bd + 20480);
                        #pragma unroll
                        for (int s = 0; s < 2; s++) {
                            int nj = g * 2 + s;
                            mma16816(acc2[nj], ahf, bh[s],  bh[2 + s]);
                            mma16816(acc2[nj], ahf, bl2[s], bl2[2 + s]);
                        }
                    }
                }
                __syncthreads();
                if (tid == 0 && cidx < NCHUNK_TOT) issue(cidx);
                cidx++; cc++;
            }
        }
        {   // hB epilogue: hB = 0.5*(hB_hi+hB_lo) + 0.5*tanh(acc2 + b_f2), re-split hi/lo
            int r0 = wm * 16 + (lane >> 2);
            #pragma unroll
            for (int nj = 0; nj < 16; nj++) {
                int c = wn * 128 + nj * 8 + (lane & 3) * 2;
                float bb0 = b_f2[c], bb1 = b_f2[c + 1];
                #pragma unroll
                for (int p = 0; p < 2; p++) {
                    int r = r0 + p * 8;
                    float v0 = acc2[nj][p * 2]     + bb0;
                    float v1 = acc2[nj][p * 2 + 1] + bb1;
                    uint32_t ohr = *(uint32_t*)(smem + SM_HBH + (size_t)r * 528 + c * 2);
                    uint32_t olr = *(uint32_t*)(smem + SM_HBL + (size_t)r * 528 + c * 2);
                    __half2 oh2 = *(__half2*)&ohr;
                    __half2 ol2 = *(__half2*)&olr;
                    float2 fh = __half22float2(oh2);
                    float2 fl = __half22float2(ol2);
                    float n0 = 0.5f * (fh.x + fl.x) + 0.5f * tanhf(v0);
                    float n1 = 0.5f * (fh.y + fl.y) + 0.5f * tanhf(v1);
                    uint32_t lo; uint32_t hi = packsplit(n0, n1, lo);
                    *(uint32_t*)(smem + SM_HBH + (size_t)r * 528 + c * 2) = hi;
                    *(uint32_t*)(smem + SM_HBL + (size_t)r * 528 + c * 2) = lo;
                }
            }
        }
        __syncthreads();
    }
    for (int i = tid; i < 2048; i += 256) {
        int row = i >> 5, c8 = i & 31;
        *(uint4*)(hBH + (size_t)(bm + row) * 256 + c8 * 8) = *(const uint4*)(smem + SM_HBH + row * 528 + c8 * 16);
        *(uint4*)(hBL + (size_t)(bm + row) * 256 + c8 * 8) = *(const uint4*)(smem + SM_HBL + row * 528 + c8 * 16);
    }
}

// ---------------- launch ----------------
extern "C" void kernel_launch(void* const* d_in, const int* in_sizes, int n_in,
                              void* d_out, int out_size) {
    const float* x     = (const float*)d_in[0];
    const float* z     = (const float*)d_in[1];
    const float* emb   = (const float*)d_in[2];
    const float* W_in1 = (const float*)d_in[3];
    const float* b_in1 = (const float*)d_in[4];
    const float* W_in2 = (const float*)d_in[5];
    const float* b_in2 = (const float*)d_in[6];
    const float* W_f1  = (const float*)d_in[7];
    const float* b_f1  = (const float*)d_in[8];
    const float* W_f2  = (const float*)d_in[9];
    const float* b_f2  = (const float*)d_in[10];
    const float* W_out = (const float*)d_in[11];
    const float* b_out = (const float*)d_in[12];
    float* out = (float*)d_out;

    cudaFuncSetAttribute(hgemm_g,    cudaFuncAttributeMaxDynamicSharedMemorySize, SMEMTOT);
    cudaFuncSetAttribute(hgemm_head, cudaFuncAttributeMaxDynamicSharedMemorySize, SMEMHEAD);
    cudaFuncSetAttribute(fractal_kernel, cudaFuncAttributeMaxDynamicSharedMemorySize, SMEM_FRAC);

    #define SYM(p, s) void* p; cudaGetSymbolAddress(&p, s)
    SYM(ftH, g_ftH); SYM(ftL, g_ftL);
    SYM(w1H, g_w1H); SYM(w1L, g_w1L);
    SYM(w2H, g_w2H); SYM(w2L, g_w2L);
    SYM(woH, g_woH);
    SYM(hAH, g_hAH); SYM(hAL, g_hAL);
    SYM(hBH, g_hBH); SYM(hBL, g_hBL);
    SYM(p1,  g_p1);  SYM(p2,  g_p2);
    #undef SYM
    typedef __half hf;

    feats_kernel<<<BROWS / 256, 256>>>(x, z, emb);
    dim3 wb(32, 8);
    wsplit_kernel<<<dim3(INPAD / 32, HID / 32),  wb>>>(W_in1, (hf*)w1H, (hf*)w1L, 121, INPAD, HID);
    wsplit_kernel<<<dim3(HID / 32,  HID / 32),   wb>>>(W_in2, (hf*)w2H, (hf*)w2L, HID, HID, HID);
    wsplit_kernel<<<dim3(HID / 32,  VOCAB / 32), wb>>>(W_out, (hf*)woH, nullptr, HID, HID, VOCAB);
    pack_f1<<<(HID * HID2 + 255) / 256, 256>>>(W_f1);
    pack_f2<<<(HID2 * HID + 255) / 256, 256>>>(W_f2);

    // mlp_in (3-term)
    hgemm_g<<<dim3(HID / 128, BROWS / 128), 256, SMEMTOT>>>(
        (hf*)ftH, (hf*)ftL, (hf*)w1H, (hf*)w1L, b_in1,
        (hf*)hAH, (hf*)hAL, HID, INPAD);
    hgemm_g<<<dim3(HID / 128, BROWS / 128), 256, SMEMTOT>>>(
        (hf*)hAH, (hf*)hAL, (hf*)w2H, (hf*)w2L, b_in2,
        (hf*)hBH, (hf*)hBL, HID, HID);

    // fractal refinement: ONE persistent launch, 2-term GEMMs
    fractal_kernel<<<BROWS / FM, 256, SMEM_FRAC>>>(
        (hf*)hBH, (hf*)hBL, (const unsigned char*)p1, (const unsigned char*)p2, b_f1, b_f2);

    // output head (1-term: A_hi x W_hi)
    hgemm_head<<<dim3(VOCAB / 128, BROWS / 128), 256, SMEMHEAD>>>(
        (hf*)hBH, (hf*)woH, b_out, out, VOCAB, HID);
}

// round 14
// speedup vs baseline: 4.3185x; 1.2645x over previous
#include <cuda_runtime.h>
#include <cuda_fp16.h>
#include <math.h>
#include <stdint.h>

#define BROWS 8192
#define HID   256
#define HID2  512
#define VOCAB 32000
#define INPAD 128
#define NSTEPS 48

// ---------------- device scratch (static, no allocation) ----------------
__device__ __align__(16) __half g_ftH[BROWS * INPAD];
__device__ __align__(16) __half g_w1H[HID * INPAD];
__device__ __align__(16) __half g_w2H[HID * HID];
__device__ __align__(16) __half g_woH[(size_t)VOCAB * HID];
__device__ __align__(16) __half g_hAH[BROWS * HID], g_hAL[BROWS * HID];
__device__ __align__(16) __half g_hBH[BROWS * HID], g_hBL[BROWS * HID];
// packed hi-only weight panels for the fractal loop (ldmatrix-ready, 80B pitch)
__device__ __align__(16) unsigned char g_p1[32 * 10240];   // W_f1: 32 panels [128n][32k]
__device__ __align__(16) unsigned char g_p2[16 * 20480];   // W_f2: 16 panels [256n][32k]

// ---------------- helpers ----------------
__device__ __forceinline__ uint32_t smem_u32(const void* p) {
    uint32_t a;
    asm("{ .reg .u64 t; cvta.to.shared.u64 t, %1; cvt.u32.u64 %0, t; }" : "=r"(a) : "l"(p));
    return a;
}
__device__ __forceinline__ void split2(float v, __half& h, __half& l) {
    h = __float2half(v);
    l = __float2half(v - __half2float(h));
}
__device__ __forceinline__ uint32_t packsplit(float v0, float v1, uint32_t& lo) {
    __half h0, l0, h1, l1;
    split2(v0, h0, l0); split2(v1, h1, l1);
    lo = (uint32_t)__half_as_ushort(l0) | ((uint32_t)__half_as_ushort(l1) << 16);
    return (uint32_t)__half_as_ushort(h0) | ((uint32_t)__half_as_ushort(h1) << 16);
}
__device__ __forceinline__ uint32_t packh2(float v0, float v1) {
    __half h0 = __float2half(v0), h1 = __float2half(v1);
    return (uint32_t)__half_as_ushort(h0) | ((uint32_t)__half_as_ushort(h1) << 16);
}
__device__ __forceinline__ void cp16(uint32_t dst, const void* src) {
    asm volatile("cp.async.cg.shared.global [%0], [%1], 16;" :: "r"(dst), "l"(src));
}
__device__ __forceinline__ void ldsm4(uint32_t* r, uint32_t a) {
    asm volatile("ldmatrix.sync.aligned.m8n8.x4.shared.b16 {%0,%1,%2,%3}, [%4];"
                 : "=r"(r[0]), "=r"(r[1]), "=r"(r[2]), "=r"(r[3]) : "r"(a));
}
__device__ __forceinline__ void mma16816(float* d, const uint32_t* a, uint32_t b0, uint32_t b1) {
    asm volatile("mma.sync.aligned.m16n8k16.row.col.f32.f16.f16.f32 "
                 "{%0,%1,%2,%3}, {%4,%5,%6,%7}, {%8,%9}, {%0,%1,%2,%3};"
                 : "+f"(d[0]), "+f"(d[1]), "+f"(d[2]), "+f"(d[3])
                 : "r"(a[0]), "r"(a[1]), "r"(a[2]), "r"(a[3]), "r"(b0), "r"(b1));
}
__device__ __forceinline__ void bulkcp(uint32_t dst, const void* src, uint32_t bytes, uint32_t mbar) {
    asm volatile("cp.async.bulk.shared::cluster.global.mbarrier::complete_tx::bytes [%0], [%1], %2, [%3];"
                 :: "r"(dst), "l"(src), "r"(bytes), "r"(mbar) : "memory");
}
#define MBAR_INIT(a, c) \
    asm volatile("mbarrier.init.shared.b64 [%0], %1;" :: "r"(a), "r"((uint32_t)(c)) : "memory")
#define MBAR_EXPECT_TX(a, bytes) \
    asm volatile("mbarrier.arrive.expect_tx.shared.b64 _, [%0], %1;" :: "r"(a), "r"((uint32_t)(bytes)) : "memory")
#define MBAR_WAIT(a, p) do {                                                      \
    uint32_t _m = (a), _p = (uint32_t)(p), _d;                                    \
    asm volatile("{ .reg .pred q; mbarrier.try_wait.parity.acquire.cta.shared::cta.b64 q, [%1], %2; " \
                 "selp.b32 %0, 1, 0, q; }" : "=r"(_d) : "r"(_m), "r"(_p) : "memory"); \
    if (!_d) {                                                                    \
        asm volatile("{ .reg .pred Q; WL_%=: mbarrier.try_wait.parity.acquire.cta.shared::cta.b64 Q, [%0], %1, 0x989680; " \
                     "@Q bra.uni WD_%=; bra.uni WL_%=; WD_%=: }" :: "r"(_m), "r"(_p) : "memory"); \
    } } while (0)

// ---------------- feature assembly (fp16 hi only, padded to 128) ----------------
__global__ void feats_kernel(const float* __restrict__ x, const float* __restrict__ z,
                             const float* __restrict__ emb) {
    int b = blockIdx.x * blockDim.x + threadIdx.x;
    if (b >= BROWS) return;
    float xc = fminf(fmaxf(x[b], 0.0f), 1.0f);
    __half* fH = g_ftH + (size_t)b * INPAD;
    fH[0] = __float2half(xc);

    const float TWO_PI = 6.283185307179586f;
    float a = TWO_PI * xc;
    double fd = 1.0;
    #pragma unroll 1
    for (int j = 0; j < 32; j++) {
        float fr = (float)fd;
        float arg = a * fr;
        fH[1 + j]  = __float2half(sinf(arg));
        fH[33 + j] = __float2half(cosf(arg));
        fd *= 3.5;
    }
    float res = 16.0f;
    #pragma unroll 1
    for (int lv = 0; lv < 12; lv++) {
        float pos = xc * res;
        float i0f = floorf(pos);
        int   i0  = (int)i0f;
        float w   = pos - i0f;
        int h0 = i0 & 16383, h1 = (i0 + 1) & 16383;
        const float* t0 = emb + (size_t)h0 * 24 + lv * 2;
        const float* t1 = emb + (size_t)h1 * 24 + lv * 2;
        fH[65 + lv*2]   = __float2half((1.0f - w) * t0[0] + w * t1[0]);
        fH[65 + lv*2+1] = __float2half((1.0f - w) * t0[1] + w * t1[1]);
        res *= 2.0f;
    }
    const float* zp = z + (size_t)b * 32;
    #pragma unroll
    for (int j = 0; j < 32; j++) fH[89 + j] = __float2half(zp[j]);
    #pragma unroll
    for (int j = 121; j < 128; j++) fH[j] = __float2half(0.0f);
}

// ---------------- weight transpose (hi only): W[Kreal][N] -> Th[N][Kpad] ----------------
__global__ void wsplit_kernel(const float* __restrict__ W, __half* __restrict__ Th,
                              int Kreal, int Kpad, int N) {
    __shared__ float t[32][33];
    int kt = blockIdx.x * 32, nt = blockIdx.y * 32;
    int tx = threadIdx.x, ty = threadIdx.y;
    #pragma unroll
    for (int i = 0; i < 32; i += 8) {
        int k = kt + ty + i;
        t[ty + i][tx] = (k < Kreal) ? W[(size_t)k * N + nt + tx] : 0.0f;
    }
    __syncthreads();
    #pragma unroll
    for (int i = 0; i < 32; i += 8) {
        int n = nt + ty + i, k = kt + tx;
        Th[(size_t)n * Kpad + k] = __float2half(t[tx][ty + i]);
    }
}

// ---------------- pack W_f1 [256k][512n] hi into 32 panels ----------------
__global__ void pack_f1(const float* __restrict__ W) {
    int i = blockIdx.x * 256 + threadIdx.x;
    if (i >= HID * HID2) return;
    int k = i / HID2, n = i % HID2;
    int nt = n >> 7, nl = n & 127, kc = k >> 5, kl = k & 31;
    *(__half*)(g_p1 + (size_t)(nt * 8 + kc) * 10240 + nl * 80 + kl * 2) = __float2half(W[i]);
}
// ---------------- pack W_f2 [512k][256n] hi into 16 panels ----------------
__global__ void pack_f2(const float* __restrict__ W) {
    int i = blockIdx.x * 256 + threadIdx.x;
    if (i >= HID2 * HID) return;
    int k = i / HID, n = i % HID;
    int nt = k >> 7, kc = (k >> 5) & 3, kl = k & 31;
    *(__half*)(g_p2 + (size_t)(nt * 4 + kc) * 20480 + n * 80 + kl * 2) = __float2half(W[i]);
}

// ---------------- 1-term fp16 GEMM: C = epi(A_hi @ B_hi^T + bias) ----------------
// EPI 0: GELU -> Ch (+ Cl split) ; EPI 2: fp32 + bias -> Cf
#define TSTR   80
#define TBYTES (128 * TSTR)
#define HBUFB  (2 * TBYTES)
#define SMEMG  (2 * HBUFB)

template <int EPI>
__global__ void __launch_bounds__(256) hgemm1(
    const __half* __restrict__ Ah, const __half* __restrict__ Bh,
    const float* __restrict__ bias,
    __half* __restrict__ Ch, __half* __restrict__ Cl,
    float* __restrict__ Cf, int N, int K)
{
    extern __shared__ char smem[];
    const uint32_t sb = smem_u32(smem);
    const int tid  = threadIdx.x;
    const int lane = tid & 31, wid = tid >> 5;
    const int wm = wid & 3, wn = wid >> 2;
    const int bm = blockIdx.y * 128, bn = blockIdx.x * 128;
    const int nchunks = K >> 5;

    float acc[2][8][4];
    #pragma unroll
    for (int a = 0; a < 2; a++)
        #pragma unroll
        for (int b = 0; b < 8; b++)
            #pragma unroll
            for (int c = 0; c < 4; c++) acc[a][b][c] = 0.0f;

    const __half* gsrc[2] = {Ah, Bh};

    auto load_chunk = [&](int c, int buf) {
        const int k0 = c << 5;
        uint32_t base = sb + buf * HBUFB;
        #pragma unroll
        for (int t2 = 0; t2 < 2; t2++) {
            const __half* g = gsrc[t2];
            int rb = (t2 == 0) ? bm : bn;
            #pragma unroll
            for (int i = 0; i < 2; i++) {
                int idx = tid + i * 256;
                int row = idx >> 2, c16 = idx & 3;
                cp16(base + t2 * TBYTES + row * TSTR + c16 * 16,
                     g + (size_t)(rb + row) * K + k0 + c16 * 8);
            }
        }
    };

    const int mat = lane >> 3, rin = lane & 7;
    const int lrow = (mat & 1) * 8 + rin;
    const int kof  = (mat >> 1) * 8;

    load_chunk(0, 0);
    asm volatile("cp.async.commit_group;" ::: "memory");

    for (int c = 0; c < nchunks; c++) {
        const int buf = c & 1;
        if (c + 1 < nchunks) load_chunk(c + 1, buf ^ 1);
        asm volatile("cp.async.commit_group;" ::: "memory");
        if (c + 1 < nchunks) asm volatile("cp.async.wait_group 1;" ::: "memory");
        else                 asm volatile("cp.async.wait_group 0;" ::: "memory");
        __syncthreads();

        const uint32_t sa = sb + buf * HBUFB;
        #pragma unroll
        for (int k16 = 0; k16 < 32; k16 += 16) {
            uint32_t ahf[2][4];
            #pragma unroll
            for (int mt = 0; mt < 2; mt++) {
                uint32_t ad = sa + (wm * 32 + mt * 16 + lrow) * TSTR + (k16 + kof) * 2;
                ldsm4(ahf[mt], ad);
            }
            uint32_t bhf[4][4];
            #pragma unroll
            for (int g = 0; g < 4; g++) {
                uint32_t bd = sa + TBYTES + (wn * 64 + g * 16 + lrow) * TSTR + (k16 + kof) * 2;
                ldsm4(bhf[g], bd);
            }
            #pragma unroll
            for (int nj = 0; nj < 8; nj++) {
                uint32_t b0 = bhf[nj >> 1][nj & 1], b1 = bhf[nj >> 1][2 + (nj & 1)];
                mma16816(acc[0][nj], ahf[0], b0, b1);
                mma16816(acc[1][nj], ahf[1], b0, b1);
            }
        }
        __syncthreads();
    }

    const float RS2 = 0.70710678118654752f;
    #pragma unroll
    for (int mt = 0; mt < 2; mt++) {
        #pragma unroll
        for (int nj = 0; nj < 8; nj++) {
            float* d = acc[mt][nj];
            int rg = bm + wm * 32 + mt * 16 + (lane >> 2);
            int cg = bn + wn * 64 + nj * 8 + (lane & 3) * 2;
            float bb0 = bias[cg], bb1 = bias[cg + 1];
            size_t off0 = (size_t)rg * N + cg;
            size_t off1 = (size_t)(rg + 8) * N + cg;
            if (EPI == 2) {
                *(float2*)(Cf + off0) = make_float2(d[0] + bb0, d[1] + bb1);
                *(float2*)(Cf + off1) = make_float2(d[2] + bb0, d[3] + bb1);
            } else {
                float v[4] = {d[0] + bb0, d[1] + bb1, d[2] + bb0, d[3] + bb1};
                float o[4];
                #pragma unroll
                for (int j = 0; j < 4; j++)
                    o[j] = 0.5f * v[j] * (1.0f + erff(v[j] * RS2));
                uint32_t lo0, lo1;
                uint32_t hi0 = packsplit(o[0], o[1], lo0);
                uint32_t hi1 = packsplit(o[2], o[3], lo1);
                *(uint32_t*)(Ch + off0) = hi0;  *(uint32_t*)(Cl + off0) = lo0;
                *(uint32_t*)(Ch + off1) = hi1;  *(uint32_t*)(Cl + off1) = lo1;
            }
        }
    }
}

// ---------------- persistent fractal loop kernel (1-term GEMMs, exact hi/lo carry) ----------------
#define FM       64
#define SM_HBH   0
#define SM_HBL   33792          // 64*528
#define SM_UH    67584          // 64*272
#define SM_WS0   84992
#define SM_WS1   105472         // +20480
#define SM_MB    125952
#define SMEM_FRAC 125984
#define NCHUNK_TOT (NSTEPS * 48)

__global__ void __launch_bounds__(256) fractal_kernel(
    __half* __restrict__ hBH, __half* __restrict__ hBL,
    const unsigned char* __restrict__ p1, const unsigned char* __restrict__ p2,
    const float* __restrict__ b_f1, const float* __restrict__ b_f2)
{
    extern __shared__ char smem[];
    const uint32_t sb = smem_u32(smem);
    const int tid = threadIdx.x, lane = tid & 31, wid = tid >> 5;
    const int wm = wid & 3, wn = wid >> 2;
    const int bm = blockIdx.x * FM;
    const int mat = lane >> 3, rin = lane & 7;
    const int lrow = (mat & 1) * 8 + rin;
    const int kof  = (mat >> 1) * 8;
    const float RS2 = 0.70710678118654752f;

    if (tid == 0) { MBAR_INIT(sb + SM_MB, 1); MBAR_INIT(sb + SM_MB + 8, 1); }
    for (int i = tid; i < 2048; i += 256) {
        int row = i >> 5, c8 = i & 31;
        *(uint4*)(smem + SM_HBH + row * 528 + c8 * 16) = *(const uint4*)(hBH + (size_t)(bm + row) * 256 + c8 * 8);
        *(uint4*)(smem + SM_HBL + row * 528 + c8 * 16) = *(const uint4*)(hBL + (size_t)(bm + row) * 256 + c8 * 8);
    }
    __syncthreads();

    auto issue = [&](int j) {
        int jj = j % 48;
        int nt = jj / 12, pi = jj % 12;
        const unsigned char* src; uint32_t bytes;
        if (pi < 8) { src = p1 + (size_t)(nt * 8 + pi) * 10240;       bytes = 10240; }
        else        { src = p2 + (size_t)(nt * 4 + (pi - 8)) * 20480; bytes = 20480; }
        uint32_t mb = sb + SM_MB + (j & 1) * 8;
        MBAR_EXPECT_TX(mb, bytes);
        bulkcp(sb + ((j & 1) ? SM_WS1 : SM_WS0), src, bytes, mb);
    };
    if (tid == 0) { issue(0); issue(1); }
    int cidx = 2, cc = 0, ph0 = 0, ph1 = 0;

    #pragma unroll 1
    for (int step = 0; step < NSTEPS; step++) {
        float acc2[16][4];
        #pragma unroll
        for (int a = 0; a < 16; a++)
            #pragma unroll
            for (int b = 0; b < 4; b++) acc2[a][b] = 0.0f;

        #pragma unroll 1
        for (int nt = 0; nt < 4; nt++) {
            // ---- GEMM1 (1-term): u = gelu(hB_hi @ W1h^T + b) ----
            float acc1[8][4];
            #pragma unroll
            for (int a = 0; a < 8; a++)
                #pragma unroll
                for (int b = 0; b < 4; b++) acc1[a][b] = 0.0f;

            #pragma unroll 1
            for (int kc = 0; kc < 8; kc++) {
                if ((cc & 1) == 0) { MBAR_WAIT(sb + SM_MB,     ph0); ph0 ^= 1; }
                else               { MBAR_WAIT(sb + SM_MB + 8, ph1); ph1 ^= 1; }
                const uint32_t ws = sb + ((cc & 1) ? SM_WS1 : SM_WS0);
                #pragma unroll
                for (int k16 = 0; k16 < 32; k16 += 16) {
                    int kg = kc * 32 + k16;
                    uint32_t ahf[4];
                    uint32_t ad = sb + SM_HBH + (wm * 16 + lrow) * 528 + (kg + kof) * 2;
                    ldsm4(ahf, ad);
                    uint32_t bh[4][4];
                    #pragma unroll
                    for (int g = 0; g < 4; g++) {
                        uint32_t bd = ws + (wn * 64 + g * 16 + lrow) * 80 + (k16 + kof) * 2;
                        ldsm4(bh[g], bd);
                    }
                    #pragma unroll
                    for (int nj = 0; nj < 8; nj++) {
                        uint32_t b0 = bh[nj >> 1][nj & 1], b1 = bh[nj >> 1][2 + (nj & 1)];
                        mma16816(acc1[nj], ahf, b0, b1);
                    }
                }
                __syncthreads();
                if (tid == 0 && cidx < NCHUNK_TOT) issue(cidx);
                cidx++; cc++;
            }
            {   // u epilogue: gelu -> u smem (hi only, pitch 272)
                int r0 = wm * 16 + (lane >> 2);
                #pragma unroll
                for (int nj = 0; nj < 8; nj++) {
                    int c = wn * 64 + nj * 8 + (lane & 3) * 2;
                    float bb0 = b_f1[nt * 128 + c], bb1 = b_f1[nt * 128 + c + 1];
                    float v[4] = {acc1[nj][0] + bb0, acc1[nj][1] + bb1,
                                  acc1[nj][2] + bb0, acc1[nj][3] + bb1};
                    float o[4];
                    #pragma unroll
                    for (int j = 0; j < 4; j++) o[j] = 0.5f * v[j] * (1.0f + erff(v[j] * RS2));
                    *(uint32_t*)(smem + SM_UH + (size_t)r0 * 272 + c * 2)       = packh2(o[0], o[1]);
                    *(uint32_t*)(smem + SM_UH + (size_t)(r0 + 8) * 272 + c * 2) = packh2(o[2], o[3]);
                }
            }
            __syncthreads();
            // ---- GEMM2 partial (1-term): acc2 += u_hi @ W2h^T ----
            #pragma unroll 1
            for (int kc2 = 0; kc2 < 4; kc2++) {
                if ((cc & 1) == 0) { MBAR_WAIT(sb + SM_MB,     ph0); ph0 ^= 1; }
                else               { MBAR_WAIT(sb + SM_MB + 8, ph1); ph1 ^= 1; }
                const uint32_t ws = sb + ((cc & 1) ? SM_WS1 : SM_WS0);
                #pragma unroll
                for (int k16 = 0; k16 < 32; k16 += 16) {
                    int kl = kc2 * 32 + k16;
                    uint32_t ahf[4];
                    uint32_t ad = sb + SM_UH + (wm * 16 + lrow) * 272 + (kl + kof) * 2;
                    ldsm4(ahf, ad);
                    #pragma unroll
                    for (int g = 0; g < 8; g++) {
                        uint32_t bd = ws + (wn * 128 + g * 16 + lrow) * 80 + (k16 + kof) * 2;
                        uint32_t bh[4];
                        ldsm4(bh, bd);
                        #pragma unroll
                        for (int s = 0; s < 2; s++) {
                            int nj = g * 2 + s;
                            mma16816(acc2[nj], ahf, bh[s], bh[2 + s]);
                        }
                    }
                }
                __syncthreads();
                if (tid == 0 && cidx < NCHUNK_TOT) issue(cidx);
                cidx++; cc++;
            }
        }
        {   // hB epilogue: hB = 0.5*(hB_hi+hB_lo) + 0.5*tanh(acc2 + b_f2), re-split hi/lo
            int r0 = wm * 16 + (lane >> 2);
            #pragma unroll
            for (int nj = 0; nj < 16; nj++) {
                int c = wn * 128 + nj * 8 + (lane & 3) * 2;
                float bb0 = b_f2[c], bb1 = b_f2[c + 1];
                #pragma unroll
                for (int p = 0; p < 2; p++) {
                    int r = r0 + p * 8;
                    float v0 = acc2[nj][p * 2]     + bb0;
                    float v1 = acc2[nj][p * 2 + 1] + bb1;
                    uint32_t ohr = *(uint32_t*)(smem + SM_HBH + (size_t)r * 528 + c * 2);
                    uint32_t olr = *(uint32_t*)(smem + SM_HBL + (size_t)r * 528 + c * 2);
                    __half2 oh2 = *(__half2*)&ohr;
                    __half2 ol2 = *(__half2*)&olr;
                    float2 fh = __half22float2(oh2);
                    float2 fl = __half22float2(ol2);
                    float n0 = 0.5f * (fh.x + fl.x) + 0.5f * tanhf(v0);
                    float n1 = 0.5f * (fh.y + fl.y) + 0.5f * tanhf(v1);
                    uint32_t lo; uint32_t hi = packsplit(n0, n1, lo);
                    *(uint32_t*)(smem + SM_HBH + (size_t)r * 528 + c * 2) = hi;
                    *(uint32_t*)(smem + SM_HBL + (size_t)r * 528 + c * 2) = lo;
                }
            }
        }
        __syncthreads();
    }
    for (int i = tid; i < 2048; i += 256) {
        int row = i >> 5, c8 = i & 31;
        *(uint4*)(hBH + (size_t)(bm + row) * 256 + c8 * 8) = *(const uint4*)(smem + SM_HBH + row * 528 + c8 * 16);
        *(uint4*)(hBL + (size_t)(bm + row) * 256 + c8 * 8) = *(const uint4*)(smem + SM_HBL + row * 528 + c8 * 16);
    }
}

// ---------------- launch ----------------
extern "C" void kernel_launch(void* const* d_in, const int* in_sizes, int n_in,
                              void* d_out, int out_size) {
    const float* x     = (const float*)d_in[0];
    const float* z     = (const float*)d_in[1];
    const float* emb   = (const float*)d_in[2];
    const float* W_in1 = (const float*)d_in[3];
    const float* b_in1 = (const float*)d_in[4];
    const float* W_in2 = (const float*)d_in[5];
    const float* b_in2 = (const float*)d_in[6];
    const float* W_f1  = (const float*)d_in[7];
    const float* b_f1  = (const float*)d_in[8];
    const float* W_f2  = (const float*)d_in[9];
    const float* b_f2  = (const float*)d_in[10];
    const float* W_out = (const float*)d_in[11];
    const float* b_out = (const float*)d_in[12];
    float* out = (float*)d_out;

    cudaFuncSetAttribute(hgemm1<0>, cudaFuncAttributeMaxDynamicSharedMemorySize, SMEMG);
    cudaFuncSetAttribute(hgemm1<2>, cudaFuncAttributeMaxDynamicSharedMemorySize, SMEMG);
    cudaFuncSetAttribute(fractal_kernel, cudaFuncAttributeMaxDynamicSharedMemorySize, SMEM_FRAC);

    #define SYM(p, s) void* p; cudaGetSymbolAddress(&p, s)
    SYM(ftH, g_ftH);
    SYM(w1H, g_w1H); SYM(w2H, g_w2H); SYM(woH, g_woH);
    SYM(hAH, g_hAH); SYM(hAL, g_hAL);
    SYM(hBH, g_hBH); SYM(hBL, g_hBL);
    SYM(p1,  g_p1);  SYM(p2,  g_p2);
    #undef SYM
    typedef __half hf;

    feats_kernel<<<BROWS / 256, 256>>>(x, z, emb);
    dim3 wb(32, 8);
    wsplit_kernel<<<dim3(INPAD / 32, HID / 32),  wb>>>(W_in1, (hf*)w1H, 121, INPAD, HID);
    wsplit_kernel<<<dim3(HID / 32,  HID / 32),   wb>>>(W_in2, (hf*)w2H, HID, HID, HID);
    wsplit_kernel<<<dim3(HID / 32,  VOCAB / 32), wb>>>(W_out, (hf*)woH, HID, HID, VOCAB);
    pack_f1<<<(HID * HID2 + 255) / 256, 256>>>(W_f1);
    pack_f2<<<(HID2 * HID + 255) / 256, 256>>>(W_f2);

    // mlp_in (1-term)
    hgemm1<0><<<dim3(HID / 128, BROWS / 128), 256, SMEMG>>>(
        (hf*)ftH, (hf*)w1H, b_in1, (hf*)hAH, (hf*)hAL, nullptr, HID, INPAD);
    hgemm1<0><<<dim3(HID / 128, BROWS / 128), 256, SMEMG>>>(
        (hf*)hAH, (hf*)w2H, b_in2, (hf*)hBH, (hf*)hBL, nullptr, HID, HID);

    // fractal refinement: ONE persistent launch, 1-term GEMMs + exact hi/lo carry
    fractal_kernel<<<BROWS / FM, 256, SMEM_FRAC>>>(
        (hf*)hBH, (hf*)hBL, (const unsigned char*)p1, (const unsigned char*)p2, b_f1, b_f2);

    // output head (1-term)
    hgemm1<2><<<dim3(VOCAB / 128, BROWS / 128), 256, SMEMG>>>(
        (hf*)hBH, (hf*)woH, b_out, nullptr, nullptr, out, VOCAB, HID);
}

// round 16
// speedup vs baseline: 4.8264x; 1.1176x over previous
#include <cuda_runtime.h>
#include <cuda_fp16.h>
#include <math.h>
#include <stdint.h>

#define BROWS 8192
#define HID   256
#define HID2  512
#define VOCAB 32000
#define INPAD 128
#define NSTEPS 48

// ---------------- device scratch (static, no allocation) ----------------
__device__ __align__(16) __half g_ftH[BROWS * INPAD];
__device__ __align__(16) __half g_w1H[HID * INPAD];
__device__ __align__(16) __half g_w2H[HID * HID];
__device__ __align__(16) __half g_woH[(size_t)VOCAB * HID];
__device__ __align__(16) __half g_hAH[BROWS * HID], g_hAL[BROWS * HID];
__device__ __align__(16) __half g_hBH[BROWS * HID], g_hBL[BROWS * HID];
// hi-only weight panels for the fractal loop, 64-K chunks, 144B pitch (ldmatrix-ready)
#define P1PAN 18432              // [128n][64k] : 128 * 144
#define P2PAN 36864              // [256n][64k] : 256 * 144
__device__ __align__(16) unsigned char g_p1[16 * P1PAN];   // W_f1: (nt 0..3, kc 0..3)
__device__ __align__(16) unsigned char g_p2[8  * P2PAN];   // W_f2: (nt 0..3, kc2 0..1)

// ---------------- helpers ----------------
__device__ __forceinline__ uint32_t smem_u32(const void* p) {
    uint32_t a;
    asm("{ .reg .u64 t; cvta.to.shared.u64 t, %1; cvt.u32.u64 %0, t; }" : "=r"(a) : "l"(p));
    return a;
}
__device__ __forceinline__ void split2(float v, __half& h, __half& l) {
    h = __float2half(v);
    l = __float2half(v - __half2float(h));
}
__device__ __forceinline__ uint32_t packsplit(float v0, float v1, uint32_t& lo) {
    __half h0, l0, h1, l1;
    split2(v0, h0, l0); split2(v1, h1, l1);
    lo = (uint32_t)__half_as_ushort(l0) | ((uint32_t)__half_as_ushort(l1) << 16);
    return (uint32_t)__half_as_ushort(h0) | ((uint32_t)__half_as_ushort(h1) << 16);
}
__device__ __forceinline__ uint32_t packh2(float v0, float v1) {
    __half h0 = __float2half(v0), h1 = __float2half(v1);
    return (uint32_t)__half_as_ushort(h0) | ((uint32_t)__half_as_ushort(h1) << 16);
}
__device__ __forceinline__ void cp16(uint32_t dst, const void* src) {
    asm volatile("cp.async.cg.shared.global [%0], [%1], 16;" :: "r"(dst), "l"(src));
}
__device__ __forceinline__ void ldsm4(uint32_t* r, uint32_t a) {
    asm volatile("ldmatrix.sync.aligned.m8n8.x4.shared.b16 {%0,%1,%2,%3}, [%4];"
                 : "=r"(r[0]), "=r"(r[1]), "=r"(r[2]), "=r"(r[3]) : "r"(a));
}
__device__ __forceinline__ void mma16816(float* d, const uint32_t* a, uint32_t b0, uint32_t b1) {
    asm volatile("mma.sync.aligned.m16n8k16.row.col.f32.f16.f16.f32 "
                 "{%0,%1,%2,%3}, {%4,%5,%6,%7}, {%8,%9}, {%0,%1,%2,%3};"
                 : "+f"(d[0]), "+f"(d[1]), "+f"(d[2]), "+f"(d[3])
                 : "r"(a[0]), "r"(a[1]), "r"(a[2]), "r"(a[3]), "r"(b0), "r"(b1));
}
__device__ __forceinline__ void bulkcp(uint32_t dst, const void* src, uint32_t bytes, uint32_t mbar) {
    asm volatile("cp.async.bulk.shared::cluster.global.mbarrier::complete_tx::bytes [%0], [%1], %2, [%3];"
                 :: "r"(dst), "l"(src), "r"(bytes), "r"(mbar) : "memory");
}
#define MBAR_INIT(a, c) \
    asm volatile("mbarrier.init.shared.b64 [%0], %1;" :: "r"(a), "r"((uint32_t)(c)) : "memory")
#define MBAR_EXPECT_TX(a, bytes) \
    asm volatile("mbarrier.arrive.expect_tx.shared.b64 _, [%0], %1;" :: "r"(a), "r"((uint32_t)(bytes)) : "memory")
#define MBAR_WAIT(a, p) do {                                                      \
    uint32_t _m = (a), _p = (uint32_t)(p), _d;                                    \
    asm volatile("{ .reg .pred q; mbarrier.try_wait.parity.acquire.cta.shared::cta.b64 q, [%1], %2; " \
                 "selp.b32 %0, 1, 0, q; }" : "=r"(_d) : "r"(_m), "r"(_p) : "memory"); \
    if (!_d) {                                                                    \
        asm volatile("{ .reg .pred Q; WL_%=: mbarrier.try_wait.parity.acquire.cta.shared::cta.b64 Q, [%0], %1, 0x989680; " \
                     "@Q bra.uni WD_%=; bra.uni WL_%=; WD_%=: }" :: "r"(_m), "r"(_p) : "memory"); \
    } } while (0)

// ---------------- feature assembly (fp16 hi only, padded to 128) ----------------
__global__ void feats_kernel(const float* __restrict__ x, const float* __restrict__ z,
                             const float* __restrict__ emb) {
    int b = blockIdx.x * blockDim.x + threadIdx.x;
    if (b >= BROWS) return;
    float xc = fminf(fmaxf(x[b], 0.0f), 1.0f);
    __half* fH = g_ftH + (size_t)b * INPAD;
    fH[0] = __float2half(xc);

    const float TWO_PI = 6.283185307179586f;
    float a = TWO_PI * xc;
    double fd = 1.0;
    #pragma unroll 1
    for (int j = 0; j < 32; j++) {
        float fr = (float)fd;
        float arg = a * fr;
        fH[1 + j]  = __float2half(sinf(arg));
        fH[33 + j] = __float2half(cosf(arg));
        fd *= 3.5;
    }
    float res = 16.0f;
    #pragma unroll 1
    for (int lv = 0; lv < 12; lv++) {
        float pos = xc * res;
        float i0f = floorf(pos);
        int   i0  = (int)i0f;
        float w   = pos - i0f;
        int h0 = i0 & 16383, h1 = (i0 + 1) & 16383;
        const float* t0 = emb + (size_t)h0 * 24 + lv * 2;
        const float* t1 = emb + (size_t)h1 * 24 + lv * 2;
        fH[65 + lv*2]   = __float2half((1.0f - w) * t0[0] + w * t1[0]);
        fH[65 + lv*2+1] = __float2half((1.0f - w) * t0[1] + w * t1[1]);
        res *= 2.0f;
    }
    const float* zp = z + (size_t)b * 32;
    #pragma unroll
    for (int j = 0; j < 32; j++) fH[89 + j] = __float2half(zp[j]);
    #pragma unroll
    for (int j = 121; j < 128; j++) fH[j] = __float2half(0.0f);
}

// ---------------- weight transpose (hi only): W[Kreal][N] -> Th[N][Kpad] ----------------
__global__ void wsplit_kernel(const float* __restrict__ W, __half* __restrict__ Th,
                              int Kreal, int Kpad, int N) {
    __shared__ float t[32][33];
    int kt = blockIdx.x * 32, nt = blockIdx.y * 32;
    int tx = threadIdx.x, ty = threadIdx.y;
    #pragma unroll
    for (int i = 0; i < 32; i += 8) {
        int k = kt + ty + i;
        t[ty + i][tx] = (k < Kreal) ? W[(size_t)k * N + nt + tx] : 0.0f;
    }
    __syncthreads();
    #pragma unroll
    for (int i = 0; i < 32; i += 8) {
        int n = nt + ty + i, k = kt + tx;
        Th[(size_t)n * Kpad + k] = __float2half(t[tx][ty + i]);
    }
}

// ---------------- pack W_f1 [256k][512n] hi into 16 panels ([128n][64k], 144B pitch) ----------------
__global__ void pack_f1(const float* __restrict__ W) {
    int i = blockIdx.x * 256 + threadIdx.x;
    if (i >= HID * HID2) return;
    int k = i / HID2, n = i % HID2;
    int nt = n >> 7, nl = n & 127, kc = k >> 6, kl = k & 63;
    *(__half*)(g_p1 + (size_t)(nt * 4 + kc) * P1PAN + nl * 144 + kl * 2) = __float2half(W[i]);
}
// ---------------- pack W_f2 [512k][256n] hi into 8 panels ([256n][64k], 144B pitch) ----------------
__global__ void pack_f2(const float* __restrict__ W) {
    int i = blockIdx.x * 256 + threadIdx.x;
    if (i >= HID2 * HID) return;
    int k = i / HID, n = i % HID;
    int nt = k >> 7, kc2 = (k >> 6) & 1, kl = k & 63;
    *(__half*)(g_p2 + (size_t)(nt * 2 + kc2) * P2PAN + n * 144 + kl * 2) = __float2half(W[i]);
}

// ---------------- 1-term fp16 GEMM: C = epi(A_hi @ B_hi^T + bias) ----------------
// EPI 0: GELU -> Ch (+ Cl split) ; EPI 2: fp32 + bias -> Cf
#define TSTR   80
#define TBYTES (128 * TSTR)
#define HBUFB  (2 * TBYTES)
#define SMEMG  (2 * HBUFB)

template <int EPI>
__global__ void __launch_bounds__(256) hgemm1(
    const __half* __restrict__ Ah, const __half* __restrict__ Bh,
    const float* __restrict__ bias,
    __half* __restrict__ Ch, __half* __restrict__ Cl,
    float* __restrict__ Cf, int N, int K)
{
    extern __shared__ char smem[];
    const uint32_t sb = smem_u32(smem);
    const int tid  = threadIdx.x;
    const int lane = tid & 31, wid = tid >> 5;
    const int wm = wid & 3, wn = wid >> 2;
    const int bm = blockIdx.y * 128, bn = blockIdx.x * 128;
    const int nchunks = K >> 5;

    float acc[2][8][4];
    #pragma unroll
    for (int a = 0; a < 2; a++)
        #pragma unroll
        for (int b = 0; b < 8; b++)
            #pragma unroll
            for (int c = 0; c < 4; c++) acc[a][b][c] = 0.0f;

    const __half* gsrc[2] = {Ah, Bh};

    auto load_chunk = [&](int c, int buf) {
        const int k0 = c << 5;
        uint32_t base = sb + buf * HBUFB;
        #pragma unroll
        for (int t2 = 0; t2 < 2; t2++) {
            const __half* g = gsrc[t2];
            int rb = (t2 == 0) ? bm : bn;
            #pragma unroll
            for (int i = 0; i < 2; i++) {
                int idx = tid + i * 256;
                int row = idx >> 2, c16 = idx & 3;
                cp16(base + t2 * TBYTES + row * TSTR + c16 * 16,
                     g + (size_t)(rb + row) * K + k0 + c16 * 8);
            }
        }
    };

    const int mat = lane >> 3, rin = lane & 7;
    const int lrow = (mat & 1) * 8 + rin;
    const int kof  = (mat >> 1) * 8;

    load_chunk(0, 0);
    asm volatile("cp.async.commit_group;" ::: "memory");

    for (int c = 0; c < nchunks; c++) {
        const int buf = c & 1;
        if (c + 1 < nchunks) load_chunk(c + 1, buf ^ 1);
        asm volatile("cp.async.commit_group;" ::: "memory");
        if (c + 1 < nchunks) asm volatile("cp.async.wait_group 1;" ::: "memory");
        else                 asm volatile("cp.async.wait_group 0;" ::: "memory");
        __syncthreads();

        const uint32_t sa = sb + buf * HBUFB;
        #pragma unroll
        for (int k16 = 0; k16 < 32; k16 += 16) {
            uint32_t ahf[2][4];
            #pragma unroll
            for (int mt = 0; mt < 2; mt++) {
                uint32_t ad = sa + (wm * 32 + mt * 16 + lrow) * TSTR + (k16 + kof) * 2;
                ldsm4(ahf[mt], ad);
            }
            uint32_t bhf[4][4];
            #pragma unroll
            for (int g = 0; g < 4; g++) {
                uint32_t bd = sa + TBYTES + (wn * 64 + g * 16 + lrow) * TSTR + (k16 + kof) * 2;
                ldsm4(bhf[g], bd);
            }
            #pragma unroll
            for (int nj = 0; nj < 8; nj++) {
                uint32_t b0 = bhf[nj >> 1][nj & 1], b1 = bhf[nj >> 1][2 + (nj & 1)];
                mma16816(acc[0][nj], ahf[0], b0, b1);
                mma16816(acc[1][nj], ahf[1], b0, b1);
            }
        }
        __syncthreads();
    }

    const float RS2 = 0.70710678118654752f;
    #pragma unroll
    for (int mt = 0; mt < 2; mt++) {
        #pragma unroll
        for (int nj = 0; nj < 8; nj++) {
            float* d = acc[mt][nj];
            int rg = bm + wm * 32 + mt * 16 + (lane >> 2);
            int cg = bn + wn * 64 + nj * 8 + (lane & 3) * 2;
            float bb0 = bias[cg], bb1 = bias[cg + 1];
            size_t off0 = (size_t)rg * N + cg;
            size_t off1 = (size_t)(rg + 8) * N + cg;
            if (EPI == 2) {
                *(float2*)(Cf + off0) = make_float2(d[0] + bb0, d[1] + bb1);
                *(float2*)(Cf + off1) = make_float2(d[2] + bb0, d[3] + bb1);
            } else {
                float v[4] = {d[0] + bb0, d[1] + bb1, d[2] + bb0, d[3] + bb1};
                float o[4];
                #pragma unroll
                for (int j = 0; j < 4; j++)
                    o[j] = 0.5f * v[j] * (1.0f + erff(v[j] * RS2));
                uint32_t lo0, lo1;
                uint32_t hi0 = packsplit(o[0], o[1], lo0);
                uint32_t hi1 = packsplit(o[2], o[3], lo1);
                *(uint32_t*)(Ch + off0) = hi0;  *(uint32_t*)(Cl + off0) = lo0;
                *(uint32_t*)(Ch + off1) = hi1;  *(uint32_t*)(Cl + off1) = lo1;
            }
        }
    }
}

// ---------------- persistent fractal loop kernel ----------------
// 512 threads (16 warps: 4M x 4N), 64-K chunks, 1-term GEMMs, exact hi/lo carry.
#define FM       64
#define SM_HBH   0
#define SM_HBL   33792          // 64*528
#define SM_UH    67584          // 64*272 = 17408
#define SM_WS0   84992
#define SM_WS1   (84992 + P2PAN)          // 121856
#define SM_MB    (SM_WS1 + P2PAN)         // 158720
#define SMEM_FRAC (SM_MB + 16)            // 158736
#define NCHUNK_TOT (NSTEPS * 24)

__global__ void __launch_bounds__(512) fractal_kernel(
    __half* __restrict__ hBH, __half* __restrict__ hBL,
    const unsigned char* __restrict__ p1, const unsigned char* __restrict__ p2,
    const float* __restrict__ b_f1, const float* __restrict__ b_f2)
{
    extern __shared__ char smem[];
    const uint32_t sb = smem_u32(smem);
    const int tid = threadIdx.x, lane = tid & 31, wid = tid >> 5;
    const int wm = wid & 3;          // M slice: 4 x 16 rows
    const int wn = wid >> 2;         // N slice: 4
    const int bm = blockIdx.x * FM;
    const int mat = lane >> 3, rin = lane & 7;
    const int lrow = (mat & 1) * 8 + rin;
    const int kof  = (mat >> 1) * 8;
    const float RS2 = 0.70710678118654752f;

    if (tid == 0) { MBAR_INIT(sb + SM_MB, 1); MBAR_INIT(sb + SM_MB + 8, 1); }
    for (int i = tid; i < 2048; i += 512) {
        int row = i >> 5, c8 = i & 31;
        *(uint4*)(smem + SM_HBH + row * 528 + c8 * 16) = *(const uint4*)(hBH + (size_t)(bm + row) * 256 + c8 * 8);
        *(uint4*)(smem + SM_HBL + row * 528 + c8 * 16) = *(const uint4*)(hBL + (size_t)(bm + row) * 256 + c8 * 8);
    }
    __syncthreads();

    // chunk schedule per step: for nt in 0..3: 4x G1 panel (nt*4+kc), 2x G2 panel (nt*2+kc2)
    auto issue = [&](int j) {
        int jj = j % 24;
        int nt = jj / 6, pi = jj % 6;
        const unsigned char* src; uint32_t bytes;
        if (pi < 4) { src = p1 + (size_t)(nt * 4 + pi) * P1PAN;       bytes = P1PAN; }
        else        { src = p2 + (size_t)(nt * 2 + (pi - 4)) * P2PAN; bytes = P2PAN; }
        uint32_t mb = sb + SM_MB + (j & 1) * 8;
        MBAR_EXPECT_TX(mb, bytes);
        bulkcp(sb + ((j & 1) ? SM_WS1 : SM_WS0), src, bytes, mb);
    };
    if (tid == 0) { issue(0); issue(1); }
    int cidx = 2, cc = 0, ph0 = 0, ph1 = 0;

    #pragma unroll 1
    for (int step = 0; step < NSTEPS; step++) {
        float acc2[8][4];
        #pragma unroll
        for (int a = 0; a < 8; a++)
            #pragma unroll
            for (int b = 0; b < 4; b++) acc2[a][b] = 0.0f;

        #pragma unroll 1
        for (int nt = 0; nt < 4; nt++) {
            // ---- GEMM1 (1-term): u[64,128] = gelu(hB_hi[64,256] @ W1h^T + b) ----
            float acc1[4][4];
            #pragma unroll
            for (int a = 0; a < 4; a++)
                #pragma unroll
                for (int b = 0; b < 4; b++) acc1[a][b] = 0.0f;

            #pragma unroll 1
            for (int kc = 0; kc < 4; kc++) {
                if ((cc & 1) == 0) { MBAR_WAIT(sb + SM_MB,     ph0); ph0 ^= 1; }
                else               { MBAR_WAIT(sb + SM_MB + 8, ph1); ph1 ^= 1; }
                const uint32_t ws = sb + ((cc & 1) ? SM_WS1 : SM_WS0);
                #pragma unroll
                for (int k16 = 0; k16 < 64; k16 += 16) {
                    int kg = kc * 64 + k16;
                    uint32_t ahf[4];
                    uint32_t ad = sb + SM_HBH + (wm * 16 + lrow) * 528 + (kg + kof) * 2;
                    ldsm4(ahf, ad);
                    uint32_t bh[2][4];
                    #pragma unroll
                    for (int g = 0; g < 2; g++) {
                        uint32_t bd = ws + (wn * 32 + g * 16 + lrow) * 144 + (k16 + kof) * 2;
                        ldsm4(bh[g], bd);
                    }
                    #pragma unroll
                    for (int nj = 0; nj < 4; nj++) {
                        uint32_t b0 = bh[nj >> 1][nj & 1], b1 = bh[nj >> 1][2 + (nj & 1)];
                        mma16816(acc1[nj], ahf, b0, b1);
                    }
                }
                __syncthreads();
                if (tid == 0 && cidx < NCHUNK_TOT) issue(cidx);
                cidx++; cc++;
            }
            {   // u epilogue: gelu -> u smem (hi only, pitch 272); warp covers 16r x 32c
                int r0 = wm * 16 + (lane >> 2);
                #pragma unroll
                for (int nj = 0; nj < 4; nj++) {
                    int c = wn * 32 + nj * 8 + (lane & 3) * 2;
                    float bb0 = b_f1[nt * 128 + c], bb1 = b_f1[nt * 128 + c + 1];
                    float v[4] = {acc1[nj][0] + bb0, acc1[nj][1] + bb1,
                                  acc1[nj][2] + bb0, acc1[nj][3] + bb1};
                    float o[4];
                    #pragma unroll
                    for (int j = 0; j < 4; j++) o[j] = 0.5f * v[j] * (1.0f + erff(v[j] * RS2));
                    *(uint32_t*)(smem + SM_UH + (size_t)r0 * 272 + c * 2)       = packh2(o[0], o[1]);
                    *(uint32_t*)(smem + SM_UH + (size_t)(r0 + 8) * 272 + c * 2) = packh2(o[2], o[3]);
                }
            }
            __syncthreads();
            // ---- GEMM2 partial (1-term): acc2 += u_hi[64,128] @ W2h^T  (256 cols) ----
            #pragma unroll 1
            for (int kc2 = 0; kc2 < 2; kc2++) {
                if ((cc & 1) == 0) { MBAR_WAIT(sb + SM_MB,     ph0); ph0 ^= 1; }
                else               { MBAR_WAIT(sb + SM_MB + 8, ph1); ph1 ^= 1; }
                const uint32_t ws = sb + ((cc & 1) ? SM_WS1 : SM_WS0);
                #pragma unroll
                for (int k16 = 0; k16 < 64; k16 += 16) {
                    int kl = kc2 * 64 + k16;
                    uint32_t ahf[4];
                    uint32_t ad = sb + SM_UH + (wm * 16 + lrow) * 272 + (kl + kof) * 2;
                    ldsm4(ahf, ad);
                    #pragma unroll
                    for (int g = 0; g < 4; g++) {
                        uint32_t bd = ws + (wn * 64 + g * 16 + lrow) * 144 + (k16 + kof) * 2;
                        uint32_t bh[4];
                        ldsm4(bh, bd);
                        #pragma unroll
                        for (int s = 0; s < 2; s++) {
                            int nj = g * 2 + s;
                            mma16816(acc2[nj], ahf, bh[s], bh[2 + s]);
                        }
                    }
                }
                __syncthreads();
                if (tid == 0 && cidx < NCHUNK_TOT) issue(cidx);
                cidx++; cc++;
            }
        }
        {   // hB epilogue: hB = 0.5*(hB_hi+hB_lo) + 0.5*tanh(acc2 + b_f2); warp: 16r x 64c
            int r0 = wm * 16 + (lane >> 2);
            #pragma unroll
            for (int nj = 0; nj < 8; nj++) {
                int c = wn * 64 + nj * 8 + (lane & 3) * 2;
                float bb0 = b_f2[c], bb1 = b_f2[c + 1];
                #pragma unroll
                for (int p = 0; p < 2; p++) {
                    int r = r0 + p * 8;
                    float v0 = acc2[nj][p * 2]     + bb0;
                    float v1 = acc2[nj][p * 2 + 1] + bb1;
                    uint32_t ohr = *(uint32_t*)(smem + SM_HBH + (size_t)r * 528 + c * 2);
                    uint32_t olr = *(uint32_t*)(smem + SM_HBL + (size_t)r * 528 + c * 2);
                    __half2 oh2 = *(__half2*)&ohr;
                    __half2 ol2 = *(__half2*)&olr;
                    float2 fh = __half22float2(oh2);
                    float2 fl = __half22float2(ol2);
                    float n0 = 0.5f * (fh.x + fl.x) + 0.5f * tanhf(v0);
                    float n1 = 0.5f * (fh.y + fl.y) + 0.5f * tanhf(v1);
                    uint32_t lo; uint32_t hi = packsplit(n0, n1, lo);
                    *(uint32_t*)(smem + SM_HBH + (size_t)r * 528 + c * 2) = hi;
                    *(uint32_t*)(smem + SM_HBL + (size_t)r * 528 + c * 2) = lo;
                }
            }
        }
        __syncthreads();
    }
    for (int i = tid; i < 2048; i += 512) {
        int row = i >> 5, c8 = i & 31;
        *(uint4*)(hBH + (size_t)(bm + row) * 256 + c8 * 8) = *(const uint4*)(smem + SM_HBH + row * 528 + c8 * 16);
        *(uint4*)(hBL + (size_t)(bm + row) * 256 + c8 * 8) = *(const uint4*)(smem + SM_HBL + row * 528 + c8 * 16);
    }
}

// ---------------- launch ----------------
extern "C" void kernel_launch(void* const* d_in, const int* in_sizes, int n_in,
                              void* d_out, int out_size) {
    const float* x     = (const float*)d_in[0];
    const float* z     = (const float*)d_in[1];
    const float* emb   = (const float*)d_in[2];
    const float* W_in1 = (const float*)d_in[3];
    const float* b_in1 = (const float*)d_in[4];
    const float* W_in2 = (const float*)d_in[5];
    const float* b_in2 = (const float*)d_in[6];
    const float* W_f1  = (const float*)d_in[7];
    const float* b_f1  = (const float*)d_in[8];
    const float* W_f2  = (const float*)d_in[9];
    const float* b_f2  = (const float*)d_in[10];
    const float* W_out = (const float*)d_in[11];
    const float* b_out = (const float*)d_in[12];
    float* out = (float*)d_out;

    cudaFuncSetAttribute(hgemm1<0>, cudaFuncAttributeMaxDynamicSharedMemorySize, SMEMG);
    cudaFuncSetAttribute(hgemm1<2>, cudaFuncAttributeMaxDynamicSharedMemorySize, SMEMG);
    cudaFuncSetAttribute(fractal_kernel, cudaFuncAttributeMaxDynamicSharedMemorySize, SMEM_FRAC);

    #define SYM(p, s) void* p; cudaGetSymbolAddress(&p, s)
    SYM(ftH, g_ftH);
    SYM(w1H, g_w1H); SYM(w2H, g_w2H); SYM(woH, g_woH);
    SYM(hAH, g_hAH); SYM(hAL, g_hAL);
    SYM(hBH, g_hBH); SYM(hBL, g_hBL);
    SYM(p1,  g_p1);  SYM(p2,  g_p2);
    #undef SYM
    typedef __half hf;

    feats_kernel<<<BROWS / 256, 256>>>(x, z, emb);
    dim3 wb(32, 8);
    wsplit_kernel<<<dim3(INPAD / 32, HID / 32),  wb>>>(W_in1, (hf*)w1H, 121, INPAD, HID);
    wsplit_kernel<<<dim3(HID / 32,  HID / 32),   wb>>>(W_in2, (hf*)w2H, HID, HID, HID);
    wsplit_kernel<<<dim3(HID / 32,  VOCAB / 32), wb>>>(W_out, (hf*)woH, HID, HID, VOCAB);
    pack_f1<<<(HID * HID2 + 255) / 256, 256>>>(W_f1);
    pack_f2<<<(HID2 * HID + 255) / 256, 256>>>(W_f2);

    // mlp_in (1-term)
    hgemm1<0><<<dim3(HID / 128, BROWS / 128), 256, SMEMG>>>(
        (hf*)ftH, (hf*)w1H, b_in1, (hf*)hAH, (hf*)hAL, nullptr, HID, INPAD);
    hgemm1<0><<<dim3(HID / 128, BROWS / 128), 256, SMEMG>>>(
        (hf*)hAH, (hf*)w2H, b_in2, (hf*)hBH, (hf*)hBL, nullptr, HID, HID);

    // fractal refinement: ONE persistent launch, 512 threads, 64-K chunks
    fractal_kernel<<<BROWS / FM, 512, SMEM_FRAC>>>(
        (hf*)hBH, (hf*)hBL, (const unsigned char*)p1, (const unsigned char*)p2, b_f1, b_f2);

    // output head (1-term)
    hgemm1<2><<<dim3(VOCAB / 128, BROWS / 128), 256, SMEMG>>>(
        (hf*)hBH, (hf*)woH, b_out, nullptr, nullptr, out, VOCAB, HID);
}

// round 17
// speedup vs baseline: 4.9376x; 1.0230x over previous
#include <cuda_runtime.h>
#include <cuda_fp16.h>
#include <math.h>
#include <stdint.h>

#define BROWS 8192
#define HID   256
#define HID2  512
#define VOCAB 32000
#define INPAD 128
#define NSTEPS 48

// ---------------- device scratch (static, no allocation) ----------------
__device__ __align__(16) __half g_ftH[BROWS * INPAD];
__device__ __align__(16) __half g_w1H[HID * INPAD];
__device__ __align__(16) __half g_w2H[HID * HID];
__device__ __align__(16) __half g_woH[(size_t)VOCAB * HID];
__device__ __align__(16) __half g_hAH[BROWS * HID], g_hAL[BROWS * HID];
__device__ __align__(16) __half g_hBH[BROWS * HID], g_hBL[BROWS * HID];
// hi-only weight panels for the fractal loop, 64-K chunks, 144B pitch (ldmatrix-ready)
#define P1PAN 18432              // [128n][64k] : 128 * 144
#define P2PAN 36864              // [256n][64k] : 256 * 144
__device__ __align__(16) unsigned char g_p1[16 * P1PAN];   // W_f1: (nt 0..3, kc 0..3)
__device__ __align__(16) unsigned char g_p2[8  * P2PAN];   // W_f2: (nt 0..3, kc2 0..1)

// ---------------- helpers ----------------
__device__ __forceinline__ uint32_t smem_u32(const void* p) {
    uint32_t a;
    asm("{ .reg .u64 t; cvta.to.shared.u64 t, %1; cvt.u32.u64 %0, t; }" : "=r"(a) : "l"(p));
    return a;
}
__device__ __forceinline__ void split2(float v, __half& h, __half& l) {
    h = __float2half(v);
    l = __float2half(v - __half2float(h));
}
__device__ __forceinline__ uint32_t packsplit(float v0, float v1, uint32_t& lo) {
    __half h0, l0, h1, l1;
    split2(v0, h0, l0); split2(v1, h1, l1);
    lo = (uint32_t)__half_as_ushort(l0) | ((uint32_t)__half_as_ushort(l1) << 16);
    return (uint32_t)__half_as_ushort(h0) | ((uint32_t)__half_as_ushort(h1) << 16);
}
__device__ __forceinline__ uint32_t packh2(float v0, float v1) {
    __half h0 = __float2half(v0), h1 = __float2half(v1);
    return (uint32_t)__half_as_ushort(h0) | ((uint32_t)__half_as_ushort(h1) << 16);
}
__device__ __forceinline__ void cp16(uint32_t dst, const void* src) {
    asm volatile("cp.async.cg.shared.global [%0], [%1], 16;" :: "r"(dst), "l"(src));
}
__device__ __forceinline__ void ldsm4(uint32_t* r, uint32_t a) {
    asm volatile("ldmatrix.sync.aligned.m8n8.x4.shared.b16 {%0,%1,%2,%3}, [%4];"
                 : "=r"(r[0]), "=r"(r[1]), "=r"(r[2]), "=r"(r[3]) : "r"(a));
}
__device__ __forceinline__ void mma16816(float* d, const uint32_t* a, uint32_t b0, uint32_t b1) {
    asm volatile("mma.sync.aligned.m16n8k16.row.col.f32.f16.f16.f32 "
                 "{%0,%1,%2,%3}, {%4,%5,%6,%7}, {%8,%9}, {%0,%1,%2,%3};"
                 : "+f"(d[0]), "+f"(d[1]), "+f"(d[2]), "+f"(d[3])
                 : "r"(a[0]), "r"(a[1]), "r"(a[2]), "r"(a[3]), "r"(b0), "r"(b1));
}
__device__ __forceinline__ void bulkcp(uint32_t dst, const void* src, uint32_t bytes, uint32_t mbar) {
    asm volatile("cp.async.bulk.shared::cluster.global.mbarrier::complete_tx::bytes [%0], [%1], %2, [%3];"
                 :: "r"(dst), "l"(src), "r"(bytes), "r"(mbar) : "memory");
}
#define MBAR_INIT(a, c) \
    asm volatile("mbarrier.init.shared.b64 [%0], %1;" :: "r"(a), "r"((uint32_t)(c)) : "memory")
#define MBAR_EXPECT_TX(a, bytes) \
    asm volatile("mbarrier.arrive.expect_tx.shared.b64 _, [%0], %1;" :: "r"(a), "r"((uint32_t)(bytes)) : "memory")
#define MBAR_ARRIVE(a) \
    asm volatile("mbarrier.arrive.shared.b64 _, [%0];" :: "r"(a) : "memory")
#define MBAR_WAIT(a, p) do {                                                      \
    uint32_t _m = (a), _p = (uint32_t)(p), _d;                                    \
    asm volatile("{ .reg .pred q; mbarrier.try_wait.parity.acquire.cta.shared::cta.b64 q, [%1], %2; " \
                 "selp.b32 %0, 1, 0, q; }" : "=r"(_d) : "r"(_m), "r"(_p) : "memory"); \
    if (!_d) {                                                                    \
        asm volatile("{ .reg .pred Q; WL_%=: mbarrier.try_wait.parity.acquire.cta.shared::cta.b64 Q, [%0], %1, 0x989680; " \
                     "@Q bra.uni WD_%=; bra.uni WL_%=; WD_%=: }" :: "r"(_m), "r"(_p) : "memory"); \
    } } while (0)

// ---------------- feature assembly: one thread per (row, j) ----------------
__global__ void feats_kernel(const float* __restrict__ x, const float* __restrict__ z,
                             const float* __restrict__ emb) {
    int idx = blockIdx.x * blockDim.x + threadIdx.x;   // 8192 * 32
    int b = idx >> 5, j = idx & 31;
    float xc = fminf(fmaxf(x[b], 0.0f), 1.0f);
    __half* fH = g_ftH + (size_t)b * INPAD;

    // fourier pair j: freq via same double-iteration rounding sequence as before
    double fd = 1.0;
    #pragma unroll 1
    for (int t = 0; t < j; t++) fd *= 3.5;
    const float TWO_PI = 6.283185307179586f;
    float arg = (TWO_PI * xc) * (float)fd;
    float s, c;
    sincosf(arg, &s, &c);
    fH[1 + j]  = __float2half(s);
    fH[33 + j] = __float2half(c);

    if (j == 0) {
        fH[0] = __float2half(xc);
        #pragma unroll
        for (int q = 121; q < 128; q++) fH[q] = __float2half(0.0f);
    }
    if (j < 12) {   // hash level j : res = 16 * 2^j (exact)
        float res = (float)(1 << (j + 4));
        float pos = xc * res;
        float i0f = floorf(pos);
        int   i0  = (int)i0f;
        float w   = pos - i0f;
        int h0 = i0 & 16383, h1 = (i0 + 1) & 16383;
        const float* t0 = emb + (size_t)h0 * 24 + j * 2;
        const float* t1 = emb + (size_t)h1 * 24 + j * 2;
        fH[65 + j*2]   = __float2half((1.0f - w) * t0[0] + w * t1[0]);
        fH[65 + j*2+1] = __float2half((1.0f - w) * t0[1] + w * t1[1]);
    }
    fH[89 + j] = __float2half(z[(size_t)b * 32 + j]);
}

// ---------------- weight transpose (hi only): W[Kreal][N] -> Th[N][Kpad] ----------------
__global__ void wsplit_kernel(const float* __restrict__ W, __half* __restrict__ Th,
                              int Kreal, int Kpad, int N) {
    __shared__ float t[32][33];
    int kt = blockIdx.x * 32, nt = blockIdx.y * 32;
    int tx = threadIdx.x, ty = threadIdx.y;
    #pragma unroll
    for (int i = 0; i < 32; i += 8) {
        int k = kt + ty + i;
        t[ty + i][tx] = (k < Kreal) ? W[(size_t)k * N + nt + tx] : 0.0f;
    }
    __syncthreads();
    #pragma unroll
    for (int i = 0; i < 32; i += 8) {
        int n = nt + ty + i, k = kt + tx;
        Th[(size_t)n * Kpad + k] = __float2half(t[tx][ty + i]);
    }
}

// ---------------- pack W_f1 [256k][512n] hi into 16 panels ([128n][64k], 144B pitch) ----------------
__global__ void pack_f1(const float* __restrict__ W) {
    int i = blockIdx.x * 256 + threadIdx.x;
    if (i >= HID * HID2) return;
    int k = i / HID2, n = i % HID2;
    int nt = n >> 7, nl = n & 127, kc = k >> 6, kl = k & 63;
    *(__half*)(g_p1 + (size_t)(nt * 4 + kc) * P1PAN + nl * 144 + kl * 2) = __float2half(W[i]);
}
// ---------------- pack W_f2 [512k][256n] hi into 8 panels ([256n][64k], 144B pitch) ----------------
__global__ void pack_f2(const float* __restrict__ W) {
    int i = blockIdx.x * 256 + threadIdx.x;
    if (i >= HID2 * HID) return;
    int k = i / HID, n = i % HID;
    int nt = k >> 7, kc2 = (k >> 6) & 1, kl = k & 63;
    *(__half*)(g_p2 + (size_t)(nt * 2 + kc2) * P2PAN + n * 144 + kl * 2) = __float2half(W[i]);
}

// ---------------- 1-term fp16 GEMM: C = epi(A_hi @ B_hi^T + bias) ----------------
#define TSTR   80
#define TBYTES (128 * TSTR)
#define HBUFB  (2 * TBYTES)
#define SMEMG  (2 * HBUFB)

template <int EPI>
__global__ void __launch_bounds__(256) hgemm1(
    const __half* __restrict__ Ah, const __half* __restrict__ Bh,
    const float* __restrict__ bias,
    __half* __restrict__ Ch, __half* __restrict__ Cl,
    float* __restrict__ Cf, int N, int K)
{
    extern __shared__ char smem[];
    const uint32_t sb = smem_u32(smem);
    const int tid  = threadIdx.x;
    const int lane = tid & 31, wid = tid >> 5;
    const int wm = wid & 3, wn = wid >> 2;
    const int bm = blockIdx.y * 128, bn = blockIdx.x * 128;
    const int nchunks = K >> 5;

    float acc[2][8][4];
    #pragma unroll
    for (int a = 0; a < 2; a++)
        #pragma unroll
        for (int b = 0; b < 8; b++)
            #pragma unroll
            for (int c = 0; c < 4; c++) acc[a][b][c] = 0.0f;

    const __half* gsrc[2] = {Ah, Bh};

    auto load_chunk = [&](int c, int buf) {
        const int k0 = c << 5;
        uint32_t base = sb + buf * HBUFB;
        #pragma unroll
        for (int t2 = 0; t2 < 2; t2++) {
            const __half* g = gsrc[t2];
            int rb = (t2 == 0) ? bm : bn;
            #pragma unroll
            for (int i = 0; i < 2; i++) {
                int idx = tid + i * 256;
                int row = idx >> 2, c16 = idx & 3;
                cp16(base + t2 * TBYTES + row * TSTR + c16 * 16,
                     g + (size_t)(rb + row) * K + k0 + c16 * 8);
            }
        }
    };

    const int mat = lane >> 3, rin = lane & 7;
    const int lrow = (mat & 1) * 8 + rin;
    const int kof  = (mat >> 1) * 8;

    load_chunk(0, 0);
    asm volatile("cp.async.commit_group;" ::: "memory");

    for (int c = 0; c < nchunks; c++) {
        const int buf = c & 1;
        if (c + 1 < nchunks) load_chunk(c + 1, buf ^ 1);
        asm volatile("cp.async.commit_group;" ::: "memory");
        if (c + 1 < nchunks) asm volatile("cp.async.wait_group 1;" ::: "memory");
        else                 asm volatile("cp.async.wait_group 0;" ::: "memory");
        __syncthreads();

        const uint32_t sa = sb + buf * HBUFB;
        #pragma unroll
        for (int k16 = 0; k16 < 32; k16 += 16) {
            uint32_t ahf[2][4];
            #pragma unroll
            for (int mt = 0; mt < 2; mt++) {
                uint32_t ad = sa + (wm * 32 + mt * 16 + lrow) * TSTR + (k16 + kof) * 2;
                ldsm4(ahf[mt], ad);
            }
            uint32_t bhf[4][4];
            #pragma unroll
            for (int g = 0; g < 4; g++) {
                uint32_t bd = sa + TBYTES + (wn * 64 + g * 16 + lrow) * TSTR + (k16 + kof) * 2;
                ldsm4(bhf[g], bd);
            }
            #pragma unroll
            for (int nj = 0; nj < 8; nj++) {
                uint32_t b0 = bhf[nj >> 1][nj & 1], b1 = bhf[nj >> 1][2 + (nj & 1)];
                mma16816(acc[0][nj], ahf[0], b0, b1);
                mma16816(acc[1][nj], ahf[1], b0, b1);
            }
        }
        __syncthreads();
    }

    const float RS2 = 0.70710678118654752f;
    #pragma unroll
    for (int mt = 0; mt < 2; mt++) {
        #pragma unroll
        for (int nj = 0; nj < 8; nj++) {
            float* d = acc[mt][nj];
            int rg = bm + wm * 32 + mt * 16 + (lane >> 2);
            int cg = bn + wn * 64 + nj * 8 + (lane & 3) * 2;
            float bb0 = bias[cg], bb1 = bias[cg + 1];
            size_t off0 = (size_t)rg * N + cg;
            size_t off1 = (size_t)(rg + 8) * N + cg;
            if (EPI == 2) {
                *(float2*)(Cf + off0) = make_float2(d[0] + bb0, d[1] + bb1);
                *(float2*)(Cf + off1) = make_float2(d[2] + bb0, d[3] + bb1);
            } else {
                float v[4] = {d[0] + bb0, d[1] + bb1, d[2] + bb0, d[3] + bb1};
                float o[4];
                #pragma unroll
                for (int j = 0; j < 4; j++)
                    o[j] = 0.5f * v[j] * (1.0f + erff(v[j] * RS2));
                uint32_t lo0, lo1;
                uint32_t hi0 = packsplit(o[0], o[1], lo0);
                uint32_t hi1 = packsplit(o[2], o[3], lo1);
                *(uint32_t*)(Ch + off0) = hi0;  *(uint32_t*)(Cl + off0) = lo0;
                *(uint32_t*)(Ch + off1) = hi1;  *(uint32_t*)(Cl + off1) = lo1;
            }
        }
    }
}

// ---------------- persistent fractal loop kernel ----------------
// 512 threads (16 warps: 4M x 4N), 64-K chunks, 1-term GEMMs, exact hi/lo carry.
// Producer-consumer mbarriers instead of per-chunk __syncthreads:
//   full[2]  (count 1, tx-based) : weight data ready
//   cons[2]  (count 16)          : all warps done reading a buffer -> reusable
#define FM       64
#define SM_HBH   0
#define SM_HBL   33792          // 64*528
#define SM_UH    67584          // 64*272 = 17408
#define SM_WS0   84992
#define SM_WS1   (84992 + P2PAN)          // 121856
#define SM_MB    (SM_WS1 + P2PAN)         // 158720  : full0,full1,cons0,cons1 (8B each)
#define SMEM_FRAC (SM_MB + 32)
#define NCHUNK_TOT (NSTEPS * 24)

__global__ void __launch_bounds__(512) fractal_kernel(
    __half* __restrict__ hBH, __half* __restrict__ hBL,
    const unsigned char* __restrict__ p1, const unsigned char* __restrict__ p2,
    const float* __restrict__ b_f1, const float* __restrict__ b_f2)
{
    extern __shared__ char smem[];
    const uint32_t sb = smem_u32(smem);
    const int tid = threadIdx.x, lane = tid & 31, wid = tid >> 5;
    const int wm = wid & 3;          // M slice: 4 x 16 rows
    const int wn = wid >> 2;         // N slice: 4
    const int bm = blockIdx.x * FM;
    const int mat = lane >> 3, rin = lane & 7;
    const int lrow = (mat & 1) * 8 + rin;
    const int kof  = (mat >> 1) * 8;
    const float RS2 = 0.70710678118654752f;

    if (tid == 0) {
        MBAR_INIT(sb + SM_MB,      1);   // full0
        MBAR_INIT(sb + SM_MB + 8,  1);   // full1
        MBAR_INIT(sb + SM_MB + 16, 16);  // cons0
        MBAR_INIT(sb + SM_MB + 24, 16);  // cons1
    }
    for (int i = tid; i < 2048; i += 512) {
        int row = i >> 5, c8 = i & 31;
        *(uint4*)(smem + SM_HBH + row * 528 + c8 * 16) = *(const uint4*)(hBH + (size_t)(bm + row) * 256 + c8 * 8);
        *(uint4*)(smem + SM_HBL + row * 528 + c8 * 16) = *(const uint4*)(hBL + (size_t)(bm + row) * 256 + c8 * 8);
    }
    __syncthreads();

    auto issue = [&](int j) {
        int jj = j % 24;
        int nt = jj / 6, pi = jj % 6;
        const unsigned char* src; uint32_t bytes;
        if (pi < 4) { src = p1 + (size_t)(nt * 4 + pi) * P1PAN;       bytes = P1PAN; }
        else        { src = p2 + (size_t)(nt * 2 + (pi - 4)) * P2PAN; bytes = P2PAN; }
        uint32_t mb = sb + SM_MB + (j & 1) * 8;
        MBAR_EXPECT_TX(mb, bytes);
        bulkcp(sb + ((j & 1) ? SM_WS1 : SM_WS0), src, bytes, mb);
    };
    if (tid == 0) { issue(0); issue(1); }
    int cc = 0;              // chunk counter (consumed)
    int fph0 = 0, fph1 = 0;  // per-thread full-barrier parities
    int cph0 = 0, cph1 = 0;  // tid0-only consume-barrier parities

    // consume one chunk boundary: arrive cons, producer re-issues
    auto chunk_end = [&]() {
        uint32_t cmb = sb + SM_MB + 16 + (cc & 1) * 8;
        if (lane == 0) MBAR_ARRIVE(cmb);
        if (tid == 0) {
            int nx = cc + 2;
            if (nx < NCHUNK_TOT) {
                if ((cc & 1) == 0) { MBAR_WAIT(cmb, cph0); cph0 ^= 1; }
                else               { MBAR_WAIT(cmb, cph1); cph1 ^= 1; }
                issue(nx);
            }
        }
        cc++;
    };
    auto full_wait = [&]() {
        if ((cc & 1) == 0) { MBAR_WAIT(sb + SM_MB,     fph0); fph0 ^= 1; }
        else               { MBAR_WAIT(sb + SM_MB + 8, fph1); fph1 ^= 1; }
    };

    #pragma unroll 1
    for (int step = 0; step < NSTEPS; step++) {
        float acc2[8][4];
        #pragma unroll
        for (int a = 0; a < 8; a++)
            #pragma unroll
            for (int b = 0; b < 4; b++) acc2[a][b] = 0.0f;

        #pragma unroll 1
        for (int nt = 0; nt < 4; nt++) {
            // ---- GEMM1 (1-term): u[64,128] = gelu(hB_hi[64,256] @ W1h^T + b) ----
            float acc1[4][4];
            #pragma unroll
            for (int a = 0; a < 4; a++)
                #pragma unroll
                for (int b = 0; b < 4; b++) acc1[a][b] = 0.0f;

            #pragma unroll 1
            for (int kc = 0; kc < 4; kc++) {
                full_wait();
                const uint32_t ws = sb + ((cc & 1) ? SM_WS1 : SM_WS0);
                #pragma unroll
                for (int k16 = 0; k16 < 64; k16 += 16) {
                    int kg = kc * 64 + k16;
                    uint32_t ahf[4];
                    uint32_t ad = sb + SM_HBH + (wm * 16 + lrow) * 528 + (kg + kof) * 2;
                    ldsm4(ahf, ad);
                    uint32_t bh[2][4];
                    #pragma unroll
                    for (int g = 0; g < 2; g++) {
                        uint32_t bd = ws + (wn * 32 + g * 16 + lrow) * 144 + (k16 + kof) * 2;
                        ldsm4(bh[g], bd);
                    }
                    #pragma unroll
                    for (int nj = 0; nj < 4; nj++) {
                        uint32_t b0 = bh[nj >> 1][nj & 1], b1 = bh[nj >> 1][2 + (nj & 1)];
                        mma16816(acc1[nj], ahf, b0, b1);
                    }
                }
                chunk_end();
            }
            // barrier: all warps done G1 (and prev G2's u reads) before u overwrite
            __syncthreads();
            {   // u epilogue: gelu -> u smem (hi only, pitch 272); warp covers 16r x 32c
                int r0 = wm * 16 + (lane >> 2);
                #pragma unroll
                for (int nj = 0; nj < 4; nj++) {
                    int c = wn * 32 + nj * 8 + (lane & 3) * 2;
                    float bb0 = b_f1[nt * 128 + c], bb1 = b_f1[nt * 128 + c + 1];
                    float v[4] = {acc1[nj][0] + bb0, acc1[nj][1] + bb1,
                                  acc1[nj][2] + bb0, acc1[nj][3] + bb1};
                    float o[4];
                    #pragma unroll
                    for (int j = 0; j < 4; j++) o[j] = 0.5f * v[j] * (1.0f + erff(v[j] * RS2));
                    *(uint32_t*)(smem + SM_UH + (size_t)r0 * 272 + c * 2)       = packh2(o[0], o[1]);
                    *(uint32_t*)(smem + SM_UH + (size_t)(r0 + 8) * 272 + c * 2) = packh2(o[2], o[3]);
                }
            }
            __syncthreads();
            // ---- GEMM2 partial (1-term): acc2 += u_hi[64,128] @ W2h^T  (256 cols) ----
            #pragma unroll 1
            for (int kc2 = 0; kc2 < 2; kc2++) {
                full_wait();
                const uint32_t ws = sb + ((cc & 1) ? SM_WS1 : SM_WS0);
                #pragma unroll
                for (int k16 = 0; k16 < 64; k16 += 16) {
                    int kl = kc2 * 64 + k16;
                    uint32_t ahf[4];
                    uint32_t ad = sb + SM_UH + (wm * 16 + lrow) * 272 + (kl + kof) * 2;
                    ldsm4(ahf, ad);
                    #pragma unroll
                    for (int g = 0; g < 4; g++) {
                        uint32_t bd = ws + (wn * 64 + g * 16 + lrow) * 144 + (k16 + kof) * 2;
                        uint32_t bh[4];
                        ldsm4(bh, bd);
                        #pragma unroll
                        for (int s = 0; s < 2; s++) {
                            int nj = g * 2 + s;
                            mma16816(acc2[nj], ahf, bh[s], bh[2 + s]);
                        }
                    }
                }
                chunk_end();
            }
        }
        {   // hB epilogue: hB = 0.5*(hB_hi+hB_lo) + 0.5*tanh(acc2 + b_f2); warp: 16r x 64c
            // (all hB readers -- G1 of this step -- are past the nt=3 post-G1 barrier)
            int r0 = wm * 16 + (lane >> 2);
            #pragma unroll
            for (int nj = 0; nj < 8; nj++) {
                int c = wn * 64 + nj * 8 + (lane & 3) * 2;
                float bb0 = b_f2[c], bb1 = b_f2[c + 1];
                #pragma unroll
                for (int p = 0; p < 2; p++) {
                    int r = r0 + p * 8;
                    float v0 = acc2[nj][p * 2]     + bb0;
                    float v1 = acc2[nj][p * 2 + 1] + bb1;
                    uint32_t ohr = *(uint32_t*)(smem + SM_HBH + (size_t)r * 528 + c * 2);
                    uint32_t olr = *(uint32_t*)(smem + SM_HBL + (size_t)r * 528 + c * 2);
                    __half2 oh2 = *(__half2*)&ohr;
                    __half2 ol2 = *(__half2*)&olr;
                    float2 fh = __half22float2(oh2);
                    float2 fl = __half22float2(ol2);
                    float n0 = 0.5f * (fh.x + fl.x) + 0.5f * tanhf(v0);
                    float n1 = 0.5f * (fh.y + fl.y) + 0.5f * tanhf(v1);
                    uint32_t lo; uint32_t hi = packsplit(n0, n1, lo);
                    *(uint32_t*)(smem + SM_HBH + (size_t)r * 528 + c * 2) = hi;
                    *(uint32_t*)(smem + SM_HBL + (size_t)r * 528 + c * 2) = lo;
                }
            }
        }
        __syncthreads();   // hB visible to next step's G1
    }
    for (int i = tid; i < 2048; i += 512) {
        int row = i >> 5, c8 = i & 31;
        *(uint4*)(hBH + (size_t)(bm + row) * 256 + c8 * 8) = *(const uint4*)(smem + SM_HBH + row * 528 + c8 * 16);
        *(uint4*)(hBL + (size_t)(bm + row) * 256 + c8 * 8) = *(const uint4*)(smem + SM_HBL + row * 528 + c8 * 16);
    }
}

// ---------------- launch ----------------
extern "C" void kernel_launch(void* const* d_in, const int* in_sizes, int n_in,
                              void* d_out, int out_size) {
    const float* x     = (const float*)d_in[0];
    const float* z     = (const float*)d_in[1];
    const float* emb   = (const float*)d_in[2];
    const float* W_in1 = (const float*)d_in[3];
    const float* b_in1 = (const float*)d_in[4];
    const float* W_in2 = (const float*)d_in[5];
    const float* b_in2 = (const float*)d_in[6];
    const float* W_f1  = (const float*)d_in[7];
    const float* b_f1  = (const float*)d_in[8];
    const float* W_f2  = (const float*)d_in[9];
    const float* b_f2  = (const float*)d_in[10];
    const float* W_out = (const float*)d_in[11];
    const float* b_out = (const float*)d_in[12];
    float* out = (float*)d_out;

    cudaFuncSetAttribute(hgemm1<0>, cudaFuncAttributeMaxDynamicSharedMemorySize, SMEMG);
    cudaFuncSetAttribute(hgemm1<2>, cudaFuncAttributeMaxDynamicSharedMemorySize, SMEMG);
    cudaFuncSetAttribute(fractal_kernel, cudaFuncAttributeMaxDynamicSharedMemorySize, SMEM_FRAC);

    #define SYM(p, s) void* p; cudaGetSymbolAddress(&p, s)
    SYM(ftH, g_ftH);
    SYM(w1H, g_w1H); SYM(w2H, g_w2H); SYM(woH, g_woH);
    SYM(hAH, g_hAH); SYM(hAL, g_hAL);
    SYM(hBH, g_hBH); SYM(hBL, g_hBL);
    SYM(p1,  g_p1);  SYM(p2,  g_p2);
    #undef SYM
    typedef __half hf;

    feats_kernel<<<(BROWS * 32) / 256, 256>>>(x, z, emb);
    dim3 wb(32, 8);
    wsplit_kernel<<<dim3(INPAD / 32, HID / 32),  wb>>>(W_in1, (hf*)w1H, 121, INPAD, HID);
    wsplit_kernel<<<dim3(HID / 32,  HID / 32),   wb>>>(W_in2, (hf*)w2H, HID, HID, HID);
    wsplit_kernel<<<dim3(HID / 32,  VOCAB / 32), wb>>>(W_out, (hf*)woH, HID, HID, VOCAB);
    pack_f1<<<(HID * HID2 + 255) / 256, 256>>>(W_f1);
    pack_f2<<<(HID2 * HID + 255) / 256, 256>>>(W_f2);

    // mlp_in (1-term)
    hgemm1<0><<<dim3(HID / 128, BROWS / 128), 256, SMEMG>>>(
        (hf*)ftH, (hf*)w1H, b_in1, (hf*)hAH, (hf*)hAL, nullptr, HID, INPAD);
    hgemm1<0><<<dim3(HID / 128, BROWS / 128), 256, SMEMG>>>(
        (hf*)hAH, (hf*)w2H, b_in2, (hf*)hBH, (hf*)hBL, nullptr, HID, HID);

    // fractal refinement: ONE persistent launch, mbarrier producer/consumer pipeline
    fractal_kernel<<<BROWS / FM, 512, SMEM_FRAC>>>(
        (hf*)hBH, (hf*)hBL, (const unsigned char*)p1, (const unsigned char*)p2, b_f1, b_f2);

    // output head (1-term)
    hgemm1<2><<<dim3(VOCAB / 128, BROWS / 128), 256, SMEMG>>>(
        (hf*)hBH, (hf*)woH, b_out, nullptr, nullptr, out, VOCAB, HID);
}